// round 1
// baseline (speedup 1.0000x reference)
#include <cuda_runtime.h>
#include <math.h>

#define NN 100000
#define CC 128
#define KK 16
#define BB 16
#define MT 32           // nodes per block
#define EPSF 1e-9f
#define HS 129          // Hs row stride (pad to kill bank conflicts)

// -------- device scratch (global accumulators, zeroed each launch) --------
__device__ float g_sum_s[KK];        // column sums of s
__device__ float g_ent;              // sum over n,k of s*log(s+eps)
__device__ float g_A[KK][2];         // sum s*pos
__device__ float g_P[KK];            // sum s*|pos|^2
__device__ float g_bs[BB][KK];       // per-batch sum s
__device__ float g_bsp[BB][KK][2];   // per-batch sum s*pos

// -------- init: zero scratch + pooled-output region --------
__global__ void init_kernel(float* __restrict__ out_pool) {
    int i = blockIdx.x * blockDim.x + threadIdx.x;
    if (i < BB * KK * CC) out_pool[i] = 0.0f;
    if (i < KK) {
        g_sum_s[i] = 0.f; g_P[i] = 0.f;
        g_A[i][0] = 0.f; g_A[i][1] = 0.f;
    }
    if (i == 0) g_ent = 0.f;
    if (i < BB * KK)     ((float*)g_bs)[i] = 0.f;
    if (i < BB * KK * 2) ((float*)g_bsp)[i] = 0.f;
}

// -------- main fused kernel: MLP + gumbel softmax + all reductions + pooling --------
__global__ __launch_bounds__(256)
void fused_kernel(const float* __restrict__ x,
                  const float* __restrict__ pos,
                  const int*   __restrict__ batch,
                  const float* __restrict__ gumbel,
                  const float* __restrict__ W1,
                  const float* __restrict__ b1,
                  const float* __restrict__ W2,
                  const float* __restrict__ b2,
                  const float* __restrict__ scaling,
                  const float* __restrict__ active,
                  float* __restrict__ out_pool,   // [B,K,C]
                  float* __restrict__ out_s)      // [N,K]
{
    __shared__ __align__(16) float Xs[MT * CC];        // x tile
    __shared__ __align__(16) float Hsm[MT * HS];       // hidden (padded stride)
    __shared__ __align__(16) float W2s[CC * KK];
    __shared__ __align__(16) float Ls[MT * KK];        // logits, then s
    __shared__ float Ps[MT * 2];
    __shared__ float b2s[KK];
    __shared__ float acts[KK];
    __shared__ int   Bsm[MT];

    const int tid = threadIdx.x;
    const int n0  = blockIdx.x * MT;
    const int nvalid = min(MT, NN - n0);

    // ---- load tiles ----
    {
        const float4* xg = (const float4*)(x + (size_t)n0 * CC);
        float4* Xs4 = (float4*)Xs;
        const int tot4 = MT * CC / 4;           // 1024
        const int valid4 = nvalid * CC / 4;
        for (int i = tid; i < tot4; i += 256)
            Xs4[i] = (i < valid4) ? xg[i] : make_float4(0.f, 0.f, 0.f, 0.f);
        for (int i = tid; i < CC * KK; i += 256) W2s[i] = W2[i];
        if (tid < KK) { b2s[tid] = b2[tid]; acts[tid] = active[tid]; }
        for (int i = tid; i < MT; i += 256) {
            if (i < nvalid) {
                Ps[2*i]   = pos[(size_t)(n0 + i) * 2];
                Ps[2*i+1] = pos[(size_t)(n0 + i) * 2 + 1];
                Bsm[i]    = batch[n0 + i];
            } else {
                Ps[2*i] = 0.f; Ps[2*i+1] = 0.f; Bsm[i] = -1;
            }
        }
    }
    __syncthreads();

    // ---- stage A: H = relu(X @ W1 + b1), register-tiled 4x4 per thread ----
    {
        const int tx = tid & 31;       // col group: cols 4*tx .. 4*tx+3
        const int ty = tid >> 5;       // row group: rows 4*ty .. 4*ty+3
        float4 acc[4];
        const float4 bb = *(const float4*)(b1 + tx * 4);
        #pragma unroll
        for (int i = 0; i < 4; i++) acc[i] = bb;

        const float4* Xs4 = (const float4*)Xs;
        #pragma unroll 4
        for (int k4 = 0; k4 < CC / 4; k4++) {
            float4 w0 = *(const float4*)(W1 + (size_t)(k4*4 + 0) * CC + tx * 4);
            float4 w1 = *(const float4*)(W1 + (size_t)(k4*4 + 1) * CC + tx * 4);
            float4 w2 = *(const float4*)(W1 + (size_t)(k4*4 + 2) * CC + tx * 4);
            float4 w3 = *(const float4*)(W1 + (size_t)(k4*4 + 3) * CC + tx * 4);
            #pragma unroll
            for (int i = 0; i < 4; i++) {
                float4 xv = Xs4[(ty*4 + i) * (CC/4) + k4];
                acc[i].x += xv.x*w0.x + xv.y*w1.x + xv.z*w2.x + xv.w*w3.x;
                acc[i].y += xv.x*w0.y + xv.y*w1.y + xv.z*w2.y + xv.w*w3.y;
                acc[i].z += xv.x*w0.z + xv.y*w1.z + xv.z*w2.z + xv.w*w3.z;
                acc[i].w += xv.x*w0.w + xv.y*w1.w + xv.z*w2.w + xv.w*w3.w;
            }
        }
        #pragma unroll
        for (int i = 0; i < 4; i++) {
            float* hr = Hsm + (ty*4 + i) * HS + tx * 4;
            hr[0] = fmaxf(acc[i].x, 0.f);
            hr[1] = fmaxf(acc[i].y, 0.f);
            hr[2] = fmaxf(acc[i].z, 0.f);
            hr[3] = fmaxf(acc[i].w, 0.f);
        }
    }
    __syncthreads();

    // ---- stage B: logits = (H @ W2 + b2)*scaling, masked ----
    {
        const int n  = tid >> 3;            // 0..31
        const int kb = (tid & 7) * 2;       // 0,2,...,14
        float a0 = b2s[kb], a1 = b2s[kb + 1];
        const float* hrow = Hsm + n * HS;
        #pragma unroll 8
        for (int c = 0; c < CC; c++) {
            float hv = hrow[c];
            float2 w = *(const float2*)(W2s + c * KK + kb);
            a0 += hv * w.x;
            a1 += hv * w.y;
        }
        const float sc = scaling[0];
        Ls[n * KK + kb]     = (acts[kb]     == 0.f) ? -1e9f : a0 * sc;
        Ls[n * KK + kb + 1] = (acts[kb + 1] == 0.f) ? -1e9f : a1 * sc;
    }
    __syncthreads();

    // ---- gumbel softmax (TAU = 1) ----
    if (tid < MT) {
        const int n = tid;
        if (n < nvalid) {
            float l[KK];
            const float4* g4 = (const float4*)(gumbel + (size_t)(n0 + n) * KK);
            float gv[KK];
            #pragma unroll
            for (int q = 0; q < 4; q++) {
                float4 g = g4[q];
                gv[q*4+0] = g.x; gv[q*4+1] = g.y; gv[q*4+2] = g.z; gv[q*4+3] = g.w;
            }
            float m = -3.4e38f;
            #pragma unroll
            for (int k = 0; k < KK; k++) { l[k] = Ls[n * KK + k] + gv[k]; m = fmaxf(m, l[k]); }
            float ssum = 0.f;
            #pragma unroll
            for (int k = 0; k < KK; k++) { l[k] = __expf(l[k] - m); ssum += l[k]; }
            const float inv = 1.f / ssum;
            float4* so = (float4*)(out_s + (size_t)(n0 + n) * KK);
            #pragma unroll
            for (int q = 0; q < 4; q++) {
                float4 v = make_float4(l[q*4+0]*inv, l[q*4+1]*inv, l[q*4+2]*inv, l[q*4+3]*inv);
                so[q] = v;
                Ls[n * KK + q*4+0] = v.x; Ls[n * KK + q*4+1] = v.y;
                Ls[n * KK + q*4+2] = v.z; Ls[n * KK + q*4+3] = v.w;
            }
        } else {
            #pragma unroll
            for (int k = 0; k < KK; k++) Ls[n * KK + k] = 0.f;
        }
    }
    __syncthreads();

    // ---- stage C1: global + per-batch statistics (threads 0..15, one per k) ----
    if (tid < KK) {
        const int k = tid;
        float gs = 0.f, ge = 0.f, gax = 0.f, gay = 0.f, gp = 0.f;
        int cur = Bsm[0];
        float bs = 0.f, bx = 0.f, by = 0.f;
        for (int n = 0; n < MT; n++) {
            const int bv = Bsm[n];
            if (bv < 0) break;
            if (bv != cur) {
                atomicAdd(&g_bs[cur][k], bs);
                atomicAdd(&g_bsp[cur][k][0], bx);
                atomicAdd(&g_bsp[cur][k][1], by);
                bs = bx = by = 0.f; cur = bv;
            }
            const float sv = Ls[n * KK + k];
            const float px = Ps[2*n], py = Ps[2*n+1];
            gs  += sv;
            ge  += sv * __logf(sv + EPSF);
            gax += sv * px;
            gay += sv * py;
            gp  += sv * (px*px + py*py);
            bs  += sv; bx += sv * px; by += sv * py;
        }
        if (cur >= 0) {
            atomicAdd(&g_bs[cur][k], bs);
            atomicAdd(&g_bsp[cur][k][0], bx);
            atomicAdd(&g_bsp[cur][k][1], by);
        }
        atomicAdd(&g_sum_s[k], gs);
        atomicAdd(&g_ent, ge);
        atomicAdd(&g_A[k][0], gax);
        atomicAdd(&g_A[k][1], gay);
        atomicAdd(&g_P[k], gp);
    }

    // ---- stage C2: pooled features out[b,k,c] += s[n,k]*x[n,c] (all 256 threads) ----
    {
        const int k  = tid >> 4;        // 0..15
        const int cg = tid & 15;        // 8 channels: c = cg*8..cg*8+7
        const float4* Xs4 = (const float4*)Xs;
        float4 A0 = make_float4(0.f,0.f,0.f,0.f);
        float4 A1 = make_float4(0.f,0.f,0.f,0.f);
        int cur = Bsm[0];
        for (int n = 0; n < MT; n++) {
            const int bv = Bsm[n];
            if (bv < 0) break;
            if (bv != cur) {
                float* base = out_pool + ((size_t)cur * KK + k) * CC + cg * 8;
                atomicAdd(base+0, A0.x); atomicAdd(base+1, A0.y);
                atomicAdd(base+2, A0.z); atomicAdd(base+3, A0.w);
                atomicAdd(base+4, A1.x); atomicAdd(base+5, A1.y);
                atomicAdd(base+6, A1.z); atomicAdd(base+7, A1.w);
                A0 = make_float4(0.f,0.f,0.f,0.f);
                A1 = make_float4(0.f,0.f,0.f,0.f);
                cur = bv;
            }
            const float sv = Ls[n * KK + k];
            const float4 x0 = Xs4[n * (CC/4) + cg*2];
            const float4 x1 = Xs4[n * (CC/4) + cg*2 + 1];
            A0.x += sv*x0.x; A0.y += sv*x0.y; A0.z += sv*x0.z; A0.w += sv*x0.w;
            A1.x += sv*x1.x; A1.y += sv*x1.y; A1.z += sv*x1.z; A1.w += sv*x1.w;
        }
        if (cur >= 0) {
            float* base = out_pool + ((size_t)cur * KK + k) * CC + cg * 8;
            atomicAdd(base+0, A0.x); atomicAdd(base+1, A0.y);
            atomicAdd(base+2, A0.z); atomicAdd(base+3, A0.w);
            atomicAdd(base+4, A1.x); atomicAdd(base+5, A1.y);
            atomicAdd(base+6, A1.z); atomicAdd(base+7, A1.w);
        }
    }
}

// -------- finalize: super-node mus, separation, losses --------
__global__ void finalize_kernel(const float* __restrict__ active,
                                float* __restrict__ mu_out,     // [B,K,2]
                                float* __restrict__ losses)     // [6]
{
    __shared__ float mus[BB][KK][2];
    __shared__ float red[256];
    const int tid = threadIdx.x;
    const int b = tid >> 4, k = tid & 15;

    const float denom = g_bs[b][k] + EPSF;
    const float mx = g_bsp[b][k][0] / denom;
    const float my = g_bsp[b][k][1] / denom;
    mus[b][k][0] = mx; mus[b][k][1] = my;
    mu_out[tid * 2]     = mx;
    mu_out[tid * 2 + 1] = my;
    __syncthreads();

    float rep = 0.f;
    #pragma unroll
    for (int j = 0; j < KK; j++) {
        if (j == k) continue;
        float dx = mus[b][k][0] - mus[b][j][0];
        float dy = mus[b][k][1] - mus[b][j][1];
        rep += 1.f / (dx*dx + dy*dy + 1.f);
    }
    red[tid] = rep;
    __syncthreads();
    for (int st = 128; st > 0; st >>= 1) {
        if (tid < st) red[tid] += red[tid + st];
        __syncthreads();
    }

    if (tid == 0) {
        const float sep = red[0] / ((float)(KK * (KK - 1)) + EPSF);
        const float entropy = -g_ent / (float)NN;
        float div = 0.f, prun = 0.f, spat = 0.f, spar = 0.f;
        for (int kk = 0; kk < KK; kk++) {
            const float avg = g_sum_s[kk] / (float)NN;
            div  += avg * __logf(avg + EPSF);
            const float am = active[kk];
            prun += fabsf(avg * (1.f - am));
            spar += am;
            const float S = g_sum_s[kk] + EPSF;
            const float mgx = g_A[kk][0] / S;
            const float mgy = g_A[kk][1] / S;
            // var = P/S - 2*mu.mu + mu.mu = P/S - |mu|^2  (s_norm^T pos == mu_g exactly)
            spat += g_P[kk] / S - (mgx*mgx + mgy*mgy);
        }
        losses[0] = entropy;
        losses[1] = div;
        losses[2] = spat / (float)KK;
        losses[3] = prun / (float)KK;
        losses[4] = spar / (float)KK;
        losses[5] = sep;
    }
}

extern "C" void kernel_launch(void* const* d_in, const int* in_sizes, int n_in,
                              void* d_out, int out_size) {
    const float* x       = (const float*)d_in[0];
    const float* pos     = (const float*)d_in[1];
    const int*   batch   = (const int*)  d_in[2];
    const float* gumbel  = (const float*)d_in[3];
    const float* W1      = (const float*)d_in[4];
    const float* b1      = (const float*)d_in[5];
    const float* W2      = (const float*)d_in[6];
    const float* b2      = (const float*)d_in[7];
    const float* scaling = (const float*)d_in[8];
    const float* active  = (const float*)d_in[9];

    float* out = (float*)d_out;
    float* out_pool   = out;                                   // [B,K,C]   = 32768
    float* out_s      = out + (size_t)BB*KK*CC;                // [N,K]     = 1600000
    float* out_mu     = out_s + (size_t)NN*KK;                 // [B,K,2]   = 512
    float* out_losses = out_mu + (size_t)BB*KK*2;              // [6]

    init_kernel<<<(BB*KK*CC + 255) / 256, 256>>>(out_pool);
    fused_kernel<<<(NN + MT - 1) / MT, 256>>>(
        x, pos, batch, gumbel, W1, b1, W2, b2, scaling, active, out_pool, out_s);
    finalize_kernel<<<1, 256>>>(active, out_mu, out_losses);
}

// round 2
// speedup vs baseline: 1.2014x; 1.2014x over previous
#include <cuda_runtime.h>
#include <math.h>

#define NN 100000
#define CC 128
#define KK 16
#define BB 16
#define MT 64           // nodes per block
#define EPSF 1e-9f
#define HS 132          // H row stride in floats (132 mod 32 = 4 -> conflict-free)

// -------- device scratch (global accumulators, zeroed each launch) --------
__device__ float g_sum_s[KK];
__device__ float g_ent;
__device__ float g_A[KK][2];
__device__ float g_P[KK];
__device__ float g_bs[BB][KK];
__device__ float g_bsp[BB][KK][2];

__global__ void init_kernel(float* __restrict__ out_pool) {
    int i = blockIdx.x * blockDim.x + threadIdx.x;
    if (i < BB * KK * CC) out_pool[i] = 0.0f;
    if (i < KK) {
        g_sum_s[i] = 0.f; g_P[i] = 0.f;
        g_A[i][0] = 0.f; g_A[i][1] = 0.f;
    }
    if (i == 0) g_ent = 0.f;
    if (i < BB * KK)     ((float*)g_bs)[i] = 0.f;
    if (i < BB * KK * 2) ((float*)g_bsp)[i] = 0.f;
}

__global__ __launch_bounds__(256)
void fused_kernel(const float* __restrict__ x,
                  const float* __restrict__ pos,
                  const int*   __restrict__ batch,
                  const float* __restrict__ gumbel,
                  const float* __restrict__ W1,
                  const float* __restrict__ b1,
                  const float* __restrict__ W2,
                  const float* __restrict__ b2,
                  const float* __restrict__ scaling,
                  const float* __restrict__ active,
                  float* __restrict__ out_pool,   // [B,K,C]
                  float* __restrict__ out_s)      // [N,K]
{
    // buf: first holds x tile (stride 128 floats), then H tile (stride 132)
    __shared__ __align__(16) float buf[MT * HS];       // 33792 B
    __shared__ __align__(16) float W2s[CC * KK];       // 8192 B
    __shared__ __align__(16) float Ls[MT * KK];        // 4096 B
    __shared__ float Ps[MT * 2];
    __shared__ float b2s[KK];
    __shared__ float acts[KK];
    __shared__ int   Bsm[MT];

    const int tid = threadIdx.x;
    const int tx  = tid & 31;
    const int wp  = tid >> 5;
    const int n0  = blockIdx.x * MT;
    const int nvalid = min(MT, NN - n0);

    // ---- load tiles ----
    float4* Xs4 = (float4*)buf;                        // x view: stride 32 float4
    {
        const float4* xg = (const float4*)(x + (size_t)n0 * CC);
        const int valid4 = nvalid * (CC / 4);
        for (int i = tid; i < MT * (CC / 4); i += 256)
            Xs4[i] = (i < valid4) ? xg[i] : make_float4(0.f, 0.f, 0.f, 0.f);
        for (int i = tid; i < CC * KK; i += 256) W2s[i] = W2[i];
        if (tid < KK) { b2s[tid] = b2[tid]; acts[tid] = active[tid]; }
        for (int i = tid; i < MT; i += 256) {
            if (i < nvalid) {
                Ps[2*i]   = pos[(size_t)(n0 + i) * 2];
                Ps[2*i+1] = pos[(size_t)(n0 + i) * 2 + 1];
                Bsm[i]    = batch[n0 + i];
            } else {
                Ps[2*i] = 0.f; Ps[2*i+1] = 0.f; Bsm[i] = -1;
            }
        }
    }
    __syncthreads();

    // ---- stage A: H = relu(X @ W1 + b1). warp wp owns rows 8*wp..8*wp+7,
    //      lane tx owns cols 4*tx..4*tx+3. 8x4 accumulators per thread.
    float4 acc[8];
    {
        const float4 bb = *(const float4*)(b1 + tx * 4);
        #pragma unroll
        for (int i = 0; i < 8; i++) acc[i] = bb;

        #pragma unroll 2
        for (int k4 = 0; k4 < CC / 4; k4++) {
            float4 w0 = *(const float4*)(W1 + (size_t)(k4*4 + 0) * CC + tx * 4);
            float4 w1 = *(const float4*)(W1 + (size_t)(k4*4 + 1) * CC + tx * 4);
            float4 w2 = *(const float4*)(W1 + (size_t)(k4*4 + 2) * CC + tx * 4);
            float4 w3 = *(const float4*)(W1 + (size_t)(k4*4 + 3) * CC + tx * 4);
            #pragma unroll
            for (int i = 0; i < 8; i++) {
                float4 xv = Xs4[(wp*8 + i) * (CC/4) + k4];   // broadcast across lanes
                acc[i].x += xv.x*w0.x + xv.y*w1.x + xv.z*w2.x + xv.w*w3.x;
                acc[i].y += xv.x*w0.y + xv.y*w1.y + xv.z*w2.y + xv.w*w3.y;
                acc[i].z += xv.x*w0.z + xv.y*w1.z + xv.z*w2.z + xv.w*w3.z;
                acc[i].w += xv.x*w0.w + xv.y*w1.w + xv.z*w2.w + xv.w*w3.w;
            }
        }
    }
    __syncthreads();   // all x-tile reads complete before H overwrites buf

    #pragma unroll
    for (int i = 0; i < 8; i++) {
        float4 h;
        h.x = fmaxf(acc[i].x, 0.f);
        h.y = fmaxf(acc[i].y, 0.f);
        h.z = fmaxf(acc[i].z, 0.f);
        h.w = fmaxf(acc[i].w, 0.f);
        *(float4*)(buf + (wp*8 + i) * HS + tx * 4) = h;    // 528B row pitch, 16B aligned
    }
    __syncthreads();

    // ---- stage B: logits = (H @ W2 + b2)*scaling, masked. thread = (n, 4 k's)
    {
        const int n  = tid >> 2;           // 0..63
        const int kb = (tid & 3) * 4;      // 0,4,8,12
        float4 a = *(const float4*)(b2s + kb);
        const float* hrow = buf + n * HS;
        #pragma unroll 8
        for (int c = 0; c < CC; c++) {
            const float hv = hrow[c];
            const float4 w = *(const float4*)(W2s + c * KK + kb);
            a.x += hv * w.x; a.y += hv * w.y; a.z += hv * w.z; a.w += hv * w.w;
        }
        const float sc = scaling[0];
        float4 o;
        o.x = (acts[kb+0] == 0.f) ? -1e9f : a.x * sc;
        o.y = (acts[kb+1] == 0.f) ? -1e9f : a.y * sc;
        o.z = (acts[kb+2] == 0.f) ? -1e9f : a.z * sc;
        o.w = (acts[kb+3] == 0.f) ? -1e9f : a.w * sc;
        *(float4*)(Ls + n * KK + kb) = o;
    }
    __syncthreads();

    // ---- gumbel softmax (TAU = 1), one thread per node ----
    if (tid < nvalid) {
        const int n = tid;
        float l[KK];
        const float4* g4 = (const float4*)(gumbel + (size_t)(n0 + n) * KK);
        #pragma unroll
        for (int q = 0; q < 4; q++) {
            float4 g = g4[q];
            l[q*4+0] = Ls[n*KK + q*4+0] + g.x;
            l[q*4+1] = Ls[n*KK + q*4+1] + g.y;
            l[q*4+2] = Ls[n*KK + q*4+2] + g.z;
            l[q*4+3] = Ls[n*KK + q*4+3] + g.w;
        }
        float m = -3.4e38f;
        #pragma unroll
        for (int k = 0; k < KK; k++) m = fmaxf(m, l[k]);
        float ssum = 0.f;
        #pragma unroll
        for (int k = 0; k < KK; k++) { l[k] = __expf(l[k] - m); ssum += l[k]; }
        const float inv = 1.f / ssum;
        float4* so = (float4*)(out_s + (size_t)(n0 + n) * KK);
        #pragma unroll
        for (int q = 0; q < 4; q++) {
            float4 v = make_float4(l[q*4+0]*inv, l[q*4+1]*inv, l[q*4+2]*inv, l[q*4+3]*inv);
            so[q] = v;
            Ls[n*KK + q*4+0] = v.x; Ls[n*KK + q*4+1] = v.y;
            Ls[n*KK + q*4+2] = v.z; Ls[n*KK + q*4+3] = v.w;
        }
    }
    __syncthreads();

    // ---- stage C1: statistics ----
    const bool uniform = (nvalid == MT) && (Bsm[0] == Bsm[MT-1]);
    if (uniform) {
        // all 256 threads: k = tid>>4, group g = tid&15 handles 4 nodes
        const int k = tid >> 4;
        const int g = tid & 15;
        float gs = 0.f, ge = 0.f, gax = 0.f, gay = 0.f, gp = 0.f;
        #pragma unroll
        for (int j = 0; j < 4; j++) {
            const int n = g*4 + j;
            const float sv = Ls[n*KK + k];
            const float px = Ps[2*n], py = Ps[2*n+1];
            gs  += sv;
            ge  += sv * __logf(sv + EPSF);
            gax += sv * px;
            gay += sv * py;
            gp  += sv * (px*px + py*py);
        }
        #pragma unroll
        for (int off = 8; off > 0; off >>= 1) {
            gs  += __shfl_down_sync(0xffffffffu, gs,  off, 16);
            ge  += __shfl_down_sync(0xffffffffu, ge,  off, 16);
            gax += __shfl_down_sync(0xffffffffu, gax, off, 16);
            gay += __shfl_down_sync(0xffffffffu, gay, off, 16);
            gp  += __shfl_down_sync(0xffffffffu, gp,  off, 16);
        }
        if (g == 0) {
            const int b = Bsm[0];
            atomicAdd(&g_sum_s[k], gs);
            atomicAdd(&g_ent, ge);
            atomicAdd(&g_A[k][0], gax);
            atomicAdd(&g_A[k][1], gay);
            atomicAdd(&g_P[k], gp);
            atomicAdd(&g_bs[b][k], gs);
            atomicAdd(&g_bsp[b][k][0], gax);
            atomicAdd(&g_bsp[b][k][1], gay);
        }
    } else if (tid < KK) {
        // rare: boundary tile or tail — serial per-k
        const int k = tid;
        float gs = 0.f, ge = 0.f, gax = 0.f, gay = 0.f, gp = 0.f;
        int cur = Bsm[0];
        float bs = 0.f, bx = 0.f, by = 0.f;
        for (int n = 0; n < MT; n++) {
            const int bv = Bsm[n];
            if (bv < 0) break;
            if (bv != cur) {
                atomicAdd(&g_bs[cur][k], bs);
                atomicAdd(&g_bsp[cur][k][0], bx);
                atomicAdd(&g_bsp[cur][k][1], by);
                bs = bx = by = 0.f; cur = bv;
            }
            const float sv = Ls[n*KK + k];
            const float px = Ps[2*n], py = Ps[2*n+1];
            gs  += sv;
            ge  += sv * __logf(sv + EPSF);
            gax += sv * px;
            gay += sv * py;
            gp  += sv * (px*px + py*py);
            bs  += sv; bx += sv * px; by += sv * py;
        }
        if (cur >= 0) {
            atomicAdd(&g_bs[cur][k], bs);
            atomicAdd(&g_bsp[cur][k][0], bx);
            atomicAdd(&g_bsp[cur][k][1], by);
        }
        atomicAdd(&g_sum_s[k], gs);
        atomicAdd(&g_ent, ge);
        atomicAdd(&g_A[k][0], gax);
        atomicAdd(&g_A[k][1], gay);
        atomicAdd(&g_P[k], gp);
    }

    // ---- stage C2: pooled features. warp wp owns channels 16*wp..16*wp+15,
    //      lane: k = tx&15, channel-half = tx>>4. x re-read from global (L1-hot).
    {
        const int k    = tx & 15;
        const int half = tx >> 4;
        const int cb4  = wp * 4 + half * 2;           // float4 index within row
        const float4* xg4 = (const float4*)(x + (size_t)n0 * CC);
        float4 A0 = make_float4(0.f,0.f,0.f,0.f);
        float4 A1 = make_float4(0.f,0.f,0.f,0.f);
        int cur = Bsm[0];
        for (int n = 0; n < MT; n++) {
            const int bv = Bsm[n];
            if (bv < 0) break;
            if (bv != cur) {
                float* base = out_pool + ((size_t)cur * KK + k) * CC + cb4 * 4;
                atomicAdd(base+0, A0.x); atomicAdd(base+1, A0.y);
                atomicAdd(base+2, A0.z); atomicAdd(base+3, A0.w);
                atomicAdd(base+4, A1.x); atomicAdd(base+5, A1.y);
                atomicAdd(base+6, A1.z); atomicAdd(base+7, A1.w);
                A0 = make_float4(0.f,0.f,0.f,0.f);
                A1 = make_float4(0.f,0.f,0.f,0.f);
                cur = bv;
            }
            const float sv = Ls[n*KK + k];
            const float4 x0 = xg4[n * (CC/4) + cb4];
            const float4 x1 = xg4[n * (CC/4) + cb4 + 1];
            A0.x += sv*x0.x; A0.y += sv*x0.y; A0.z += sv*x0.z; A0.w += sv*x0.w;
            A1.x += sv*x1.x; A1.y += sv*x1.y; A1.z += sv*x1.z; A1.w += sv*x1.w;
        }
        if (cur >= 0) {
            float* base = out_pool + ((size_t)cur * KK + k) * CC + cb4 * 4;
            atomicAdd(base+0, A0.x); atomicAdd(base+1, A0.y);
            atomicAdd(base+2, A0.z); atomicAdd(base+3, A0.w);
            atomicAdd(base+4, A1.x); atomicAdd(base+5, A1.y);
            atomicAdd(base+6, A1.z); atomicAdd(base+7, A1.w);
        }
    }
}

// -------- finalize: super-node mus, separation, losses --------
__global__ void finalize_kernel(const float* __restrict__ active,
                                float* __restrict__ mu_out,     // [B,K,2]
                                float* __restrict__ losses)     // [6]
{
    __shared__ float mus[BB][KK][2];
    __shared__ float red[256];
    const int tid = threadIdx.x;
    const int b = tid >> 4, k = tid & 15;

    const float denom = g_bs[b][k] + EPSF;
    const float mx = g_bsp[b][k][0] / denom;
    const float my = g_bsp[b][k][1] / denom;
    mus[b][k][0] = mx; mus[b][k][1] = my;
    mu_out[tid * 2]     = mx;
    mu_out[tid * 2 + 1] = my;
    __syncthreads();

    float rep = 0.f;
    #pragma unroll
    for (int j = 0; j < KK; j++) {
        if (j == k) continue;
        float dx = mus[b][k][0] - mus[b][j][0];
        float dy = mus[b][k][1] - mus[b][j][1];
        rep += 1.f / (dx*dx + dy*dy + 1.f);
    }
    red[tid] = rep;
    __syncthreads();
    for (int st = 128; st > 0; st >>= 1) {
        if (tid < st) red[tid] += red[tid + st];
        __syncthreads();
    }

    if (tid == 0) {
        const float sep = red[0] / ((float)(KK * (KK - 1)) + EPSF);
        const float entropy = -g_ent / (float)NN;
        float div = 0.f, prun = 0.f, spat = 0.f, spar = 0.f;
        for (int kk = 0; kk < KK; kk++) {
            const float avg = g_sum_s[kk] / (float)NN;
            div  += avg * __logf(avg + EPSF);
            const float am = active[kk];
            prun += fabsf(avg * (1.f - am));
            spar += am;
            const float S = g_sum_s[kk] + EPSF;
            const float mgx = g_A[kk][0] / S;
            const float mgy = g_A[kk][1] / S;
            spat += g_P[kk] / S - (mgx*mgx + mgy*mgy);
        }
        losses[0] = entropy;
        losses[1] = div;
        losses[2] = spat / (float)KK;
        losses[3] = prun / (float)KK;
        losses[4] = spar / (float)KK;
        losses[5] = sep;
    }
}

extern "C" void kernel_launch(void* const* d_in, const int* in_sizes, int n_in,
                              void* d_out, int out_size) {
    const float* x       = (const float*)d_in[0];
    const float* pos     = (const float*)d_in[1];
    const int*   batch   = (const int*)  d_in[2];
    const float* gumbel  = (const float*)d_in[3];
    const float* W1      = (const float*)d_in[4];
    const float* b1      = (const float*)d_in[5];
    const float* W2      = (const float*)d_in[6];
    const float* b2      = (const float*)d_in[7];
    const float* scaling = (const float*)d_in[8];
    const float* active  = (const float*)d_in[9];

    float* out = (float*)d_out;
    float* out_pool   = out;                                   // [B,K,C]
    float* out_s      = out + (size_t)BB*KK*CC;                // [N,K]
    float* out_mu     = out_s + (size_t)NN*KK;                 // [B,K,2]
    float* out_losses = out_mu + (size_t)BB*KK*2;              // [6]

    init_kernel<<<(BB*KK*CC + 255) / 256, 256>>>(out_pool);
    fused_kernel<<<(NN + MT - 1) / MT, 256>>>(
        x, pos, batch, gumbel, W1, b1, W2, b2, scaling, active, out_pool, out_s);
    finalize_kernel<<<1, 256>>>(active, out_mu, out_losses);
}

// round 4
// speedup vs baseline: 1.2575x; 1.0467x over previous
#include <cuda_runtime.h>
#include <cuda_bf16.h>
#include <cstdint>
#include <math.h>

#define NN 100000
#define CC 128
#define KK 16
#define BB 16
#define MT 128          // nodes per block
#define NTHREADS 256
#define EPSF 1e-9f

// ---------------- dynamic shared-memory layout (bytes) ----------------
#define OFF_XHI   0        // x_hi  bf16 [128][128], 16B-chunk XOR swizzle (32768)
#define OFF_XLO   32768    // x_lo
#define OFF_WHI   65536    // W1^T [n][k] bf16 hi
#define OFF_WLO   98304    // W1^T [n][k] bf16 lo
#define OFF_W2    131072   // W2 fp32 [128][16]          (8192)
#define OFF_LP    139264   // partial logits [2][128][16](16384)
#define OFF_LS    155648   // s [128][16]                (8192)
#define OFF_PS    163840   // pos [128][2]               (1024)
#define OFF_BSM   164864   // batch [128] int            (512)
#define OFF_B1    165376   // b1 [128]                   (512)
#define OFF_B2    165888   // 64
#define OFF_ACT   165952   // 64
#define OFF_SC    166016   // 4
#define SMEM_TOTAL 166080
// H fp32 [128][132] (67584 B) reuses OFF_XHI.. after MMA completes
#define HSTRIDE 132

// -------- device scratch --------
__device__ float g_sum_s[KK];
__device__ float g_ent;
__device__ float g_A[KK][2];
__device__ float g_P[KK];
__device__ float g_bs[BB][KK];
__device__ float g_bsp[BB][KK][2];
// W1^T bf16 hi/lo pre-swizzled [n][k] images (32KB each)
__device__ __align__(16) uint32_t g_W1sw_hi[CC * CC / 2];
__device__ __align__(16) uint32_t g_W1sw_lo[CC * CC / 2];

// swizzled byte offset inside a 128x128 bf16 tile, row-major 256B rows,
// 16B chunks XORed with (row & 7)
__host__ __device__ __forceinline__ uint32_t sw_off(int row, int chunk) {
    return (uint32_t)(row * 256 + ((chunk ^ (row & 7)) << 4));
}

// ---------------- PTX helpers ----------------
__device__ __forceinline__ uint32_t smem_u32(const void* p) {
    uint32_t a;
    asm("{ .reg .u64 t; cvta.to.shared.u64 t, %1; cvt.u32.u64 %0, t; }" : "=r"(a) : "l"(p));
    return a;
}
__device__ __forceinline__ void ldmx4(uint32_t* r, uint32_t addr) {
    asm volatile("ldmatrix.sync.aligned.m8n8.x4.shared.b16 {%0,%1,%2,%3}, [%4];"
                 : "=r"(r[0]), "=r"(r[1]), "=r"(r[2]), "=r"(r[3]) : "r"(addr));
}
__device__ __forceinline__ void ldmx2(uint32_t* r, uint32_t addr) {
    asm volatile("ldmatrix.sync.aligned.m8n8.x2.shared.b16 {%0,%1}, [%2];"
                 : "=r"(r[0]), "=r"(r[1]) : "r"(addr));
}
__device__ __forceinline__ void mma_bf16(float* d, const uint32_t* a, const uint32_t* b) {
    asm volatile("mma.sync.aligned.m16n8k16.row.col.f32.bf16.bf16.f32 "
                 "{%0,%1,%2,%3}, {%4,%5,%6,%7}, {%8,%9}, {%0,%1,%2,%3};"
                 : "+f"(d[0]), "+f"(d[1]), "+f"(d[2]), "+f"(d[3])
                 : "r"(a[0]), "r"(a[1]), "r"(a[2]), "r"(a[3]), "r"(b[0]), "r"(b[1]));
}

// ---------------- init: zero accum + out_pool, build W1^T [n][k] bf16 hi/lo images ----------------
__global__ void init_kernel(float* __restrict__ out_pool, const float* __restrict__ W1) {
    int i = blockIdx.x * blockDim.x + threadIdx.x;
    if (i < BB * KK * CC) out_pool[i] = 0.0f;
    if (i < KK) {
        g_sum_s[i] = 0.f; g_P[i] = 0.f;
        g_A[i][0] = 0.f; g_A[i][1] = 0.f;
    }
    if (i == 0) g_ent = 0.f;
    if (i < BB * KK)     ((float*)g_bs)[i] = 0.f;
    if (i < BB * KK * 2) ((float*)g_bsp)[i] = 0.f;

    // image element (n-row, k-col) = W1[k][n]; pairs of k packed into u32
    if (i < CC * CC / 2) {
        const int n  = i >> 6;            // 0..127
        const int cp = i & 63;            // k-pair index
        const int k0 = 2 * cp, k1 = 2 * cp + 1;
        const float f0 = W1[(size_t)k0 * CC + n];
        const float f1 = W1[(size_t)k1 * CC + n];
        __nv_bfloat16 h0 = __float2bfloat16(f0);
        __nv_bfloat16 h1 = __float2bfloat16(f1);
        __nv_bfloat16 l0 = __float2bfloat16(f0 - __bfloat162float(h0));
        __nv_bfloat16 l1 = __float2bfloat16(f1 - __bfloat162float(h1));
        const int chunk = cp >> 2;        // 16B chunk (4 k-pairs)
        const int p     = cp & 3;
        const uint32_t w = (sw_off(n, chunk) + p * 4) >> 2;
        g_W1sw_hi[w] = ((uint32_t)__bfloat16_as_ushort(h1) << 16) | __bfloat16_as_ushort(h0);
        g_W1sw_lo[w] = ((uint32_t)__bfloat16_as_ushort(l1) << 16) | __bfloat16_as_ushort(l0);
    }
}

__device__ __forceinline__ uint32_t pack_bf16_hi(float a, float b) {
    __nv_bfloat16 ha = __float2bfloat16(a), hb = __float2bfloat16(b);
    return ((uint32_t)__bfloat16_as_ushort(hb) << 16) | __bfloat16_as_ushort(ha);
}
__device__ __forceinline__ uint32_t pack_bf16_lo(float a, float b) {
    __nv_bfloat16 ha = __float2bfloat16(a), hb = __float2bfloat16(b);
    __nv_bfloat16 la = __float2bfloat16(a - __bfloat162float(ha));
    __nv_bfloat16 lb = __float2bfloat16(b - __bfloat162float(hb));
    return ((uint32_t)__bfloat16_as_ushort(lb) << 16) | __bfloat16_as_ushort(la);
}

// ---------------- fused kernel ----------------
__global__ __launch_bounds__(NTHREADS, 1)
void fused_kernel(const float* __restrict__ x,
                  const float* __restrict__ pos,
                  const int*   __restrict__ batch,
                  const float* __restrict__ gumbel,
                  const float* __restrict__ b1,
                  const float* __restrict__ W2,
                  const float* __restrict__ b2,
                  const float* __restrict__ scaling,
                  const float* __restrict__ active,
                  float* __restrict__ out_pool,
                  float* __restrict__ out_s)
{
    extern __shared__ __align__(16) char smem[];
    const uint32_t sb = smem_u32(smem);
    const int tid = threadIdx.x;
    const int tx  = tid & 31;
    const int wp  = tid >> 5;
    const int n0  = blockIdx.x * MT;
    const int nvalid = min(MT, NN - n0);

    float* W2s = (float*)(smem + OFF_W2);
    float* Lp  = (float*)(smem + OFF_LP);
    float* Ls  = (float*)(smem + OFF_LS);
    float* Ps  = (float*)(smem + OFF_PS);
    int*   Bsm = (int*)(smem + OFF_BSM);
    float* b1s = (float*)(smem + OFF_B1);
    float* b2s = (float*)(smem + OFF_B2);
    float* acts= (float*)(smem + OFF_ACT);
    float* scs = (float*)(smem + OFF_SC);

    // ---- prologue: W1 images verbatim copy (64KB) ----
    {
        const float4* srch = (const float4*)g_W1sw_hi;
        const float4* srcl = (const float4*)g_W1sw_lo;
        float4* dsth = (float4*)(smem + OFF_WHI);
        float4* dstl = (float4*)(smem + OFF_WLO);
        for (int i = tid; i < CC * CC / 8; i += NTHREADS) { dsth[i] = srch[i]; dstl[i] = srcl[i]; }
    }

    // ---- x tile: fp32 -> bf16 hi/lo into swizzled smem ([m][k]) ----
    {
        const float4* xg = (const float4*)(x + (size_t)n0 * CC);
        for (int i = tid; i < MT * CC / 8; i += NTHREADS) {   // 2048, 8 elems each
            const int row   = i >> 4;
            const int chunk = i & 15;
            float4 v0, v1;
            if (row < nvalid) {
                v0 = xg[(size_t)row * 32 + chunk * 2];
                v1 = xg[(size_t)row * 32 + chunk * 2 + 1];
            } else {
                v0 = v1 = make_float4(0.f, 0.f, 0.f, 0.f);
            }
            uint4 hi, lo;
            hi.x = pack_bf16_hi(v0.x, v0.y); hi.y = pack_bf16_hi(v0.z, v0.w);
            hi.z = pack_bf16_hi(v1.x, v1.y); hi.w = pack_bf16_hi(v1.z, v1.w);
            lo.x = pack_bf16_lo(v0.x, v0.y); lo.y = pack_bf16_lo(v0.z, v0.w);
            lo.z = pack_bf16_lo(v1.x, v1.y); lo.w = pack_bf16_lo(v1.z, v1.w);
            const uint32_t off = sw_off(row, chunk);
            *(uint4*)(smem + OFF_XHI + off) = hi;
            *(uint4*)(smem + OFF_XLO + off) = lo;
        }
    }

    // ---- small tiles ----
    for (int i = tid; i < CC * KK / 4; i += NTHREADS)
        ((float4*)W2s)[i] = ((const float4*)W2)[i];
    if (tid < CC) b1s[tid] = b1[tid];
    if (tid < KK) { b2s[tid] = b2[tid]; acts[tid] = active[tid]; }
    if (tid == 0) scs[0] = scaling[0];
    for (int i = tid; i < MT; i += NTHREADS) {
        if (i < nvalid) {
            Ps[2*i]   = pos[(size_t)(n0 + i) * 2];
            Ps[2*i+1] = pos[(size_t)(n0 + i) * 2 + 1];
            Bsm[i]    = batch[n0 + i];
        } else {
            Ps[2*i] = 0.f; Ps[2*i+1] = 0.f; Bsm[i] = -1;
        }
    }
    __syncthreads();

    // ---- stage A: H = x@W1 via 3-pass bf16 mma.sync ----
    // warp wp owns m rows wp*16..+15, all 128 n cols (16 n-tiles of 8)
    float fa[16][4];
    #pragma unroll
    for (int j = 0; j < 16; j++) { fa[j][0]=0.f; fa[j][1]=0.f; fa[j][2]=0.f; fa[j][3]=0.f; }
    {
        const int m0 = wp * 16;
        const int ar = m0 + (tx & 7) + (tx & 8);           // A-frag row for this lane
        const int br7 = tx & 7;                            // B-frag row (mod 8)
        const uint32_t sxh = sb + OFF_XHI, sxl = sb + OFF_XLO;
        const uint32_t swh = sb + OFF_WHI, swl = sb + OFF_WLO;

        // phase 1: W_hi with both A_hi and A_lo
        #pragma unroll
        for (int ks = 0; ks < 8; ks++) {
            const int ac = ks * 2 + (tx >> 4);
            const uint32_t a_off = sw_off(ar, ac);
            uint32_t ahi[4], alo[4];
            ldmx4(ahi, sxh + a_off);
            ldmx4(alo, sxl + a_off);
            const int bc = ks * 2 + ((tx >> 3) & 1);
            uint32_t b_addr = swh + sw_off(br7, bc);       // n0=0 tile; +2048 per n-tile
            uint32_t bf[16][2];
            #pragma unroll
            for (int j = 0; j < 16; j++) { ldmx2(bf[j], b_addr); b_addr += 2048; }
            #pragma unroll
            for (int j = 0; j < 16; j++) mma_bf16(fa[j], ahi, bf[j]);
            #pragma unroll
            for (int j = 0; j < 16; j++) mma_bf16(fa[j], alo, bf[j]);
        }
        // phase 2: W_lo with A_hi
        #pragma unroll
        for (int ks = 0; ks < 8; ks++) {
            const int ac = ks * 2 + (tx >> 4);
            uint32_t ahi[4];
            ldmx4(ahi, sxh + sw_off(ar, ac));
            const int bc = ks * 2 + ((tx >> 3) & 1);
            uint32_t b_addr = swl + sw_off(br7, bc);
            #pragma unroll
            for (int j = 0; j < 16; j++) {
                uint32_t bf2[2];
                ldmx2(bf2, b_addr); b_addr += 2048;
                mma_bf16(fa[j], ahi, bf2);
            }
        }
    }
    __syncthreads();   // all tile reads done; smem tiles become H storage

    // ---- store H = relu(acc + b1) to smem [128][HSTRIDE] fp32 ----
    {
        float* Hs = (float*)(smem + OFF_XHI);
        const int r0 = wp * 16 + (tx >> 2);
        const int r1 = r0 + 8;
        const int c0 = (tx & 3) * 2;
        #pragma unroll
        for (int j = 0; j < 16; j++) {
            const int c = j * 8 + c0;
            float2 v0, v1;
            v0.x = fmaxf(fa[j][0] + b1s[c], 0.f);
            v0.y = fmaxf(fa[j][1] + b1s[c+1], 0.f);
            v1.x = fmaxf(fa[j][2] + b1s[c], 0.f);
            v1.y = fmaxf(fa[j][3] + b1s[c+1], 0.f);
            *(float2*)(Hs + r0 * HSTRIDE + c) = v0;
            *(float2*)(Hs + r1 * HSTRIDE + c) = v1;
        }
    }
    __syncthreads();

    // ---- stage B: partial logits; thread = (row n, col-half) ----
    {
        const float* Hs = (const float*)(smem + OFF_XHI);
        const int n  = tid >> 1;
        const int h2 = tid & 1;
        const int colOff = h2 * 64;
        float4 a0, a1, a2, a3;
        if (h2 == 0) {
            a0 = *(const float4*)(b2s + 0);
            a1 = *(const float4*)(b2s + 4);
            a2 = *(const float4*)(b2s + 8);
            a3 = *(const float4*)(b2s + 12);
        } else {
            a0 = a1 = a2 = a3 = make_float4(0.f, 0.f, 0.f, 0.f);
        }
        const float* hrow = Hs + n * HSTRIDE + colOff;
        #pragma unroll 4
        for (int c = 0; c < 64; c++) {
            const float hv = hrow[c];
            const float4 w0 = *(const float4*)(W2s + (colOff + c) * KK + 0);
            const float4 w1 = *(const float4*)(W2s + (colOff + c) * KK + 4);
            const float4 w2 = *(const float4*)(W2s + (colOff + c) * KK + 8);
            const float4 w3 = *(const float4*)(W2s + (colOff + c) * KK + 12);
            a0.x += hv*w0.x; a0.y += hv*w0.y; a0.z += hv*w0.z; a0.w += hv*w0.w;
            a1.x += hv*w1.x; a1.y += hv*w1.y; a1.z += hv*w1.z; a1.w += hv*w1.w;
            a2.x += hv*w2.x; a2.y += hv*w2.y; a2.z += hv*w2.z; a2.w += hv*w2.w;
            a3.x += hv*w3.x; a3.y += hv*w3.y; a3.z += hv*w3.z; a3.w += hv*w3.w;
        }
        float* dst = Lp + (h2 * MT + n) * KK;
        *(float4*)(dst + 0)  = a0;
        *(float4*)(dst + 4)  = a1;
        *(float4*)(dst + 8)  = a2;
        *(float4*)(dst + 12) = a3;
    }
    __syncthreads();

    // ---- gumbel softmax (TAU = 1) ----
    if (tid < MT) {
        const int n = tid;
        if (n < nvalid) {
            float l[KK];
            const float sc = scs[0];
            const float4* g4 = (const float4*)(gumbel + (size_t)(n0 + n) * KK);
            #pragma unroll
            for (int q = 0; q < 4; q++) {
                float4 g = g4[q];
                float gv[4] = {g.x, g.y, g.z, g.w};
                #pragma unroll
                for (int j = 0; j < 4; j++) {
                    const int k = q*4 + j;
                    float lv = Lp[n*KK + k] + Lp[(MT + n)*KK + k];
                    lv = (acts[k] == 0.f) ? -1e9f : lv * sc;
                    l[k] = lv + gv[j];
                }
            }
            float m = -3.4e38f;
            #pragma unroll
            for (int k = 0; k < KK; k++) m = fmaxf(m, l[k]);
            float ssum = 0.f;
            #pragma unroll
            for (int k = 0; k < KK; k++) { l[k] = __expf(l[k] - m); ssum += l[k]; }
            const float inv = 1.f / ssum;
            float4* so = (float4*)(out_s + (size_t)(n0 + n) * KK);
            #pragma unroll
            for (int q = 0; q < 4; q++) {
                float4 v = make_float4(l[q*4]*inv, l[q*4+1]*inv, l[q*4+2]*inv, l[q*4+3]*inv);
                so[q] = v;
                *(float4*)(Ls + n*KK + q*4) = v;
            }
        } else {
            #pragma unroll
            for (int k = 0; k < KK; k++) Ls[n*KK + k] = 0.f;
        }
    }
    __syncthreads();

    // ---- stage C1: statistics ----
    const bool uniform = (nvalid == MT) && (Bsm[0] == Bsm[MT-1]);
    if (uniform) {
        const int k = tid >> 4;
        const int g = tid & 15;
        float gs = 0.f, ge = 0.f, gax = 0.f, gay = 0.f, gp = 0.f;
        #pragma unroll
        for (int j = 0; j < 8; j++) {
            const int n = g*8 + j;
            const float sv = Ls[n*KK + k];
            const float px = Ps[2*n], py = Ps[2*n+1];
            gs  += sv;
            ge  += sv * __logf(sv + EPSF);
            gax += sv * px;
            gay += sv * py;
            gp  += sv * (px*px + py*py);
        }
        #pragma unroll
        for (int off = 8; off > 0; off >>= 1) {
            gs  += __shfl_down_sync(0xffffffffu, gs,  off, 16);
            ge  += __shfl_down_sync(0xffffffffu, ge,  off, 16);
            gax += __shfl_down_sync(0xffffffffu, gax, off, 16);
            gay += __shfl_down_sync(0xffffffffu, gay, off, 16);
            gp  += __shfl_down_sync(0xffffffffu, gp,  off, 16);
        }
        if (g == 0) {
            const int b = Bsm[0];
            atomicAdd(&g_sum_s[k], gs);
            atomicAdd(&g_ent, ge);
            atomicAdd(&g_A[k][0], gax);
            atomicAdd(&g_A[k][1], gay);
            atomicAdd(&g_P[k], gp);
            atomicAdd(&g_bs[b][k], gs);
            atomicAdd(&g_bsp[b][k][0], gax);
            atomicAdd(&g_bsp[b][k][1], gay);
        }
    } else if (tid < KK) {
        const int k = tid;
        float gs = 0.f, ge = 0.f, gax = 0.f, gay = 0.f, gp = 0.f;
        int cur = Bsm[0];
        float bs = 0.f, bx = 0.f, by = 0.f;
        for (int n = 0; n < MT; n++) {
            const int bv = Bsm[n];
            if (bv < 0) break;
            if (bv != cur) {
                atomicAdd(&g_bs[cur][k], bs);
                atomicAdd(&g_bsp[cur][k][0], bx);
                atomicAdd(&g_bsp[cur][k][1], by);
                bs = bx = by = 0.f; cur = bv;
            }
            const float sv = Ls[n*KK + k];
            const float px = Ps[2*n], py = Ps[2*n+1];
            gs  += sv;
            ge  += sv * __logf(sv + EPSF);
            gax += sv * px;
            gay += sv * py;
            gp  += sv * (px*px + py*py);
            bs  += sv; bx += sv * px; by += sv * py;
        }
        if (cur >= 0) {
            atomicAdd(&g_bs[cur][k], bs);
            atomicAdd(&g_bsp[cur][k][0], bx);
            atomicAdd(&g_bsp[cur][k][1], by);
        }
        atomicAdd(&g_sum_s[k], gs);
        atomicAdd(&g_ent, ge);
        atomicAdd(&g_A[k][0], gax);
        atomicAdd(&g_A[k][1], gay);
        atomicAdd(&g_P[k], gp);
    }

    // ---- stage C2: pooled features ----
    {
        const int k    = tx & 15;
        const int half = tx >> 4;
        const int cb4  = wp * 4 + half * 2;
        const float4* xg4 = (const float4*)(x + (size_t)n0 * CC);
        float4 A0 = make_float4(0.f,0.f,0.f,0.f);
        float4 A1 = make_float4(0.f,0.f,0.f,0.f);
        int cur = Bsm[0];
        for (int n = 0; n < MT; n++) {
            const int bv = Bsm[n];
            if (bv < 0) break;
            if (bv != cur) {
                float* base = out_pool + ((size_t)cur * KK + k) * CC + cb4 * 4;
                atomicAdd(base+0, A0.x); atomicAdd(base+1, A0.y);
                atomicAdd(base+2, A0.z); atomicAdd(base+3, A0.w);
                atomicAdd(base+4, A1.x); atomicAdd(base+5, A1.y);
                atomicAdd(base+6, A1.z); atomicAdd(base+7, A1.w);
                A0 = make_float4(0.f,0.f,0.f,0.f);
                A1 = make_float4(0.f,0.f,0.f,0.f);
                cur = bv;
            }
            const float sv = Ls[n*KK + k];
            const float4 x0 = xg4[(size_t)n * 32 + cb4];
            const float4 x1 = xg4[(size_t)n * 32 + cb4 + 1];
            A0.x += sv*x0.x; A0.y += sv*x0.y; A0.z += sv*x0.z; A0.w += sv*x0.w;
            A1.x += sv*x1.x; A1.y += sv*x1.y; A1.z += sv*x1.z; A1.w += sv*x1.w;
        }
        if (cur >= 0) {
            float* base = out_pool + ((size_t)cur * KK + k) * CC + cb4 * 4;
            atomicAdd(base+0, A0.x); atomicAdd(base+1, A0.y);
            atomicAdd(base+2, A0.z); atomicAdd(base+3, A0.w);
            atomicAdd(base+4, A1.x); atomicAdd(base+5, A1.y);
            atomicAdd(base+6, A1.z); atomicAdd(base+7, A1.w);
        }
    }
}

// -------- finalize --------
__global__ void finalize_kernel(const float* __restrict__ active,
                                float* __restrict__ mu_out,
                                float* __restrict__ losses)
{
    __shared__ float mus[BB][KK][2];
    __shared__ float red[256];
    const int tid = threadIdx.x;
    const int b = tid >> 4, k = tid & 15;

    const float denom = g_bs[b][k] + EPSF;
    const float mx = g_bsp[b][k][0] / denom;
    const float my = g_bsp[b][k][1] / denom;
    mus[b][k][0] = mx; mus[b][k][1] = my;
    mu_out[tid * 2]     = mx;
    mu_out[tid * 2 + 1] = my;
    __syncthreads();

    float rep = 0.f;
    #pragma unroll
    for (int j = 0; j < KK; j++) {
        if (j == k) continue;
        float dx = mus[b][k][0] - mus[b][j][0];
        float dy = mus[b][k][1] - mus[b][j][1];
        rep += 1.f / (dx*dx + dy*dy + 1.f);
    }
    red[tid] = rep;
    __syncthreads();
    for (int st = 128; st > 0; st >>= 1) {
        if (tid < st) red[tid] += red[tid + st];
        __syncthreads();
    }

    if (tid == 0) {
        const float sep = red[0] / ((float)(KK * (KK - 1)) + EPSF);
        const float entropy = -g_ent / (float)NN;
        float div = 0.f, prun = 0.f, spat = 0.f, spar = 0.f;
        for (int kk = 0; kk < KK; kk++) {
            const float avg = g_sum_s[kk] / (float)NN;
            div  += avg * __logf(avg + EPSF);
            const float am = active[kk];
            prun += fabsf(avg * (1.f - am));
            spar += am;
            const float S = g_sum_s[kk] + EPSF;
            const float mgx = g_A[kk][0] / S;
            const float mgy = g_A[kk][1] / S;
            spat += g_P[kk] / S - (mgx*mgx + mgy*mgy);
        }
        losses[0] = entropy;
        losses[1] = div;
        losses[2] = spat / (float)KK;
        losses[3] = prun / (float)KK;
        losses[4] = spar / (float)KK;
        losses[5] = sep;
    }
}

extern "C" void kernel_launch(void* const* d_in, const int* in_sizes, int n_in,
                              void* d_out, int out_size) {
    const float* x       = (const float*)d_in[0];
    const float* pos     = (const float*)d_in[1];
    const int*   batch   = (const int*)  d_in[2];
    const float* gumbel  = (const float*)d_in[3];
    const float* W1      = (const float*)d_in[4];
    const float* b1      = (const float*)d_in[5];
    const float* W2      = (const float*)d_in[6];
    const float* b2      = (const float*)d_in[7];
    const float* scaling = (const float*)d_in[8];
    const float* active  = (const float*)d_in[9];

    float* out = (float*)d_out;
    float* out_pool   = out;
    float* out_s      = out + (size_t)BB*KK*CC;
    float* out_mu     = out_s + (size_t)NN*KK;
    float* out_losses = out_mu + (size_t)BB*KK*2;

    cudaFuncSetAttribute(fused_kernel, cudaFuncAttributeMaxDynamicSharedMemorySize,
                         SMEM_TOTAL);

    init_kernel<<<128, 256>>>(out_pool, W1);
    fused_kernel<<<(NN + MT - 1) / MT, NTHREADS, SMEM_TOTAL>>>(
        x, pos, batch, gumbel, b1, W2, b2, scaling, active, out_pool, out_s);
    finalize_kernel<<<1, 256>>>(active, out_mu, out_losses);
}

// round 5
// speedup vs baseline: 2.0949x; 1.6659x over previous
#include <cuda_runtime.h>
#include <cuda_bf16.h>
#include <cstdint>
#include <math.h>

#define NN 100000
#define CC 128
#define KK 16
#define BB 16
#define MT 128          // nodes per block
#define NTHREADS 256
#define EPSF 1e-9f
#define TSTR 272        // padded row stride (bytes) for sT / W2T 16-row tiles

// ---------------- dynamic shared-memory layout (bytes) ----------------
#define OFF_XHI   0        // x_hi  bf16 [128][128], 16B-chunk XOR swizzle (32768)
#define OFF_XLO   32768    // x_lo
#define OFF_WHI   65536    // W1^T [n][k] bf16 hi
#define OFF_WLO   98304    // W1^T [n][k] bf16 lo
#define OFF_W2TH  131072   // W2^T [16][128] bf16 hi, 272B row stride (4352)
#define OFF_W2TL  135424   // W2^T lo
#define OFF_STH   139776   // s^T  [16][128] bf16 hi (4352)
#define OFF_STL   144128   // s^T  lo
#define OFF_LS    148480   // logits then s, fp32 [128][16]  (8192)
#define OFF_PS    156672   // pos [128][2]               (1024)
#define OFF_BSM   157696   // batch [128] int            (512)
#define OFF_B1    158208   // b1 [128]                   (512)
#define OFF_B2    158720   // 64
#define OFF_ACT   158784   // 64
#define OFF_SC    158848   // 16
#define SMEM_TOTAL 158976

// -------- device scratch --------
__device__ float g_sum_s[KK];
__device__ float g_ent;
__device__ float g_A[KK][2];
__device__ float g_P[KK];
__device__ float g_bs[BB][KK];
__device__ float g_bsp[BB][KK][2];
// W1^T bf16 hi/lo pre-swizzled [n][k] images (32KB each)
__device__ __align__(16) uint32_t g_W1sw_hi[CC * CC / 2];
__device__ __align__(16) uint32_t g_W1sw_lo[CC * CC / 2];

// swizzled byte offset inside a 128x128 bf16 tile, row-major 256B rows,
// 16B chunks XORed with (row & 7)
__host__ __device__ __forceinline__ uint32_t sw_off(int row, int chunk) {
    return (uint32_t)(row * 256 + ((chunk ^ (row & 7)) << 4));
}

// ---------------- PTX helpers ----------------
__device__ __forceinline__ uint32_t smem_u32(const void* p) {
    uint32_t a;
    asm("{ .reg .u64 t; cvta.to.shared.u64 t, %1; cvt.u32.u64 %0, t; }" : "=r"(a) : "l"(p));
    return a;
}
__device__ __forceinline__ void ldmx4(uint32_t* r, uint32_t addr) {
    asm volatile("ldmatrix.sync.aligned.m8n8.x4.shared.b16 {%0,%1,%2,%3}, [%4];"
                 : "=r"(r[0]), "=r"(r[1]), "=r"(r[2]), "=r"(r[3]) : "r"(addr));
}
__device__ __forceinline__ void ldmx2(uint32_t* r, uint32_t addr) {
    asm volatile("ldmatrix.sync.aligned.m8n8.x2.shared.b16 {%0,%1}, [%2];"
                 : "=r"(r[0]), "=r"(r[1]) : "r"(addr));
}
__device__ __forceinline__ void ldmx2t(uint32_t* r, uint32_t addr) {
    asm volatile("ldmatrix.sync.aligned.m8n8.x2.trans.shared.b16 {%0,%1}, [%2];"
                 : "=r"(r[0]), "=r"(r[1]) : "r"(addr));
}
__device__ __forceinline__ void mma_bf16(float* d, const uint32_t* a, const uint32_t* b) {
    asm volatile("mma.sync.aligned.m16n8k16.row.col.f32.bf16.bf16.f32 "
                 "{%0,%1,%2,%3}, {%4,%5,%6,%7}, {%8,%9}, {%0,%1,%2,%3};"
                 : "+f"(d[0]), "+f"(d[1]), "+f"(d[2]), "+f"(d[3])
                 : "r"(a[0]), "r"(a[1]), "r"(a[2]), "r"(a[3]), "r"(b[0]), "r"(b[1]));
}

__device__ __forceinline__ uint32_t pack_bf16_hi(float a, float b) {
    __nv_bfloat16 ha = __float2bfloat16(a), hb = __float2bfloat16(b);
    return ((uint32_t)__bfloat16_as_ushort(hb) << 16) | __bfloat16_as_ushort(ha);
}
__device__ __forceinline__ uint32_t pack_bf16_lo(float a, float b) {
    __nv_bfloat16 ha = __float2bfloat16(a), hb = __float2bfloat16(b);
    __nv_bfloat16 la = __float2bfloat16(a - __bfloat162float(ha));
    __nv_bfloat16 lb = __float2bfloat16(b - __bfloat162float(hb));
    return ((uint32_t)__bfloat16_as_ushort(lb) << 16) | __bfloat16_as_ushort(la);
}

// ---------------- init: zero accum + out_pool, build W1^T [n][k] bf16 hi/lo images ----------------
__global__ void init_kernel(float* __restrict__ out_pool, const float* __restrict__ W1) {
    int i = blockIdx.x * blockDim.x + threadIdx.x;
    if (i < BB * KK * CC) out_pool[i] = 0.0f;
    if (i < KK) {
        g_sum_s[i] = 0.f; g_P[i] = 0.f;
        g_A[i][0] = 0.f; g_A[i][1] = 0.f;
    }
    if (i == 0) g_ent = 0.f;
    if (i < BB * KK)     ((float*)g_bs)[i] = 0.f;
    if (i < BB * KK * 2) ((float*)g_bsp)[i] = 0.f;

    // image element (n-row, k-col) = W1[k][n]; pairs of k packed into u32
    if (i < CC * CC / 2) {
        const int n  = i >> 6;            // 0..127
        const int cp = i & 63;            // k-pair index
        const int k0 = 2 * cp, k1 = 2 * cp + 1;
        const float f0 = W1[(size_t)k0 * CC + n];
        const float f1 = W1[(size_t)k1 * CC + n];
        __nv_bfloat16 h0 = __float2bfloat16(f0);
        __nv_bfloat16 h1 = __float2bfloat16(f1);
        __nv_bfloat16 l0 = __float2bfloat16(f0 - __bfloat162float(h0));
        __nv_bfloat16 l1 = __float2bfloat16(f1 - __bfloat162float(h1));
        const int chunk = cp >> 2;        // 16B chunk (4 k-pairs)
        const int p     = cp & 3;
        const uint32_t w = (sw_off(n, chunk) + p * 4) >> 2;
        g_W1sw_hi[w] = ((uint32_t)__bfloat16_as_ushort(h1) << 16) | __bfloat16_as_ushort(h0);
        g_W1sw_lo[w] = ((uint32_t)__bfloat16_as_ushort(l1) << 16) | __bfloat16_as_ushort(l0);
    }
}

// ---------------- fused kernel ----------------
__global__ __launch_bounds__(NTHREADS, 1)
void fused_kernel(const float* __restrict__ x,
                  const float* __restrict__ pos,
                  const int*   __restrict__ batch,
                  const float* __restrict__ gumbel,
                  const float* __restrict__ b1,
                  const float* __restrict__ W2,
                  const float* __restrict__ b2,
                  const float* __restrict__ scaling,
                  const float* __restrict__ active,
                  float* __restrict__ out_pool,
                  float* __restrict__ out_s)
{
    extern __shared__ __align__(16) char smem[];
    const uint32_t sb = smem_u32(smem);
    const int tid = threadIdx.x;
    const int tx  = tid & 31;
    const int wp  = tid >> 5;
    const int n0  = blockIdx.x * MT;
    const int nvalid = min(MT, NN - n0);

    float* Ls  = (float*)(smem + OFF_LS);
    float* Ps  = (float*)(smem + OFF_PS);
    int*   Bsm = (int*)(smem + OFF_BSM);
    float* b1s = (float*)(smem + OFF_B1);
    float* b2s = (float*)(smem + OFF_B2);
    float* acts= (float*)(smem + OFF_ACT);
    float* scs = (float*)(smem + OFF_SC);

    // ---- prologue: W1 images verbatim copy (64KB) ----
    {
        const float4* srch = (const float4*)g_W1sw_hi;
        const float4* srcl = (const float4*)g_W1sw_lo;
        float4* dsth = (float4*)(smem + OFF_WHI);
        float4* dstl = (float4*)(smem + OFF_WLO);
        for (int i = tid; i < CC * CC / 8; i += NTHREADS) { dsth[i] = srch[i]; dstl[i] = srcl[i]; }
    }

    // ---- x tile: fp32 -> bf16 hi/lo into swizzled smem ([m][k]) ----
    {
        const float4* xg = (const float4*)(x + (size_t)n0 * CC);
        for (int i = tid; i < MT * CC / 8; i += NTHREADS) {   // 2048 groups of 8 elems
            const int row   = i >> 4;
            const int chunk = i & 15;
            float4 v0, v1;
            if (row < nvalid) {
                v0 = xg[(size_t)row * 32 + chunk * 2];
                v1 = xg[(size_t)row * 32 + chunk * 2 + 1];
            } else {
                v0 = v1 = make_float4(0.f, 0.f, 0.f, 0.f);
            }
            uint4 hi, lo;
            hi.x = pack_bf16_hi(v0.x, v0.y); hi.y = pack_bf16_hi(v0.z, v0.w);
            hi.z = pack_bf16_hi(v1.x, v1.y); hi.w = pack_bf16_hi(v1.z, v1.w);
            lo.x = pack_bf16_lo(v0.x, v0.y); lo.y = pack_bf16_lo(v0.z, v0.w);
            lo.z = pack_bf16_lo(v1.x, v1.y); lo.w = pack_bf16_lo(v1.z, v1.w);
            const uint32_t off = sw_off(row, chunk);
            *(uint4*)(smem + OFF_XHI + off) = hi;
            *(uint4*)(smem + OFF_XLO + off) = lo;
        }
    }

    // ---- W2^T bf16 hi/lo tile [16][128], 272B row stride ----
    for (int i = tid; i < CC * KK; i += NTHREADS) {
        const int c = i >> 4, k = i & 15;
        const float v = W2[i];
        __nv_bfloat16 h = __float2bfloat16(v);
        __nv_bfloat16 l = __float2bfloat16(v - __bfloat162float(h));
        *(__nv_bfloat16*)(smem + OFF_W2TH + k * TSTR + c * 2) = h;
        *(__nv_bfloat16*)(smem + OFF_W2TL + k * TSTR + c * 2) = l;
    }

    // ---- small tiles ----
    if (tid < CC) b1s[tid] = b1[tid];
    if (tid < KK) { b2s[tid] = b2[tid]; acts[tid] = active[tid]; }
    if (tid == 0) scs[0] = scaling[0];
    for (int i = tid; i < MT; i += NTHREADS) {
        if (i < nvalid) {
            Ps[2*i]   = pos[(size_t)(n0 + i) * 2];
            Ps[2*i+1] = pos[(size_t)(n0 + i) * 2 + 1];
            Bsm[i]    = batch[n0 + i];
        } else {
            Ps[2*i] = 0.f; Ps[2*i+1] = 0.f; Bsm[i] = -1;
        }
    }
    __syncthreads();

    // ---- stage A: H = x@W1 via 3-pass bf16 mma.sync ----
    float fa[16][4];
    #pragma unroll
    for (int j = 0; j < 16; j++) { fa[j][0]=0.f; fa[j][1]=0.f; fa[j][2]=0.f; fa[j][3]=0.f; }
    {
        const int m0 = wp * 16;
        const int ar = m0 + (tx & 7) + (tx & 8);
        const int br7 = tx & 7;
        const uint32_t sxh = sb + OFF_XHI, sxl = sb + OFF_XLO;
        const uint32_t swh = sb + OFF_WHI, swl = sb + OFF_WLO;

        #pragma unroll
        for (int ks = 0; ks < 8; ks++) {
            const int ac = ks * 2 + (tx >> 4);
            const uint32_t a_off = sw_off(ar, ac);
            uint32_t ahi[4], alo[4];
            ldmx4(ahi, sxh + a_off);
            ldmx4(alo, sxl + a_off);
            const int bc = ks * 2 + ((tx >> 3) & 1);
            uint32_t b_addr = swh + sw_off(br7, bc);
            uint32_t bf[16][2];
            #pragma unroll
            for (int j = 0; j < 16; j++) { ldmx2(bf[j], b_addr); b_addr += 2048; }
            #pragma unroll
            for (int j = 0; j < 16; j++) mma_bf16(fa[j], ahi, bf[j]);
            #pragma unroll
            for (int j = 0; j < 16; j++) mma_bf16(fa[j], alo, bf[j]);
        }
        #pragma unroll
        for (int ks = 0; ks < 8; ks++) {
            const int ac = ks * 2 + (tx >> 4);
            uint32_t ahi[4];
            ldmx4(ahi, sxh + sw_off(ar, ac));
            const int bc = ks * 2 + ((tx >> 3) & 1);
            uint32_t b_addr = swl + sw_off(br7, bc);
            #pragma unroll
            for (int j = 0; j < 16; j++) {
                uint32_t bf2[2];
                ldmx2(bf2, b_addr); b_addr += 2048;
                mma_bf16(fa[j], ahi, bf2);
            }
        }
    }

    // ---- relu(H + b1) in registers ----
    const int q2 = (tx & 3) * 2;
    #pragma unroll
    for (int j = 0; j < 16; j++) {
        const float bc0 = b1s[j*8 + q2], bc1 = b1s[j*8 + q2 + 1];
        fa[j][0] = fmaxf(fa[j][0] + bc0, 0.f);
        fa[j][1] = fmaxf(fa[j][1] + bc1, 0.f);
        fa[j][2] = fmaxf(fa[j][2] + bc0, 0.f);
        fa[j][3] = fmaxf(fa[j][3] + bc1, 0.f);
    }

    // ---- stage B as MMA: logits = H @ W2, 3-pass (A from accum regs) ----
    float lg0[4] = {0.f,0.f,0.f,0.f}, lg1[4] = {0.f,0.f,0.f,0.f};
    {
        const int br = tx & 7;
        const int bsel = (tx >> 3) & 1;
        const uint32_t w2th = sb + OFF_W2TH, w2tl = sb + OFF_W2TL;
        #pragma unroll
        for (int ks = 0; ks < 8; ks++) {
            uint32_t ah[4], al[4];
            ah[0] = pack_bf16_hi(fa[2*ks][0],   fa[2*ks][1]);
            ah[1] = pack_bf16_hi(fa[2*ks][2],   fa[2*ks][3]);
            ah[2] = pack_bf16_hi(fa[2*ks+1][0], fa[2*ks+1][1]);
            ah[3] = pack_bf16_hi(fa[2*ks+1][2], fa[2*ks+1][3]);
            al[0] = pack_bf16_lo(fa[2*ks][0],   fa[2*ks][1]);
            al[1] = pack_bf16_lo(fa[2*ks][2],   fa[2*ks][3]);
            al[2] = pack_bf16_lo(fa[2*ks+1][0], fa[2*ks+1][1]);
            al[3] = pack_bf16_lo(fa[2*ks+1][2], fa[2*ks+1][3]);
            const uint32_t coff = (uint32_t)(ks * 2 + bsel) * 16;
            uint32_t bh[2], bl[2];
            ldmx2(bh, w2th + br * TSTR + coff);
            ldmx2(bl, w2tl + br * TSTR + coff);
            mma_bf16(lg0, ah, bh); mma_bf16(lg0, al, bh); mma_bf16(lg0, ah, bl);
            ldmx2(bh, w2th + (8 + br) * TSTR + coff);
            ldmx2(bl, w2tl + (8 + br) * TSTR + coff);
            mma_bf16(lg1, ah, bh); mma_bf16(lg1, al, bh); mma_bf16(lg1, ah, bl);
        }
    }
    // write raw logits (pre-bias/scale) to Ls
    {
        const int r = wp * 16 + (tx >> 2);
        *(float2*)(Ls + r * KK + q2)           = make_float2(lg0[0], lg0[1]);
        *(float2*)(Ls + (r + 8) * KK + q2)     = make_float2(lg0[2], lg0[3]);
        *(float2*)(Ls + r * KK + 8 + q2)       = make_float2(lg1[0], lg1[1]);
        *(float2*)(Ls + (r + 8) * KK + 8 + q2) = make_float2(lg1[2], lg1[3]);
    }
    __syncthreads();

    // ---- gumbel softmax (TAU = 1); also writes s^T bf16 hi/lo tiles ----
    if (tid < MT) {
        const int n = tid;
        if (n < nvalid) {
            float l[KK];
            const float sc = scs[0];
            const float4* g4 = (const float4*)(gumbel + (size_t)(n0 + n) * KK);
            #pragma unroll
            for (int q = 0; q < 4; q++) {
                float4 g = g4[q];
                float gv[4] = {g.x, g.y, g.z, g.w};
                #pragma unroll
                for (int j = 0; j < 4; j++) {
                    const int k = q*4 + j;
                    float lv = Ls[n*KK + k] + b2s[k];
                    lv = (acts[k] == 0.f) ? -1e9f : lv * sc;
                    l[k] = lv + gv[j];
                }
            }
            float m = -3.4e38f;
            #pragma unroll
            for (int k = 0; k < KK; k++) m = fmaxf(m, l[k]);
            float ssum = 0.f;
            #pragma unroll
            for (int k = 0; k < KK; k++) { l[k] = __expf(l[k] - m); ssum += l[k]; }
            const float inv = 1.f / ssum;
            float4* so = (float4*)(out_s + (size_t)(n0 + n) * KK);
            #pragma unroll
            for (int q = 0; q < 4; q++) {
                float4 v = make_float4(l[q*4]*inv, l[q*4+1]*inv, l[q*4+2]*inv, l[q*4+3]*inv);
                so[q] = v;
                *(float4*)(Ls + n*KK + q*4) = v;
            }
            #pragma unroll
            for (int k = 0; k < KK; k++) {
                const float v = l[k] * inv;
                __nv_bfloat16 sh = __float2bfloat16(v);
                __nv_bfloat16 sl = __float2bfloat16(v - __bfloat162float(sh));
                *(__nv_bfloat16*)(smem + OFF_STH + k * TSTR + n * 2) = sh;
                *(__nv_bfloat16*)(smem + OFF_STL + k * TSTR + n * 2) = sl;
            }
        } else {
            #pragma unroll
            for (int k = 0; k < KK; k++) {
                Ls[n*KK + k] = 0.f;
                *(__nv_bfloat16*)(smem + OFF_STH + k * TSTR + n * 2) = __float2bfloat16(0.f);
                *(__nv_bfloat16*)(smem + OFF_STL + k * TSTR + n * 2) = __float2bfloat16(0.f);
            }
        }
    }
    __syncthreads();

    // ---- stage C1: statistics ----
    const bool uniform = (nvalid == MT) && (Bsm[0] == Bsm[MT-1]);
    if (uniform) {
        const int k = tid >> 4;
        const int g = tid & 15;
        float gs = 0.f, ge = 0.f, gax = 0.f, gay = 0.f, gp = 0.f;
        #pragma unroll
        for (int j = 0; j < 8; j++) {
            const int n = g*8 + j;
            const float sv = Ls[n*KK + k];
            const float px = Ps[2*n], py = Ps[2*n+1];
            gs  += sv;
            ge  += sv * __logf(sv + EPSF);
            gax += sv * px;
            gay += sv * py;
            gp  += sv * (px*px + py*py);
        }
        #pragma unroll
        for (int off = 8; off > 0; off >>= 1) {
            gs  += __shfl_down_sync(0xffffffffu, gs,  off, 16);
            ge  += __shfl_down_sync(0xffffffffu, ge,  off, 16);
            gax += __shfl_down_sync(0xffffffffu, gax, off, 16);
            gay += __shfl_down_sync(0xffffffffu, gay, off, 16);
            gp  += __shfl_down_sync(0xffffffffu, gp,  off, 16);
        }
        if (g == 0) {
            const int b = Bsm[0];
            atomicAdd(&g_sum_s[k], gs);
            atomicAdd(&g_ent, ge);
            atomicAdd(&g_A[k][0], gax);
            atomicAdd(&g_A[k][1], gay);
            atomicAdd(&g_P[k], gp);
            atomicAdd(&g_bs[b][k], gs);
            atomicAdd(&g_bsp[b][k][0], gax);
            atomicAdd(&g_bsp[b][k][1], gay);
        }
    } else if (tid < KK) {
        const int k = tid;
        float gs = 0.f, ge = 0.f, gax = 0.f, gay = 0.f, gp = 0.f;
        int cur = Bsm[0];
        float bs = 0.f, bx = 0.f, by = 0.f;
        for (int n = 0; n < MT; n++) {
            const int bv = Bsm[n];
            if (bv < 0) break;
            if (bv != cur) {
                atomicAdd(&g_bs[cur][k], bs);
                atomicAdd(&g_bsp[cur][k][0], bx);
                atomicAdd(&g_bsp[cur][k][1], by);
                bs = bx = by = 0.f; cur = bv;
            }
            const float sv = Ls[n*KK + k];
            const float px = Ps[2*n], py = Ps[2*n+1];
            gs  += sv;
            ge  += sv * __logf(sv + EPSF);
            gax += sv * px;
            gay += sv * py;
            gp  += sv * (px*px + py*py);
            bs  += sv; bx += sv * px; by += sv * py;
        }
        if (cur >= 0) {
            atomicAdd(&g_bs[cur][k], bs);
            atomicAdd(&g_bsp[cur][k][0], bx);
            atomicAdd(&g_bsp[cur][k][1], by);
        }
        atomicAdd(&g_sum_s[k], gs);
        atomicAdd(&g_ent, ge);
        atomicAdd(&g_A[k][0], gax);
        atomicAdd(&g_A[k][1], gay);
        atomicAdd(&g_P[k], gp);
    }

    // ---- stage C2: pooled features ----
    if (uniform) {
        // out[b] += s^T @ x via MMA: M=16 (classes), N=128 (channels, split 16/warp), K=128 (nodes)
        float p0[4] = {0.f,0.f,0.f,0.f}, p1[4] = {0.f,0.f,0.f,0.f};
        const uint32_t sth = sb + OFF_STH, stl = sb + OFF_STL;
        const uint32_t xhi = sb + OFF_XHI, xlo = sb + OFF_XLO;
        const int arow = tx & 15;
        const int asel = tx >> 4;
        #pragma unroll
        for (int ks = 0; ks < 8; ks++) {
            uint32_t sah[4], sal[4];
            const uint32_t aoff = (uint32_t)arow * TSTR + (uint32_t)(ks * 2 + asel) * 16;
            ldmx4(sah, sth + aoff);
            ldmx4(sal, stl + aoff);
            const int brow = ks * 16 + (tx & 15);
            uint32_t bh[2], bl[2];
            ldmx2t(bh, xhi + sw_off(brow, wp * 2));
            ldmx2t(bl, xlo + sw_off(brow, wp * 2));
            mma_bf16(p0, sah, bh); mma_bf16(p0, sal, bh); mma_bf16(p0, sah, bl);
            ldmx2t(bh, xhi + sw_off(brow, wp * 2 + 1));
            ldmx2t(bl, xlo + sw_off(brow, wp * 2 + 1));
            mma_bf16(p1, sah, bh); mma_bf16(p1, sal, bh); mma_bf16(p1, sah, bl);
        }
        const int b  = Bsm[0];
        const int kr = tx >> 2;
        float* base0 = out_pool + ((size_t)b * KK + kr) * CC + wp * 16;
        float* base1 = out_pool + ((size_t)b * KK + kr + 8) * CC + wp * 16;
        atomicAdd(base0 + q2,         p0[0]); atomicAdd(base0 + q2 + 1,     p0[1]);
        atomicAdd(base1 + q2,         p0[2]); atomicAdd(base1 + q2 + 1,     p0[3]);
        atomicAdd(base0 + 8 + q2,     p1[0]); atomicAdd(base0 + 8 + q2 + 1, p1[1]);
        atomicAdd(base1 + 8 + q2,     p1[2]); atomicAdd(base1 + 8 + q2 + 1, p1[3]);
    } else {
        const int k    = tx & 15;
        const int half = tx >> 4;
        const int cb4  = wp * 4 + half * 2;
        const float4* xg4 = (const float4*)(x + (size_t)n0 * CC);
        float4 A0 = make_float4(0.f,0.f,0.f,0.f);
        float4 A1 = make_float4(0.f,0.f,0.f,0.f);
        int cur = Bsm[0];
        for (int n = 0; n < MT; n++) {
            const int bv = Bsm[n];
            if (bv < 0) break;
            if (bv != cur) {
                float* base = out_pool + ((size_t)cur * KK + k) * CC + cb4 * 4;
                atomicAdd(base+0, A0.x); atomicAdd(base+1, A0.y);
                atomicAdd(base+2, A0.z); atomicAdd(base+3, A0.w);
                atomicAdd(base+4, A1.x); atomicAdd(base+5, A1.y);
                atomicAdd(base+6, A1.z); atomicAdd(base+7, A1.w);
                A0 = make_float4(0.f,0.f,0.f,0.f);
                A1 = make_float4(0.f,0.f,0.f,0.f);
                cur = bv;
            }
            const float sv = Ls[n*KK + k];
            const float4 x0 = xg4[(size_t)n * 32 + cb4];
            const float4 x1 = xg4[(size_t)n * 32 + cb4 + 1];
            A0.x += sv*x0.x; A0.y += sv*x0.y; A0.z += sv*x0.z; A0.w += sv*x0.w;
            A1.x += sv*x1.x; A1.y += sv*x1.y; A1.z += sv*x1.z; A1.w += sv*x1.w;
        }
        if (cur >= 0) {
            float* base = out_pool + ((size_t)cur * KK + k) * CC + cb4 * 4;
            atomicAdd(base+0, A0.x); atomicAdd(base+1, A0.y);
            atomicAdd(base+2, A0.z); atomicAdd(base+3, A0.w);
            atomicAdd(base+4, A1.x); atomicAdd(base+5, A1.y);
            atomicAdd(base+6, A1.z); atomicAdd(base+7, A1.w);
        }
    }
}

// -------- finalize --------
__global__ void finalize_kernel(const float* __restrict__ active,
                                float* __restrict__ mu_out,
                                float* __restrict__ losses)
{
    __shared__ float mus[BB][KK][2];
    __shared__ float red[256];
    const int tid = threadIdx.x;
    const int b = tid >> 4, k = tid & 15;

    const float denom = g_bs[b][k] + EPSF;
    const float mx = g_bsp[b][k][0] / denom;
    const float my = g_bsp[b][k][1] / denom;
    mus[b][k][0] = mx; mus[b][k][1] = my;
    mu_out[tid * 2]     = mx;
    mu_out[tid * 2 + 1] = my;
    __syncthreads();

    float rep = 0.f;
    #pragma unroll
    for (int j = 0; j < KK; j++) {
        if (j == k) continue;
        float dx = mus[b][k][0] - mus[b][j][0];
        float dy = mus[b][k][1] - mus[b][j][1];
        rep += 1.f / (dx*dx + dy*dy + 1.f);
    }
    red[tid] = rep;
    __syncthreads();
    for (int st = 128; st > 0; st >>= 1) {
        if (tid < st) red[tid] += red[tid + st];
        __syncthreads();
    }

    if (tid == 0) {
        const float sep = red[0] / ((float)(KK * (KK - 1)) + EPSF);
        const float entropy = -g_ent / (float)NN;
        float div = 0.f, prun = 0.f, spat = 0.f, spar = 0.f;
        for (int kk = 0; kk < KK; kk++) {
            const float avg = g_sum_s[kk] / (float)NN;
            div  += avg * __logf(avg + EPSF);
            const float am = active[kk];
            prun += fabsf(avg * (1.f - am));
            spar += am;
            const float S = g_sum_s[kk] + EPSF;
            const float mgx = g_A[kk][0] / S;
            const float mgy = g_A[kk][1] / S;
            spat += g_P[kk] / S - (mgx*mgx + mgy*mgy);
        }
        losses[0] = entropy;
        losses[1] = div;
        losses[2] = spat / (float)KK;
        losses[3] = prun / (float)KK;
        losses[4] = spar / (float)KK;
        losses[5] = sep;
    }
}

extern "C" void kernel_launch(void* const* d_in, const int* in_sizes, int n_in,
                              void* d_out, int out_size) {
    const float* x       = (const float*)d_in[0];
    const float* pos     = (const float*)d_in[1];
    const int*   batch   = (const int*)  d_in[2];
    const float* gumbel  = (const float*)d_in[3];
    const float* W1      = (const float*)d_in[4];
    const float* b1      = (const float*)d_in[5];
    const float* W2      = (const float*)d_in[6];
    const float* b2      = (const float*)d_in[7];
    const float* scaling = (const float*)d_in[8];
    const float* active  = (const float*)d_in[9];

    float* out = (float*)d_out;
    float* out_pool   = out;
    float* out_s      = out + (size_t)BB*KK*CC;
    float* out_mu     = out_s + (size_t)NN*KK;
    float* out_losses = out_mu + (size_t)BB*KK*2;

    cudaFuncSetAttribute(fused_kernel, cudaFuncAttributeMaxDynamicSharedMemorySize,
                         SMEM_TOTAL);

    init_kernel<<<128, 256>>>(out_pool, W1);
    fused_kernel<<<(NN + MT - 1) / MT, NTHREADS, SMEM_TOTAL>>>(
        x, pos, batch, gumbel, b1, W2, b2, scaling, active, out_pool, out_s);
    finalize_kernel<<<1, 256>>>(active, out_mu, out_losses);
}

// round 6
// speedup vs baseline: 2.4883x; 1.1878x over previous
#include <cuda_runtime.h>
#include <cuda_bf16.h>
#include <cstdint>
#include <math.h>

#define NN 100000
#define CC 128
#define KK 16
#define BB 16
#define MT 128          // nodes per block
#define NTHREADS 256
#define EPSF 1e-9f
#define TSTR 272        // padded row stride (bytes) for sT / W2T 16-row tiles

// ---------------- dynamic shared-memory layout (bytes) ----------------
#define OFF_XHI   0        // x_hi  bf16 [128][128], 16B-chunk XOR swizzle (32768)
#define OFF_XLO   32768    // x_lo
#define OFF_W2TH  65536    // W2^T [16][128] bf16 hi, 272B row stride (4352)
#define OFF_W2TL  69888    // W2^T lo
#define OFF_STH   74240    // s^T  [16][128] bf16 hi (4352)
#define OFF_STL   78592    // s^T  lo
#define OFF_LS    82944    // logits then s, fp32 [128][16]  (8192)
#define OFF_PS    91136    // pos [128][2]               (1024)
#define OFF_BSM   92160    // batch [128] int            (512)
#define OFF_B1    92672    // b1 [128]                   (512)
#define OFF_B2    93184    // 64
#define OFF_ACT   93248    // 64
#define OFF_SC    93312    // 16
#define SMEM_TOTAL 93328

// -------- device scratch --------
__device__ float g_sum_s[KK];
__device__ float g_ent;
__device__ float g_A[KK][2];
__device__ float g_P[KK];
__device__ float g_bs[BB][KK];
__device__ float g_bsp[BB][KK][2];
// W1 in mma.sync B-fragment order: [ks=8][j=16][lane=32] x uint4(bh0,bh1,bl0,bl1)
__device__ __align__(16) uint4 g_W1frag[8 * 16 * 32];

// swizzled byte offset inside a 128x128 bf16 tile, row-major 256B rows,
// 16B chunks XORed with (row & 7)
__host__ __device__ __forceinline__ uint32_t sw_off(int row, int chunk) {
    return (uint32_t)(row * 256 + ((chunk ^ (row & 7)) << 4));
}

// ---------------- PTX helpers ----------------
__device__ __forceinline__ uint32_t smem_u32(const void* p) {
    uint32_t a;
    asm("{ .reg .u64 t; cvta.to.shared.u64 t, %1; cvt.u32.u64 %0, t; }" : "=r"(a) : "l"(p));
    return a;
}
__device__ __forceinline__ void ldmx4(uint32_t* r, uint32_t addr) {
    asm volatile("ldmatrix.sync.aligned.m8n8.x4.shared.b16 {%0,%1,%2,%3}, [%4];"
                 : "=r"(r[0]), "=r"(r[1]), "=r"(r[2]), "=r"(r[3]) : "r"(addr));
}
__device__ __forceinline__ void ldmx2(uint32_t* r, uint32_t addr) {
    asm volatile("ldmatrix.sync.aligned.m8n8.x2.shared.b16 {%0,%1}, [%2];"
                 : "=r"(r[0]), "=r"(r[1]) : "r"(addr));
}
__device__ __forceinline__ void ldmx2t(uint32_t* r, uint32_t addr) {
    asm volatile("ldmatrix.sync.aligned.m8n8.x2.trans.shared.b16 {%0,%1}, [%2];"
                 : "=r"(r[0]), "=r"(r[1]) : "r"(addr));
}
__device__ __forceinline__ void mma_bf16(float* d, const uint32_t* a, const uint32_t* b) {
    asm volatile("mma.sync.aligned.m16n8k16.row.col.f32.bf16.bf16.f32 "
                 "{%0,%1,%2,%3}, {%4,%5,%6,%7}, {%8,%9}, {%0,%1,%2,%3};"
                 : "+f"(d[0]), "+f"(d[1]), "+f"(d[2]), "+f"(d[3])
                 : "r"(a[0]), "r"(a[1]), "r"(a[2]), "r"(a[3]), "r"(b[0]), "r"(b[1]));
}

__device__ __forceinline__ uint32_t pack_bf16_hi(float a, float b) {
    __nv_bfloat16 ha = __float2bfloat16(a), hb = __float2bfloat16(b);
    return ((uint32_t)__bfloat16_as_ushort(hb) << 16) | __bfloat16_as_ushort(ha);
}
__device__ __forceinline__ uint32_t pack_bf16_lo(float a, float b) {
    __nv_bfloat16 ha = __float2bfloat16(a), hb = __float2bfloat16(b);
    __nv_bfloat16 la = __float2bfloat16(a - __bfloat162float(ha));
    __nv_bfloat16 lb = __float2bfloat16(b - __bfloat162float(hb));
    return ((uint32_t)__bfloat16_as_ushort(lb) << 16) | __bfloat16_as_ushort(la);
}

// ---------------- init: zero accum + out_pool, build W1 fragment array ----------------
__global__ void init_kernel(float* __restrict__ out_pool, const float* __restrict__ W1) {
    int i = blockIdx.x * blockDim.x + threadIdx.x;
    if (i < BB * KK * CC) out_pool[i] = 0.0f;
    if (i < KK) {
        g_sum_s[i] = 0.f; g_P[i] = 0.f;
        g_A[i][0] = 0.f; g_A[i][1] = 0.f;
    }
    if (i == 0) g_ent = 0.f;
    if (i < BB * KK)     ((float*)g_bs)[i] = 0.f;
    if (i < BB * KK * 2) ((float*)g_bsp)[i] = 0.f;

    // B-fragment for mma.m16n8k16 col-major B:
    // lane t: b0 = B[k=(t%4)*2+{0,1}][n=t/4], b1 = same with k+8
    // B tile for (ks, j): n = j*8.., k = ks*16..  ;  B[k][n] = W1[k][n]
    if (i < 8 * 16 * 32) {
        const int ks = i >> 9;
        const int j  = (i >> 5) & 15;
        const int t  = i & 31;
        const int n  = j * 8 + (t >> 2);
        const int k0 = ks * 16 + (t & 3) * 2;
        const float f00 = W1[(size_t)(k0 + 0) * CC + n];
        const float f01 = W1[(size_t)(k0 + 1) * CC + n];
        const float f10 = W1[(size_t)(k0 + 8) * CC + n];
        const float f11 = W1[(size_t)(k0 + 9) * CC + n];
        uint4 w;
        w.x = pack_bf16_hi(f00, f01);
        w.y = pack_bf16_hi(f10, f11);
        w.z = pack_bf16_lo(f00, f01);
        w.w = pack_bf16_lo(f10, f11);
        g_W1frag[i] = w;
    }
}

// ---------------- fused kernel ----------------
__global__ __launch_bounds__(NTHREADS, 2)
void fused_kernel(const float* __restrict__ x,
                  const float* __restrict__ pos,
                  const int*   __restrict__ batch,
                  const float* __restrict__ gumbel,
                  const float* __restrict__ b1,
                  const float* __restrict__ W2,
                  const float* __restrict__ b2,
                  const float* __restrict__ scaling,
                  const float* __restrict__ active,
                  float* __restrict__ out_pool,
                  float* __restrict__ out_s)
{
    extern __shared__ __align__(16) char smem[];
    const uint32_t sb = smem_u32(smem);
    const int tid = threadIdx.x;
    const int tx  = tid & 31;
    const int wp  = tid >> 5;
    const int n0  = blockIdx.x * MT;
    const int nvalid = min(MT, NN - n0);

    float* Ls  = (float*)(smem + OFF_LS);
    float* Ps  = (float*)(smem + OFF_PS);
    int*   Bsm = (int*)(smem + OFF_BSM);
    float* b1s = (float*)(smem + OFF_B1);
    float* b2s = (float*)(smem + OFF_B2);
    float* acts= (float*)(smem + OFF_ACT);
    float* scs = (float*)(smem + OFF_SC);

    // ---- x tile: fp32 -> bf16 hi/lo into swizzled smem ([m][k]) ----
    {
        const float4* xg = (const float4*)(x + (size_t)n0 * CC);
        for (int i = tid; i < MT * CC / 8; i += NTHREADS) {   // 2048 groups of 8 elems
            const int row   = i >> 4;
            const int chunk = i & 15;
            float4 v0, v1;
            if (row < nvalid) {
                v0 = xg[(size_t)row * 32 + chunk * 2];
                v1 = xg[(size_t)row * 32 + chunk * 2 + 1];
            } else {
                v0 = v1 = make_float4(0.f, 0.f, 0.f, 0.f);
            }
            uint4 hi, lo;
            hi.x = pack_bf16_hi(v0.x, v0.y); hi.y = pack_bf16_hi(v0.z, v0.w);
            hi.z = pack_bf16_hi(v1.x, v1.y); hi.w = pack_bf16_hi(v1.z, v1.w);
            lo.x = pack_bf16_lo(v0.x, v0.y); lo.y = pack_bf16_lo(v0.z, v0.w);
            lo.z = pack_bf16_lo(v1.x, v1.y); lo.w = pack_bf16_lo(v1.z, v1.w);
            const uint32_t off = sw_off(row, chunk);
            *(uint4*)(smem + OFF_XHI + off) = hi;
            *(uint4*)(smem + OFF_XLO + off) = lo;
        }
    }

    // ---- W2^T bf16 hi/lo tile [16][128], 272B row stride ----
    for (int i = tid; i < CC * KK; i += NTHREADS) {
        const int c = i >> 4, k = i & 15;
        const float v = W2[i];
        __nv_bfloat16 h = __float2bfloat16(v);
        __nv_bfloat16 l = __float2bfloat16(v - __bfloat162float(h));
        *(__nv_bfloat16*)(smem + OFF_W2TH + k * TSTR + c * 2) = h;
        *(__nv_bfloat16*)(smem + OFF_W2TL + k * TSTR + c * 2) = l;
    }

    // ---- small tiles ----
    if (tid < CC) b1s[tid] = b1[tid];
    if (tid < KK) { b2s[tid] = b2[tid]; acts[tid] = active[tid]; }
    if (tid == 0) scs[0] = scaling[0];
    for (int i = tid; i < MT; i += NTHREADS) {
        if (i < nvalid) {
            Ps[2*i]   = pos[(size_t)(n0 + i) * 2];
            Ps[2*i+1] = pos[(size_t)(n0 + i) * 2 + 1];
            Bsm[i]    = batch[n0 + i];
        } else {
            Ps[2*i] = 0.f; Ps[2*i+1] = 0.f; Bsm[i] = -1;
        }
    }
    __syncthreads();

    // ---- stage A: H = x@W1, 3-pass folded into one loop; W1 B-frags via LDG ----
    float fa[16][4];
    #pragma unroll
    for (int j = 0; j < 16; j++) { fa[j][0]=0.f; fa[j][1]=0.f; fa[j][2]=0.f; fa[j][3]=0.f; }
    {
        const int ar = wp * 16 + (tx & 7) + (tx & 8);
        const uint32_t sxh = sb + OFF_XHI, sxl = sb + OFF_XLO;
        const uint4* wf = g_W1frag + tx;
        #pragma unroll
        for (int ks = 0; ks < 8; ks++) {
            const int ac = ks * 2 + (tx >> 4);
            const uint32_t a_off = sw_off(ar, ac);
            uint32_t ahi[4], alo[4];
            ldmx4(ahi, sxh + a_off);
            ldmx4(alo, sxl + a_off);
            #pragma unroll
            for (int j = 0; j < 16; j++) {
                const uint4 w = __ldg(wf + (ks * 16 + j) * 32);
                uint32_t bh[2], bl[2];
                bh[0] = w.x; bh[1] = w.y; bl[0] = w.z; bl[1] = w.w;
                mma_bf16(fa[j], ahi, bh);
                mma_bf16(fa[j], alo, bh);
                mma_bf16(fa[j], ahi, bl);
            }
        }
    }

    // ---- relu(H + b1) in registers ----
    const int q2 = (tx & 3) * 2;
    #pragma unroll
    for (int j = 0; j < 16; j++) {
        const float bc0 = b1s[j*8 + q2], bc1 = b1s[j*8 + q2 + 1];
        fa[j][0] = fmaxf(fa[j][0] + bc0, 0.f);
        fa[j][1] = fmaxf(fa[j][1] + bc1, 0.f);
        fa[j][2] = fmaxf(fa[j][2] + bc0, 0.f);
        fa[j][3] = fmaxf(fa[j][3] + bc1, 0.f);
    }

    // ---- stage B as MMA: logits = H @ W2, 3-pass (A from accum regs) ----
    float lg0[4] = {0.f,0.f,0.f,0.f}, lg1[4] = {0.f,0.f,0.f,0.f};
    {
        const int br = tx & 7;
        const int bsel = (tx >> 3) & 1;
        const uint32_t w2th = sb + OFF_W2TH, w2tl = sb + OFF_W2TL;
        #pragma unroll
        for (int ks = 0; ks < 8; ks++) {
            uint32_t ah[4], al[4];
            ah[0] = pack_bf16_hi(fa[2*ks][0],   fa[2*ks][1]);
            ah[1] = pack_bf16_hi(fa[2*ks][2],   fa[2*ks][3]);
            ah[2] = pack_bf16_hi(fa[2*ks+1][0], fa[2*ks+1][1]);
            ah[3] = pack_bf16_hi(fa[2*ks+1][2], fa[2*ks+1][3]);
            al[0] = pack_bf16_lo(fa[2*ks][0],   fa[2*ks][1]);
            al[1] = pack_bf16_lo(fa[2*ks][2],   fa[2*ks][3]);
            al[2] = pack_bf16_lo(fa[2*ks+1][0], fa[2*ks+1][1]);
            al[3] = pack_bf16_lo(fa[2*ks+1][2], fa[2*ks+1][3]);
            const uint32_t coff = (uint32_t)(ks * 2 + bsel) * 16;
            uint32_t bh[2], bl[2];
            ldmx2(bh, w2th + br * TSTR + coff);
            ldmx2(bl, w2tl + br * TSTR + coff);
            mma_bf16(lg0, ah, bh); mma_bf16(lg0, al, bh); mma_bf16(lg0, ah, bl);
            ldmx2(bh, w2th + (8 + br) * TSTR + coff);
            ldmx2(bl, w2tl + (8 + br) * TSTR + coff);
            mma_bf16(lg1, ah, bh); mma_bf16(lg1, al, bh); mma_bf16(lg1, ah, bl);
        }
    }
    // write raw logits (pre-bias/scale) to Ls
    {
        const int r = wp * 16 + (tx >> 2);
        *(float2*)(Ls + r * KK + q2)           = make_float2(lg0[0], lg0[1]);
        *(float2*)(Ls + (r + 8) * KK + q2)     = make_float2(lg0[2], lg0[3]);
        *(float2*)(Ls + r * KK + 8 + q2)       = make_float2(lg1[0], lg1[1]);
        *(float2*)(Ls + (r + 8) * KK + 8 + q2) = make_float2(lg1[2], lg1[3]);
    }
    __syncthreads();

    // ---- gumbel softmax (TAU = 1), 2 threads per node; writes s^T bf16 tiles ----
    {
        const int n    = tid >> 1;
        const int half = tid & 1;
        if (n < nvalid) {
            float l[8];
            const float sc = scs[0];
            const float4* g4 = (const float4*)(gumbel + (size_t)(n0 + n) * KK) + half * 2;
            #pragma unroll
            for (int q = 0; q < 2; q++) {
                float4 g = g4[q];
                float gv[4] = {g.x, g.y, g.z, g.w};
                #pragma unroll
                for (int j = 0; j < 4; j++) {
                    const int k = half * 8 + q * 4 + j;
                    float lv = Ls[n*KK + k] + b2s[k];
                    lv = (acts[k] == 0.f) ? -1e9f : lv * sc;
                    l[q*4 + j] = lv + gv[j];
                }
            }
            float m = -3.4e38f;
            #pragma unroll
            for (int k = 0; k < 8; k++) m = fmaxf(m, l[k]);
            m = fmaxf(m, __shfl_xor_sync(0xffffffffu, m, 1));
            float ssum = 0.f;
            #pragma unroll
            for (int k = 0; k < 8; k++) { l[k] = __expf(l[k] - m); ssum += l[k]; }
            ssum += __shfl_xor_sync(0xffffffffu, ssum, 1);
            const float inv = 1.f / ssum;
            float4* so = (float4*)(out_s + (size_t)(n0 + n) * KK) + half * 2;
            #pragma unroll
            for (int q = 0; q < 2; q++) {
                float4 v = make_float4(l[q*4]*inv, l[q*4+1]*inv, l[q*4+2]*inv, l[q*4+3]*inv);
                so[q] = v;
                *(float4*)(Ls + n*KK + half*8 + q*4) = v;
            }
            #pragma unroll
            for (int k = 0; k < 8; k++) {
                const float v = l[k] * inv;
                const int kk = half * 8 + k;
                __nv_bfloat16 sh = __float2bfloat16(v);
                __nv_bfloat16 sl = __float2bfloat16(v - __bfloat162float(sh));
                *(__nv_bfloat16*)(smem + OFF_STH + kk * TSTR + n * 2) = sh;
                *(__nv_bfloat16*)(smem + OFF_STL + kk * TSTR + n * 2) = sl;
            }
        } else {
            #pragma unroll
            for (int k = 0; k < 8; k++) {
                const int kk = half * 8 + k;
                Ls[n*KK + kk] = 0.f;
                *(__nv_bfloat16*)(smem + OFF_STH + kk * TSTR + n * 2) = __float2bfloat16(0.f);
                *(__nv_bfloat16*)(smem + OFF_STL + kk * TSTR + n * 2) = __float2bfloat16(0.f);
            }
        }
    }
    __syncthreads();

    // ---- stage C1: statistics ----
    const bool uniform = (nvalid == MT) && (Bsm[0] == Bsm[MT-1]);
    if (uniform) {
        const int k = tid >> 4;
        const int g = tid & 15;
        float gs = 0.f, ge = 0.f, gax = 0.f, gay = 0.f, gp = 0.f;
        #pragma unroll
        for (int j = 0; j < 8; j++) {
            const int n = g*8 + j;
            const float sv = Ls[n*KK + k];
            const float px = Ps[2*n], py = Ps[2*n+1];
            gs  += sv;
            ge  += sv * __logf(sv + EPSF);
            gax += sv * px;
            gay += sv * py;
            gp  += sv * (px*px + py*py);
        }
        #pragma unroll
        for (int off = 8; off > 0; off >>= 1) {
            gs  += __shfl_down_sync(0xffffffffu, gs,  off, 16);
            ge  += __shfl_down_sync(0xffffffffu, ge,  off, 16);
            gax += __shfl_down_sync(0xffffffffu, gax, off, 16);
            gay += __shfl_down_sync(0xffffffffu, gay, off, 16);
            gp  += __shfl_down_sync(0xffffffffu, gp,  off, 16);
        }
        if (g == 0) {
            const int b = Bsm[0];
            atomicAdd(&g_sum_s[k], gs);
            atomicAdd(&g_ent, ge);
            atomicAdd(&g_A[k][0], gax);
            atomicAdd(&g_A[k][1], gay);
            atomicAdd(&g_P[k], gp);
            atomicAdd(&g_bs[b][k], gs);
            atomicAdd(&g_bsp[b][k][0], gax);
            atomicAdd(&g_bsp[b][k][1], gay);
        }
    } else if (tid < KK) {
        const int k = tid;
        float gs = 0.f, ge = 0.f, gax = 0.f, gay = 0.f, gp = 0.f;
        int cur = Bsm[0];
        float bs = 0.f, bx = 0.f, by = 0.f;
        for (int n = 0; n < MT; n++) {
            const int bv = Bsm[n];
            if (bv < 0) break;
            if (bv != cur) {
                atomicAdd(&g_bs[cur][k], bs);
                atomicAdd(&g_bsp[cur][k][0], bx);
                atomicAdd(&g_bsp[cur][k][1], by);
                bs = bx = by = 0.f; cur = bv;
            }
            const float sv = Ls[n*KK + k];
            const float px = Ps[2*n], py = Ps[2*n+1];
            gs  += sv;
            ge  += sv * __logf(sv + EPSF);
            gax += sv * px;
            gay += sv * py;
            gp  += sv * (px*px + py*py);
            bs  += sv; bx += sv * px; by += sv * py;
        }
        if (cur >= 0) {
            atomicAdd(&g_bs[cur][k], bs);
            atomicAdd(&g_bsp[cur][k][0], bx);
            atomicAdd(&g_bsp[cur][k][1], by);
        }
        atomicAdd(&g_sum_s[k], gs);
        atomicAdd(&g_ent, ge);
        atomicAdd(&g_A[k][0], gax);
        atomicAdd(&g_A[k][1], gay);
        atomicAdd(&g_P[k], gp);
    }

    // ---- stage C2: pooled features ----
    if (uniform) {
        // out[b] += s^T @ x via MMA: M=16 (classes), N=128 (channels, 16/warp), K=128 (nodes)
        float p0[4] = {0.f,0.f,0.f,0.f}, p1[4] = {0.f,0.f,0.f,0.f};
        const uint32_t sth = sb + OFF_STH, stl = sb + OFF_STL;
        const uint32_t xhi = sb + OFF_XHI, xlo = sb + OFF_XLO;
        const int arow = tx & 15;
        const int asel = tx >> 4;
        #pragma unroll
        for (int ks = 0; ks < 8; ks++) {
            uint32_t sah[4], sal[4];
            const uint32_t aoff = (uint32_t)arow * TSTR + (uint32_t)(ks * 2 + asel) * 16;
            ldmx4(sah, sth + aoff);
            ldmx4(sal, stl + aoff);
            const int brow = ks * 16 + (tx & 15);
            uint32_t bh[2], bl[2];
            ldmx2t(bh, xhi + sw_off(brow, wp * 2));
            ldmx2t(bl, xlo + sw_off(brow, wp * 2));
            mma_bf16(p0, sah, bh); mma_bf16(p0, sal, bh); mma_bf16(p0, sah, bl);
            ldmx2t(bh, xhi + sw_off(brow, wp * 2 + 1));
            ldmx2t(bl, xlo + sw_off(brow, wp * 2 + 1));
            mma_bf16(p1, sah, bh); mma_bf16(p1, sal, bh); mma_bf16(p1, sah, bl);
        }
        const int b  = Bsm[0];
        const int kr = tx >> 2;
        float* base0 = out_pool + ((size_t)b * KK + kr) * CC + wp * 16;
        float* base1 = out_pool + ((size_t)b * KK + kr + 8) * CC + wp * 16;
        atomicAdd(base0 + q2,         p0[0]); atomicAdd(base0 + q2 + 1,     p0[1]);
        atomicAdd(base1 + q2,         p0[2]); atomicAdd(base1 + q2 + 1,     p0[3]);
        atomicAdd(base0 + 8 + q2,     p1[0]); atomicAdd(base0 + 8 + q2 + 1, p1[1]);
        atomicAdd(base1 + 8 + q2,     p1[2]); atomicAdd(base1 + 8 + q2 + 1, p1[3]);
    } else {
        const int k    = tx & 15;
        const int half = tx >> 4;
        const int cb4  = wp * 4 + half * 2;
        const float4* xg4 = (const float4*)(x + (size_t)n0 * CC);
        float4 A0 = make_float4(0.f,0.f,0.f,0.f);
        float4 A1 = make_float4(0.f,0.f,0.f,0.f);
        int cur = Bsm[0];
        for (int n = 0; n < MT; n++) {
            const int bv = Bsm[n];
            if (bv < 0) break;
            if (bv != cur) {
                float* base = out_pool + ((size_t)cur * KK + k) * CC + cb4 * 4;
                atomicAdd(base+0, A0.x); atomicAdd(base+1, A0.y);
                atomicAdd(base+2, A0.z); atomicAdd(base+3, A0.w);
                atomicAdd(base+4, A1.x); atomicAdd(base+5, A1.y);
                atomicAdd(base+6, A1.z); atomicAdd(base+7, A1.w);
                A0 = make_float4(0.f,0.f,0.f,0.f);
                A1 = make_float4(0.f,0.f,0.f,0.f);
                cur = bv;
            }
            const float sv = Ls[n*KK + k];
            const float4 x0 = xg4[(size_t)n * 32 + cb4];
            const float4 x1 = xg4[(size_t)n * 32 + cb4 + 1];
            A0.x += sv*x0.x; A0.y += sv*x0.y; A0.z += sv*x0.z; A0.w += sv*x0.w;
            A1.x += sv*x1.x; A1.y += sv*x1.y; A1.z += sv*x1.z; A1.w += sv*x1.w;
        }
        if (cur >= 0) {
            float* base = out_pool + ((size_t)cur * KK + k) * CC + cb4 * 4;
            atomicAdd(base+0, A0.x); atomicAdd(base+1, A0.y);
            atomicAdd(base+2, A0.z); atomicAdd(base+3, A0.w);
            atomicAdd(base+4, A1.x); atomicAdd(base+5, A1.y);
            atomicAdd(base+6, A1.z); atomicAdd(base+7, A1.w);
        }
    }
}

// -------- finalize --------
__global__ void finalize_kernel(const float* __restrict__ active,
                                float* __restrict__ mu_out,
                                float* __restrict__ losses)
{
    __shared__ float mus[BB][KK][2];
    __shared__ float red[256];
    const int tid = threadIdx.x;
    const int b = tid >> 4, k = tid & 15;

    const float denom = g_bs[b][k] + EPSF;
    const float mx = g_bsp[b][k][0] / denom;
    const float my = g_bsp[b][k][1] / denom;
    mus[b][k][0] = mx; mus[b][k][1] = my;
    mu_out[tid * 2]     = mx;
    mu_out[tid * 2 + 1] = my;
    __syncthreads();

    float rep = 0.f;
    #pragma unroll
    for (int j = 0; j < KK; j++) {
        if (j == k) continue;
        float dx = mus[b][k][0] - mus[b][j][0];
        float dy = mus[b][k][1] - mus[b][j][1];
        rep += 1.f / (dx*dx + dy*dy + 1.f);
    }
    red[tid] = rep;
    __syncthreads();
    for (int st = 128; st > 0; st >>= 1) {
        if (tid < st) red[tid] += red[tid + st];
        __syncthreads();
    }

    if (tid == 0) {
        const float sep = red[0] / ((float)(KK * (KK - 1)) + EPSF);
        const float entropy = -g_ent / (float)NN;
        float div = 0.f, prun = 0.f, spat = 0.f, spar = 0.f;
        for (int kk = 0; kk < KK; kk++) {
            const float avg = g_sum_s[kk] / (float)NN;
            div  += avg * __logf(avg + EPSF);
            const float am = active[kk];
            prun += fabsf(avg * (1.f - am));
            spar += am;
            const float S = g_sum_s[kk] + EPSF;
            const float mgx = g_A[kk][0] / S;
            const float mgy = g_A[kk][1] / S;
            spat += g_P[kk] / S - (mgx*mgx + mgy*mgy);
        }
        losses[0] = entropy;
        losses[1] = div;
        losses[2] = spat / (float)KK;
        losses[3] = prun / (float)KK;
        losses[4] = spar / (float)KK;
        losses[5] = sep;
    }
}

extern "C" void kernel_launch(void* const* d_in, const int* in_sizes, int n_in,
                              void* d_out, int out_size) {
    const float* x       = (const float*)d_in[0];
    const float* pos     = (const float*)d_in[1];
    const int*   batch   = (const int*)  d_in[2];
    const float* gumbel  = (const float*)d_in[3];
    const float* W1      = (const float*)d_in[4];
    const float* b1      = (const float*)d_in[5];
    const float* W2      = (const float*)d_in[6];
    const float* b2      = (const float*)d_in[7];
    const float* scaling = (const float*)d_in[8];
    const float* active  = (const float*)d_in[9];

    float* out = (float*)d_out;
    float* out_pool   = out;
    float* out_s      = out + (size_t)BB*KK*CC;
    float* out_mu     = out_s + (size_t)NN*KK;
    float* out_losses = out_mu + (size_t)BB*KK*2;

    cudaFuncSetAttribute(fused_kernel, cudaFuncAttributeMaxDynamicSharedMemorySize,
                         SMEM_TOTAL);

    init_kernel<<<128, 256>>>(out_pool, W1);
    fused_kernel<<<(NN + MT - 1) / MT, NTHREADS, SMEM_TOTAL>>>(
        x, pos, batch, gumbel, b1, W2, b2, scaling, active, out_pool, out_s);
    finalize_kernel<<<1, 256>>>(active, out_mu, out_losses);
}

// round 7
// speedup vs baseline: 2.5995x; 1.0447x over previous
#include <cuda_runtime.h>
#include <cuda_bf16.h>
#include <cstdint>
#include <math.h>

#define NN 100000
#define CC 128
#define KK 16
#define BB 16
#define MT 128          // nodes per block
#define NTHREADS 256
#define EPSF 1e-9f
#define TSTR 272        // padded row stride (bytes) for sT / W2T 16-row tiles

// ---------------- dynamic shared-memory layout (bytes) ----------------
#define OFF_XHI   0        // x_hi  bf16 [128][128], 16B-chunk XOR swizzle (32768)
#define OFF_XLO   32768    // x_lo
#define OFF_W2TH  65536    // W2^T [16][128] bf16 hi, 272B row stride (4352)
#define OFF_W2TL  69888    // W2^T lo
#define OFF_STH   74240    // s^T  [16][128] bf16 hi (4352)
#define OFF_STL   78592    // s^T  lo
#define OFF_LS    82944    // s fp32 [128][16]           (8192)
#define OFF_GUM   91136    // gumbel fp32 [128][16]      (8192)
#define OFF_PS    99328    // pos [128][2]               (1024)
#define OFF_BSM   100352   // batch [128] int            (512)
#define OFF_B1    100864   // b1 [128]                   (512)
#define OFF_B2    101376   // 64
#define OFF_ACT   101440   // 64
#define OFF_SC    101504   // 16
#define SMEM_TOTAL 101520

// -------- device scratch --------
__device__ float g_sum_s[KK];
__device__ float g_ent;
__device__ float g_A[KK][2];
__device__ float g_P[KK];
__device__ float g_bs[BB][KK];
__device__ float g_bsp[BB][KK][2];
// W1 in mma.sync B-fragment order: [ks=8][j=16][lane=32] x uint4(bh0,bh1,bl0,bl1)
__device__ __align__(16) uint4 g_W1frag[8 * 16 * 32];

// swizzled byte offset inside a 128x128 bf16 tile, row-major 256B rows,
// 16B chunks XORed with (row & 7)
__host__ __device__ __forceinline__ uint32_t sw_off(int row, int chunk) {
    return (uint32_t)(row * 256 + ((chunk ^ (row & 7)) << 4));
}

// ---------------- PTX helpers ----------------
__device__ __forceinline__ uint32_t smem_u32(const void* p) {
    uint32_t a;
    asm("{ .reg .u64 t; cvta.to.shared.u64 t, %1; cvt.u32.u64 %0, t; }" : "=r"(a) : "l"(p));
    return a;
}
__device__ __forceinline__ void ldmx4(uint32_t* r, uint32_t addr) {
    asm volatile("ldmatrix.sync.aligned.m8n8.x4.shared.b16 {%0,%1,%2,%3}, [%4];"
                 : "=r"(r[0]), "=r"(r[1]), "=r"(r[2]), "=r"(r[3]) : "r"(addr));
}
__device__ __forceinline__ void ldmx2(uint32_t* r, uint32_t addr) {
    asm volatile("ldmatrix.sync.aligned.m8n8.x2.shared.b16 {%0,%1}, [%2];"
                 : "=r"(r[0]), "=r"(r[1]) : "r"(addr));
}
__device__ __forceinline__ void ldmx2t(uint32_t* r, uint32_t addr) {
    asm volatile("ldmatrix.sync.aligned.m8n8.x2.trans.shared.b16 {%0,%1}, [%2];"
                 : "=r"(r[0]), "=r"(r[1]) : "r"(addr));
}
__device__ __forceinline__ void mma_bf16(float* d, const uint32_t* a, const uint32_t* b) {
    asm volatile("mma.sync.aligned.m16n8k16.row.col.f32.bf16.bf16.f32 "
                 "{%0,%1,%2,%3}, {%4,%5,%6,%7}, {%8,%9}, {%0,%1,%2,%3};"
                 : "+f"(d[0]), "+f"(d[1]), "+f"(d[2]), "+f"(d[3])
                 : "r"(a[0]), "r"(a[1]), "r"(a[2]), "r"(a[3]), "r"(b[0]), "r"(b[1]));
}
__device__ __forceinline__ void red_add_v2(float* addr, float a, float b) {
    asm volatile("red.global.add.v2.f32 [%0], {%1, %2};"
                 :: "l"(addr), "f"(a), "f"(b) : "memory");
}

__device__ __forceinline__ uint32_t pack_bf16_hi(float a, float b) {
    __nv_bfloat16 ha = __float2bfloat16(a), hb = __float2bfloat16(b);
    return ((uint32_t)__bfloat16_as_ushort(hb) << 16) | __bfloat16_as_ushort(ha);
}
__device__ __forceinline__ uint32_t pack_bf16_lo(float a, float b) {
    __nv_bfloat16 ha = __float2bfloat16(a), hb = __float2bfloat16(b);
    __nv_bfloat16 la = __float2bfloat16(a - __bfloat162float(ha));
    __nv_bfloat16 lb = __float2bfloat16(b - __bfloat162float(hb));
    return ((uint32_t)__bfloat16_as_ushort(lb) << 16) | __bfloat16_as_ushort(la);
}

// ---------------- init: zero accum + out_pool, build W1 fragment array ----------------
__global__ void init_kernel(float* __restrict__ out_pool, const float* __restrict__ W1) {
    int i = blockIdx.x * blockDim.x + threadIdx.x;
    if (i < BB * KK * CC) out_pool[i] = 0.0f;
    if (i < KK) {
        g_sum_s[i] = 0.f; g_P[i] = 0.f;
        g_A[i][0] = 0.f; g_A[i][1] = 0.f;
    }
    if (i == 0) g_ent = 0.f;
    if (i < BB * KK)     ((float*)g_bs)[i] = 0.f;
    if (i < BB * KK * 2) ((float*)g_bsp)[i] = 0.f;

    if (i < 8 * 16 * 32) {
        const int ks = i >> 9;
        const int j  = (i >> 5) & 15;
        const int t  = i & 31;
        const int n  = j * 8 + (t >> 2);
        const int k0 = ks * 16 + (t & 3) * 2;
        const float f00 = W1[(size_t)(k0 + 0) * CC + n];
        const float f01 = W1[(size_t)(k0 + 1) * CC + n];
        const float f10 = W1[(size_t)(k0 + 8) * CC + n];
        const float f11 = W1[(size_t)(k0 + 9) * CC + n];
        uint4 w;
        w.x = pack_bf16_hi(f00, f01);
        w.y = pack_bf16_hi(f10, f11);
        w.z = pack_bf16_lo(f00, f01);
        w.w = pack_bf16_lo(f10, f11);
        g_W1frag[i] = w;
    }
}

// ---------------- fused kernel ----------------
__global__ __launch_bounds__(NTHREADS, 2)
void fused_kernel(const float* __restrict__ x,
                  const float* __restrict__ pos,
                  const int*   __restrict__ batch,
                  const float* __restrict__ gumbel,
                  const float* __restrict__ b1,
                  const float* __restrict__ W2,
                  const float* __restrict__ b2,
                  const float* __restrict__ scaling,
                  const float* __restrict__ active,
                  float* __restrict__ out_pool,
                  float* __restrict__ out_s)
{
    extern __shared__ __align__(16) char smem[];
    const uint32_t sb = smem_u32(smem);
    const int tid = threadIdx.x;
    const int tx  = tid & 31;
    const int wp  = tid >> 5;
    const int n0  = blockIdx.x * MT;
    const int nvalid = min(MT, NN - n0);

    float* Ls  = (float*)(smem + OFF_LS);
    float* gum = (float*)(smem + OFF_GUM);
    float* Ps  = (float*)(smem + OFF_PS);
    int*   Bsm = (int*)(smem + OFF_BSM);
    float* b1s = (float*)(smem + OFF_B1);
    float* b2s = (float*)(smem + OFF_B2);
    float* acts= (float*)(smem + OFF_ACT);
    float* scs = (float*)(smem + OFF_SC);

    // ---- x tile: fp32 -> bf16 hi/lo into swizzled smem ([m][k]) ----
    {
        const float4* xg = (const float4*)(x + (size_t)n0 * CC);
        for (int i = tid; i < MT * CC / 8; i += NTHREADS) {   // 2048 groups of 8 elems
            const int row   = i >> 4;
            const int chunk = i & 15;
            float4 v0, v1;
            if (row < nvalid) {
                v0 = xg[(size_t)row * 32 + chunk * 2];
                v1 = xg[(size_t)row * 32 + chunk * 2 + 1];
            } else {
                v0 = v1 = make_float4(0.f, 0.f, 0.f, 0.f);
            }
            uint4 hi, lo;
            hi.x = pack_bf16_hi(v0.x, v0.y); hi.y = pack_bf16_hi(v0.z, v0.w);
            hi.z = pack_bf16_hi(v1.x, v1.y); hi.w = pack_bf16_hi(v1.z, v1.w);
            lo.x = pack_bf16_lo(v0.x, v0.y); lo.y = pack_bf16_lo(v0.z, v0.w);
            lo.z = pack_bf16_lo(v1.x, v1.y); lo.w = pack_bf16_lo(v1.z, v1.w);
            const uint32_t off = sw_off(row, chunk);
            *(uint4*)(smem + OFF_XHI + off) = hi;
            *(uint4*)(smem + OFF_XLO + off) = lo;
        }
    }

    // ---- gumbel tile -> smem (coalesced) ----
    {
        const float4* gg = (const float4*)(gumbel + (size_t)n0 * KK);
        const int valid4 = nvalid * (KK / 4);
        for (int i = tid; i < MT * KK / 4; i += NTHREADS)
            ((float4*)gum)[i] = (i < valid4) ? gg[i] : make_float4(0.f, 0.f, 0.f, 0.f);
    }

    // ---- W2^T bf16 hi/lo tile [16][128], 272B row stride ----
    for (int i = tid; i < CC * KK; i += NTHREADS) {
        const int c = i >> 4, k = i & 15;
        const float v = W2[i];
        __nv_bfloat16 h = __float2bfloat16(v);
        __nv_bfloat16 l = __float2bfloat16(v - __bfloat162float(h));
        *(__nv_bfloat16*)(smem + OFF_W2TH + k * TSTR + c * 2) = h;
        *(__nv_bfloat16*)(smem + OFF_W2TL + k * TSTR + c * 2) = l;
    }

    // ---- small tiles ----
    if (tid < CC) b1s[tid] = b1[tid];
    if (tid < KK) { b2s[tid] = b2[tid]; acts[tid] = active[tid]; }
    if (tid == 0) scs[0] = scaling[0];
    for (int i = tid; i < MT; i += NTHREADS) {
        if (i < nvalid) {
            Ps[2*i]   = pos[(size_t)(n0 + i) * 2];
            Ps[2*i+1] = pos[(size_t)(n0 + i) * 2 + 1];
            Bsm[i]    = batch[n0 + i];
        } else {
            Ps[2*i] = 0.f; Ps[2*i+1] = 0.f; Bsm[i] = -1;
        }
    }
    __syncthreads();

    // ---- stage A: H = x@W1, 3-pass folded; W1 B-frags via LDG ----
    float fa[16][4];
    #pragma unroll
    for (int j = 0; j < 16; j++) { fa[j][0]=0.f; fa[j][1]=0.f; fa[j][2]=0.f; fa[j][3]=0.f; }
    {
        const int ar = wp * 16 + (tx & 7) + (tx & 8);
        const uint32_t sxh = sb + OFF_XHI, sxl = sb + OFF_XLO;
        const uint4* wf = g_W1frag + tx;
        #pragma unroll
        for (int ks = 0; ks < 8; ks++) {
            const int ac = ks * 2 + (tx >> 4);
            const uint32_t a_off = sw_off(ar, ac);
            uint32_t ahi[4], alo[4];
            ldmx4(ahi, sxh + a_off);
            ldmx4(alo, sxl + a_off);
            #pragma unroll
            for (int j = 0; j < 16; j++) {
                const uint4 w = __ldg(wf + (ks * 16 + j) * 32);
                uint32_t bh[2], bl[2];
                bh[0] = w.x; bh[1] = w.y; bl[0] = w.z; bl[1] = w.w;
                mma_bf16(fa[j], ahi, bh);
                mma_bf16(fa[j], alo, bh);
                mma_bf16(fa[j], ahi, bl);
            }
        }
    }

    // ---- relu(H + b1) in registers ----
    const int q2 = (tx & 3) * 2;
    #pragma unroll
    for (int j = 0; j < 16; j++) {
        const float bc0 = b1s[j*8 + q2], bc1 = b1s[j*8 + q2 + 1];
        fa[j][0] = fmaxf(fa[j][0] + bc0, 0.f);
        fa[j][1] = fmaxf(fa[j][1] + bc1, 0.f);
        fa[j][2] = fmaxf(fa[j][2] + bc0, 0.f);
        fa[j][3] = fmaxf(fa[j][3] + bc1, 0.f);
    }

    // ---- stage B as MMA: logits = H @ W2, 3-pass (A from accum regs) ----
    float lg0[4] = {0.f,0.f,0.f,0.f}, lg1[4] = {0.f,0.f,0.f,0.f};
    {
        const int br = tx & 7;
        const int bsel = (tx >> 3) & 1;
        const uint32_t w2th = sb + OFF_W2TH, w2tl = sb + OFF_W2TL;
        #pragma unroll
        for (int ks = 0; ks < 8; ks++) {
            uint32_t ah[4], al[4];
            ah[0] = pack_bf16_hi(fa[2*ks][0],   fa[2*ks][1]);
            ah[1] = pack_bf16_hi(fa[2*ks][2],   fa[2*ks][3]);
            ah[2] = pack_bf16_hi(fa[2*ks+1][0], fa[2*ks+1][1]);
            ah[3] = pack_bf16_hi(fa[2*ks+1][2], fa[2*ks+1][3]);
            al[0] = pack_bf16_lo(fa[2*ks][0],   fa[2*ks][1]);
            al[1] = pack_bf16_lo(fa[2*ks][2],   fa[2*ks][3]);
            al[2] = pack_bf16_lo(fa[2*ks+1][0], fa[2*ks+1][1]);
            al[3] = pack_bf16_lo(fa[2*ks+1][2], fa[2*ks+1][3]);
            const uint32_t coff = (uint32_t)(ks * 2 + bsel) * 16;
            uint32_t bh[2], bl[2];
            ldmx2(bh, w2th + br * TSTR + coff);
            ldmx2(bl, w2tl + br * TSTR + coff);
            mma_bf16(lg0, ah, bh); mma_bf16(lg0, al, bh); mma_bf16(lg0, ah, bl);
            ldmx2(bh, w2th + (8 + br) * TSTR + coff);
            ldmx2(bl, w2tl + (8 + br) * TSTR + coff);
            mma_bf16(lg1, ah, bh); mma_bf16(lg1, al, bh); mma_bf16(lg1, ah, bl);
        }
    }

    // ---- fused bias+mask+scale+gumbel+softmax in registers (quad shuffle) ----
    // thread holds rows r0 = wp*16 + (tx>>2) and r1 = r0+8,
    // cols {q2, q2+1, 8+q2, 8+q2+1}: row0 = {lg0[0],lg0[1],lg1[0],lg1[1]}, row1 = {lg0[2],...}
    {
        const int r0v = wp * 16 + (tx >> 2);
        const int r1v = r0v + 8;
        const float sc = scs[0];
        float v0[4] = {lg0[0], lg0[1], lg1[0], lg1[1]};
        float v1[4] = {lg0[2], lg0[3], lg1[2], lg1[3]};
        const int kidx[4] = {q2, q2 + 1, 8 + q2, 9 + q2};
        #pragma unroll
        for (int j = 0; j < 4; j++) {
            const int k = kidx[j];
            const float bb = b2s[k];
            const float mk = acts[k];
            const float a0 = (mk == 0.f) ? -1e9f : (v0[j] + bb) * sc;
            const float a1 = (mk == 0.f) ? -1e9f : (v1[j] + bb) * sc;
            v0[j] = a0 + gum[r0v * KK + k];
            v1[j] = a1 + gum[r1v * KK + k];
        }
        float m0 = fmaxf(fmaxf(v0[0], v0[1]), fmaxf(v0[2], v0[3]));
        float m1 = fmaxf(fmaxf(v1[0], v1[1]), fmaxf(v1[2], v1[3]));
        m0 = fmaxf(m0, __shfl_xor_sync(0xffffffffu, m0, 1));
        m0 = fmaxf(m0, __shfl_xor_sync(0xffffffffu, m0, 2));
        m1 = fmaxf(m1, __shfl_xor_sync(0xffffffffu, m1, 1));
        m1 = fmaxf(m1, __shfl_xor_sync(0xffffffffu, m1, 2));
        float s0 = 0.f, s1 = 0.f;
        #pragma unroll
        for (int j = 0; j < 4; j++) {
            v0[j] = __expf(v0[j] - m0); s0 += v0[j];
            v1[j] = __expf(v1[j] - m1); s1 += v1[j];
        }
        s0 += __shfl_xor_sync(0xffffffffu, s0, 1);
        s0 += __shfl_xor_sync(0xffffffffu, s0, 2);
        s1 += __shfl_xor_sync(0xffffffffu, s1, 1);
        s1 += __shfl_xor_sync(0xffffffffu, s1, 2);
        const float i0 = 1.f / s0, i1 = 1.f / s1;
        const bool ok0 = r0v < nvalid, ok1 = r1v < nvalid;
        #pragma unroll
        for (int j = 0; j < 4; j++) {
            v0[j] = ok0 ? v0[j] * i0 : 0.f;
            v1[j] = ok1 ? v1[j] * i1 : 0.f;
        }
        if (ok0) {
            *(float2*)(out_s + (size_t)(n0 + r0v) * KK + q2)     = make_float2(v0[0], v0[1]);
            *(float2*)(out_s + (size_t)(n0 + r0v) * KK + 8 + q2) = make_float2(v0[2], v0[3]);
        }
        if (ok1) {
            *(float2*)(out_s + (size_t)(n0 + r1v) * KK + q2)     = make_float2(v1[0], v1[1]);
            *(float2*)(out_s + (size_t)(n0 + r1v) * KK + 8 + q2) = make_float2(v1[2], v1[3]);
        }
        *(float2*)(Ls + r0v * KK + q2)     = make_float2(v0[0], v0[1]);
        *(float2*)(Ls + r0v * KK + 8 + q2) = make_float2(v0[2], v0[3]);
        *(float2*)(Ls + r1v * KK + q2)     = make_float2(v1[0], v1[1]);
        *(float2*)(Ls + r1v * KK + 8 + q2) = make_float2(v1[2], v1[3]);
        #pragma unroll
        for (int j = 0; j < 4; j++) {
            const int k = kidx[j];
            __nv_bfloat16 h0 = __float2bfloat16(v0[j]);
            __nv_bfloat16 h1 = __float2bfloat16(v1[j]);
            *(__nv_bfloat16*)(smem + OFF_STH + k * TSTR + r0v * 2) = h0;
            *(__nv_bfloat16*)(smem + OFF_STH + k * TSTR + r1v * 2) = h1;
            *(__nv_bfloat16*)(smem + OFF_STL + k * TSTR + r0v * 2) =
                __float2bfloat16(v0[j] - __bfloat162float(h0));
            *(__nv_bfloat16*)(smem + OFF_STL + k * TSTR + r1v * 2) =
                __float2bfloat16(v1[j] - __bfloat162float(h1));
        }
    }
    __syncthreads();

    // ---- stage C1: statistics ----
    const bool uniform = (nvalid == MT) && (Bsm[0] == Bsm[MT-1]);
    if (uniform) {
        const int k = tid >> 4;
        const int g = tid & 15;
        float gs = 0.f, ge = 0.f, gax = 0.f, gay = 0.f, gp = 0.f;
        #pragma unroll
        for (int j = 0; j < 8; j++) {
            const int n = g*8 + j;
            const float sv = Ls[n*KK + k];
            const float px = Ps[2*n], py = Ps[2*n+1];
            gs  += sv;
            ge  += sv * __logf(sv + EPSF);
            gax += sv * px;
            gay += sv * py;
            gp  += sv * (px*px + py*py);
        }
        #pragma unroll
        for (int off = 8; off > 0; off >>= 1) {
            gs  += __shfl_down_sync(0xffffffffu, gs,  off, 16);
            ge  += __shfl_down_sync(0xffffffffu, ge,  off, 16);
            gax += __shfl_down_sync(0xffffffffu, gax, off, 16);
            gay += __shfl_down_sync(0xffffffffu, gay, off, 16);
            gp  += __shfl_down_sync(0xffffffffu, gp,  off, 16);
        }
        if (g == 0) {
            const int b = Bsm[0];
            atomicAdd(&g_sum_s[k], gs);
            atomicAdd(&g_ent, ge);
            red_add_v2(&g_A[k][0], gax, gay);
            atomicAdd(&g_P[k], gp);
            atomicAdd(&g_bs[b][k], gs);
            red_add_v2(&g_bsp[b][k][0], gax, gay);
        }
    } else if (tid < KK) {
        const int k = tid;
        float gs = 0.f, ge = 0.f, gax = 0.f, gay = 0.f, gp = 0.f;
        int cur = Bsm[0];
        float bs = 0.f, bx = 0.f, by = 0.f;
        for (int n = 0; n < MT; n++) {
            const int bv = Bsm[n];
            if (bv < 0) break;
            if (bv != cur) {
                atomicAdd(&g_bs[cur][k], bs);
                red_add_v2(&g_bsp[cur][k][0], bx, by);
                bs = bx = by = 0.f; cur = bv;
            }
            const float sv = Ls[n*KK + k];
            const float px = Ps[2*n], py = Ps[2*n+1];
            gs  += sv;
            ge  += sv * __logf(sv + EPSF);
            gax += sv * px;
            gay += sv * py;
            gp  += sv * (px*px + py*py);
            bs  += sv; bx += sv * px; by += sv * py;
        }
        if (cur >= 0) {
            atomicAdd(&g_bs[cur][k], bs);
            red_add_v2(&g_bsp[cur][k][0], bx, by);
        }
        atomicAdd(&g_sum_s[k], gs);
        atomicAdd(&g_ent, ge);
        red_add_v2(&g_A[k][0], gax, gay);
        atomicAdd(&g_P[k], gp);
    }

    // ---- stage C2: pooled features ----
    if (uniform) {
        float p0[4] = {0.f,0.f,0.f,0.f}, p1[4] = {0.f,0.f,0.f,0.f};
        const uint32_t sth = sb + OFF_STH, stl = sb + OFF_STL;
        const uint32_t xhi = sb + OFF_XHI, xlo = sb + OFF_XLO;
        const int arow = tx & 15;
        const int asel = tx >> 4;
        #pragma unroll
        for (int ks = 0; ks < 8; ks++) {
            uint32_t sah[4], sal[4];
            const uint32_t aoff = (uint32_t)arow * TSTR + (uint32_t)(ks * 2 + asel) * 16;
            ldmx4(sah, sth + aoff);
            ldmx4(sal, stl + aoff);
            const int brow = ks * 16 + (tx & 15);
            uint32_t bh[2], bl[2];
            ldmx2t(bh, xhi + sw_off(brow, wp * 2));
            ldmx2t(bl, xlo + sw_off(brow, wp * 2));
            mma_bf16(p0, sah, bh); mma_bf16(p0, sal, bh); mma_bf16(p0, sah, bl);
            ldmx2t(bh, xhi + sw_off(brow, wp * 2 + 1));
            ldmx2t(bl, xlo + sw_off(brow, wp * 2 + 1));
            mma_bf16(p1, sah, bh); mma_bf16(p1, sal, bh); mma_bf16(p1, sah, bl);
        }
        const int b  = Bsm[0];
        const int kr = tx >> 2;
        float* base0 = out_pool + ((size_t)b * KK + kr) * CC + wp * 16;
        float* base1 = out_pool + ((size_t)b * KK + kr + 8) * CC + wp * 16;
        red_add_v2(base0 + q2,     p0[0], p0[1]);
        red_add_v2(base1 + q2,     p0[2], p0[3]);
        red_add_v2(base0 + 8 + q2, p1[0], p1[1]);
        red_add_v2(base1 + 8 + q2, p1[2], p1[3]);
    } else {
        const int k    = tx & 15;
        const int half = tx >> 4;
        const int cb4  = wp * 4 + half * 2;
        const float4* xg4 = (const float4*)(x + (size_t)n0 * CC);
        float4 A0 = make_float4(0.f,0.f,0.f,0.f);
        float4 A1 = make_float4(0.f,0.f,0.f,0.f);
        int cur = Bsm[0];
        for (int n = 0; n < MT; n++) {
            const int bv = Bsm[n];
            if (bv < 0) break;
            if (bv != cur) {
                float* base = out_pool + ((size_t)cur * KK + k) * CC + cb4 * 4;
                red_add_v2(base+0, A0.x, A0.y);
                red_add_v2(base+2, A0.z, A0.w);
                red_add_v2(base+4, A1.x, A1.y);
                red_add_v2(base+6, A1.z, A1.w);
                A0 = make_float4(0.f,0.f,0.f,0.f);
                A1 = make_float4(0.f,0.f,0.f,0.f);
                cur = bv;
            }
            const float sv = Ls[n*KK + k];
            const float4 x0 = xg4[(size_t)n * 32 + cb4];
            const float4 x1 = xg4[(size_t)n * 32 + cb4 + 1];
            A0.x += sv*x0.x; A0.y += sv*x0.y; A0.z += sv*x0.z; A0.w += sv*x0.w;
            A1.x += sv*x1.x; A1.y += sv*x1.y; A1.z += sv*x1.z; A1.w += sv*x1.w;
        }
        if (cur >= 0) {
            float* base = out_pool + ((size_t)cur * KK + k) * CC + cb4 * 4;
            red_add_v2(base+0, A0.x, A0.y);
            red_add_v2(base+2, A0.z, A0.w);
            red_add_v2(base+4, A1.x, A1.y);
            red_add_v2(base+6, A1.z, A1.w);
        }
    }
}

// -------- finalize --------
__global__ void finalize_kernel(const float* __restrict__ active,
                                float* __restrict__ mu_out,
                                float* __restrict__ losses)
{
    __shared__ float mus[BB][KK][2];
    __shared__ float red[256];
    const int tid = threadIdx.x;
    const int b = tid >> 4, k = tid & 15;

    const float denom = g_bs[b][k] + EPSF;
    const float mx = g_bsp[b][k][0] / denom;
    const float my = g_bsp[b][k][1] / denom;
    mus[b][k][0] = mx; mus[b][k][1] = my;
    mu_out[tid * 2]     = mx;
    mu_out[tid * 2 + 1] = my;
    __syncthreads();

    float rep = 0.f;
    #pragma unroll
    for (int j = 0; j < KK; j++) {
        if (j == k) continue;
        float dx = mus[b][k][0] - mus[b][j][0];
        float dy = mus[b][k][1] - mus[b][j][1];
        rep += 1.f / (dx*dx + dy*dy + 1.f);
    }
    red[tid] = rep;
    __syncthreads();
    for (int st = 128; st > 0; st >>= 1) {
        if (tid < st) red[tid] += red[tid + st];
        __syncthreads();
    }

    if (tid == 0) {
        const float sep = red[0] / ((float)(KK * (KK - 1)) + EPSF);
        const float entropy = -g_ent / (float)NN;
        float div = 0.f, prun = 0.f, spat = 0.f, spar = 0.f;
        for (int kk = 0; kk < KK; kk++) {
            const float avg = g_sum_s[kk] / (float)NN;
            div  += avg * __logf(avg + EPSF);
            const float am = active[kk];
            prun += fabsf(avg * (1.f - am));
            spar += am;
            const float S = g_sum_s[kk] + EPSF;
            const float mgx = g_A[kk][0] / S;
            const float mgy = g_A[kk][1] / S;
            spat += g_P[kk] / S - (mgx*mgx + mgy*mgy);
        }
        losses[0] = entropy;
        losses[1] = div;
        losses[2] = spat / (float)KK;
        losses[3] = prun / (float)KK;
        losses[4] = spar / (float)KK;
        losses[5] = sep;
    }
}

extern "C" void kernel_launch(void* const* d_in, const int* in_sizes, int n_in,
                              void* d_out, int out_size) {
    const float* x       = (const float*)d_in[0];
    const float* pos     = (const float*)d_in[1];
    const int*   batch   = (const int*)  d_in[2];
    const float* gumbel  = (const float*)d_in[3];
    const float* W1      = (const float*)d_in[4];
    const float* b1      = (const float*)d_in[5];
    const float* W2      = (const float*)d_in[6];
    const float* b2      = (const float*)d_in[7];
    const float* scaling = (const float*)d_in[8];
    const float* active  = (const float*)d_in[9];

    float* out = (float*)d_out;
    float* out_pool   = out;
    float* out_s      = out + (size_t)BB*KK*CC;
    float* out_mu     = out_s + (size_t)NN*KK;
    float* out_losses = out_mu + (size_t)BB*KK*2;

    cudaFuncSetAttribute(fused_kernel, cudaFuncAttributeMaxDynamicSharedMemorySize,
                         SMEM_TOTAL);

    init_kernel<<<128, 256>>>(out_pool, W1);
    fused_kernel<<<(NN + MT - 1) / MT, NTHREADS, SMEM_TOTAL>>>(
        x, pos, batch, gumbel, b1, W2, b2, scaling, active, out_pool, out_s);
    finalize_kernel<<<1, 256>>>(active, out_mu, out_losses);
}

// round 8
// speedup vs baseline: 2.8892x; 1.1115x over previous
#include <cuda_runtime.h>
#include <cuda_fp16.h>
#include <cstdint>
#include <math.h>

#define NN 100000
#define CC 128
#define KK 16
#define BB 16
#define MT 128          // nodes per block
#define NTHREADS 256
#define EPSF 1e-9f
#define TSTR 272        // padded row stride (bytes) for sT / W2T 16-row tiles

// ---------------- dynamic shared-memory layout (bytes) ----------------
#define OFF_XH    0        // x_hi  fp16 [128][128], 16B-chunk XOR swizzle (32768)
#define OFF_XL    32768    // x_lo  fp16
#define OFF_W2TH  65536    // W2^T [16][128] fp16 hi, 272B row stride (4352)
#define OFF_W2TL  69888    // W2^T fp16 lo
#define OFF_STH   74240    // s^T  [16][128] fp16 hi (4352)
#define OFF_STL   78592    // s^T  fp16 lo
#define OFF_LS    82944    // s fp32 [128][16]           (8192)
#define OFF_GUM   91136    // gumbel fp32 [128][16]      (8192)
#define OFF_PS    99328    // pos [128][2]               (1024)
#define OFF_BSM   100352   // batch [128] int            (512)
#define OFF_B1    100864   // b1 [128]                   (512)
#define OFF_B2    101376   // 64
#define OFF_ACT   101440   // 64
#define OFF_SC    101504   // 16
#define SMEM_TOTAL 101520

// -------- device scratch --------
__device__ float g_sum_s[KK];
__device__ float g_ent;
__device__ float g_A[KK][2];
__device__ float g_P[KK];
__device__ float g_bs[BB][KK];
__device__ float g_bsp[BB][KK][2];
// W1 (fp16, single precision level) in mma.sync B-fragment order:
// [ks=8][j=16][lane=32] x uint2(bh0, bh1)
__device__ __align__(16) uint2 g_W1frag[8 * 16 * 32];

// swizzled byte offset inside a 128x128 fp16 tile, row-major 256B rows,
// 16B chunks XORed with (row & 7)
__host__ __device__ __forceinline__ uint32_t sw_off(int row, int chunk) {
    return (uint32_t)(row * 256 + ((chunk ^ (row & 7)) << 4));
}

// ---------------- PTX helpers ----------------
__device__ __forceinline__ uint32_t smem_u32(const void* p) {
    uint32_t a;
    asm("{ .reg .u64 t; cvta.to.shared.u64 t, %1; cvt.u32.u64 %0, t; }" : "=r"(a) : "l"(p));
    return a;
}
__device__ __forceinline__ void ldmx4(uint32_t* r, uint32_t addr) {
    asm volatile("ldmatrix.sync.aligned.m8n8.x4.shared.b16 {%0,%1,%2,%3}, [%4];"
                 : "=r"(r[0]), "=r"(r[1]), "=r"(r[2]), "=r"(r[3]) : "r"(addr));
}
__device__ __forceinline__ void ldmx2(uint32_t* r, uint32_t addr) {
    asm volatile("ldmatrix.sync.aligned.m8n8.x2.shared.b16 {%0,%1}, [%2];"
                 : "=r"(r[0]), "=r"(r[1]) : "r"(addr));
}
__device__ __forceinline__ void ldmx2t(uint32_t* r, uint32_t addr) {
    asm volatile("ldmatrix.sync.aligned.m8n8.x2.trans.shared.b16 {%0,%1}, [%2];"
                 : "=r"(r[0]), "=r"(r[1]) : "r"(addr));
}
__device__ __forceinline__ void mma_f16(float* d, const uint32_t* a, const uint32_t* b) {
    asm volatile("mma.sync.aligned.m16n8k16.row.col.f32.f16.f16.f32 "
                 "{%0,%1,%2,%3}, {%4,%5,%6,%7}, {%8,%9}, {%0,%1,%2,%3};"
                 : "+f"(d[0]), "+f"(d[1]), "+f"(d[2]), "+f"(d[3])
                 : "r"(a[0]), "r"(a[1]), "r"(a[2]), "r"(a[3]), "r"(b[0]), "r"(b[1]));
}
__device__ __forceinline__ void red_add_v2(float* addr, float a, float b) {
    asm volatile("red.global.add.v2.f32 [%0], {%1, %2};"
                 :: "l"(addr), "f"(a), "f"(b) : "memory");
}

__device__ __forceinline__ uint32_t pack_f16(float a, float b) {
    __half ha = __float2half_rn(a), hb = __float2half_rn(b);
    return ((uint32_t)__half_as_ushort(hb) << 16) | __half_as_ushort(ha);
}
__device__ __forceinline__ uint32_t pack_f16_lo(float a, float b) {
    __half ha = __float2half_rn(a), hb = __float2half_rn(b);
    __half la = __float2half_rn(a - __half2float(ha));
    __half lb = __float2half_rn(b - __half2float(hb));
    return ((uint32_t)__half_as_ushort(lb) << 16) | __half_as_ushort(la);
}

// ---------------- init: zero accum + out_pool, build W1 fragment array ----------------
__global__ void init_kernel(float* __restrict__ out_pool, const float* __restrict__ W1) {
    int i = blockIdx.x * blockDim.x + threadIdx.x;
    if (i < BB * KK * CC) out_pool[i] = 0.0f;
    if (i < KK) {
        g_sum_s[i] = 0.f; g_P[i] = 0.f;
        g_A[i][0] = 0.f; g_A[i][1] = 0.f;
    }
    if (i == 0) g_ent = 0.f;
    if (i < BB * KK)     ((float*)g_bs)[i] = 0.f;
    if (i < BB * KK * 2) ((float*)g_bsp)[i] = 0.f;

    if (i < 8 * 16 * 32) {
        const int ks = i >> 9;
        const int j  = (i >> 5) & 15;
        const int t  = i & 31;
        const int n  = j * 8 + (t >> 2);
        const int k0 = ks * 16 + (t & 3) * 2;
        uint2 w;
        w.x = pack_f16(W1[(size_t)(k0 + 0) * CC + n], W1[(size_t)(k0 + 1) * CC + n]);
        w.y = pack_f16(W1[(size_t)(k0 + 8) * CC + n], W1[(size_t)(k0 + 9) * CC + n]);
        g_W1frag[i] = w;
    }
}

// ---------------- fused kernel ----------------
__global__ __launch_bounds__(NTHREADS, 2)
void fused_kernel(const float* __restrict__ x,
                  const float* __restrict__ pos,
                  const int*   __restrict__ batch,
                  const float* __restrict__ gumbel,
                  const float* __restrict__ b1,
                  const float* __restrict__ W2,
                  const float* __restrict__ b2,
                  const float* __restrict__ scaling,
                  const float* __restrict__ active,
                  float* __restrict__ out_pool,
                  float* __restrict__ out_s)
{
    extern __shared__ __align__(16) char smem[];
    const uint32_t sb = smem_u32(smem);
    const int tid = threadIdx.x;
    const int tx  = tid & 31;
    const int wp  = tid >> 5;
    const int n0  = blockIdx.x * MT;
    const int nvalid = min(MT, NN - n0);

    float* Ls  = (float*)(smem + OFF_LS);
    float* gum = (float*)(smem + OFF_GUM);
    float* Ps  = (float*)(smem + OFF_PS);
    int*   Bsm = (int*)(smem + OFF_BSM);
    float* b1s = (float*)(smem + OFF_B1);
    float* b2s = (float*)(smem + OFF_B2);
    float* acts= (float*)(smem + OFF_ACT);
    float* scs = (float*)(smem + OFF_SC);

    // ---- x tile: fp32 -> fp16 hi/lo into swizzled smem ([m][k]) ----
    {
        const float4* xg = (const float4*)(x + (size_t)n0 * CC);
        for (int i = tid; i < MT * CC / 8; i += NTHREADS) {   // 2048 groups of 8 elems
            const int row   = i >> 4;
            const int chunk = i & 15;
            float4 v0, v1;
            if (row < nvalid) {
                v0 = xg[(size_t)row * 32 + chunk * 2];
                v1 = xg[(size_t)row * 32 + chunk * 2 + 1];
            } else {
                v0 = v1 = make_float4(0.f, 0.f, 0.f, 0.f);
            }
            uint4 hi, lo;
            hi.x = pack_f16(v0.x, v0.y);    hi.y = pack_f16(v0.z, v0.w);
            hi.z = pack_f16(v1.x, v1.y);    hi.w = pack_f16(v1.z, v1.w);
            lo.x = pack_f16_lo(v0.x, v0.y); lo.y = pack_f16_lo(v0.z, v0.w);
            lo.z = pack_f16_lo(v1.x, v1.y); lo.w = pack_f16_lo(v1.z, v1.w);
            const uint32_t off = sw_off(row, chunk);
            *(uint4*)(smem + OFF_XH + off) = hi;
            *(uint4*)(smem + OFF_XL + off) = lo;
        }
    }

    // ---- gumbel tile -> smem (coalesced) ----
    {
        const float4* gg = (const float4*)(gumbel + (size_t)n0 * KK);
        const int valid4 = nvalid * (KK / 4);
        for (int i = tid; i < MT * KK / 4; i += NTHREADS)
            ((float4*)gum)[i] = (i < valid4) ? gg[i] : make_float4(0.f, 0.f, 0.f, 0.f);
    }

    // ---- W2^T fp16 hi/lo tile [16][128], 272B row stride ----
    for (int i = tid; i < CC * KK; i += NTHREADS) {
        const int c = i >> 4, k = i & 15;
        const float v = W2[i];
        __half h = __float2half_rn(v);
        __half l = __float2half_rn(v - __half2float(h));
        *(__half*)(smem + OFF_W2TH + k * TSTR + c * 2) = h;
        *(__half*)(smem + OFF_W2TL + k * TSTR + c * 2) = l;
    }

    // ---- small tiles ----
    if (tid < CC) b1s[tid] = b1[tid];
    if (tid < KK) { b2s[tid] = b2[tid]; acts[tid] = active[tid]; }
    if (tid == 0) scs[0] = scaling[0];
    for (int i = tid; i < MT; i += NTHREADS) {
        if (i < nvalid) {
            Ps[2*i]   = pos[(size_t)(n0 + i) * 2];
            Ps[2*i+1] = pos[(size_t)(n0 + i) * 2 + 1];
            Bsm[i]    = batch[n0 + i];
        } else {
            Ps[2*i] = 0.f; Ps[2*i+1] = 0.f; Bsm[i] = -1;
        }
    }
    __syncthreads();

    // ---- stage A: H = x@W1, 2-pass fp16 (x_hi + x_lo) * W1_h; W1 frags via LDG ----
    float fa[16][4];
    #pragma unroll
    for (int j = 0; j < 16; j++) { fa[j][0]=0.f; fa[j][1]=0.f; fa[j][2]=0.f; fa[j][3]=0.f; }
    {
        const int ar = wp * 16 + (tx & 7) + (tx & 8);
        const uint32_t sxh = sb + OFF_XH, sxl = sb + OFF_XL;
        const uint2* wf = g_W1frag + tx;
        #pragma unroll
        for (int ks = 0; ks < 8; ks++) {
            const int ac = ks * 2 + (tx >> 4);
            const uint32_t a_off = sw_off(ar, ac);
            uint32_t ahi[4], alo[4];
            ldmx4(ahi, sxh + a_off);
            ldmx4(alo, sxl + a_off);
            #pragma unroll
            for (int j = 0; j < 16; j++) {
                const uint2 w = __ldg(wf + (ks * 16 + j) * 32);
                uint32_t bh[2];
                bh[0] = w.x; bh[1] = w.y;
                mma_f16(fa[j], ahi, bh);
                mma_f16(fa[j], alo, bh);
            }
        }
    }

    // ---- relu(H + b1) in registers ----
    const int q2 = (tx & 3) * 2;
    #pragma unroll
    for (int j = 0; j < 16; j++) {
        const float bc0 = b1s[j*8 + q2], bc1 = b1s[j*8 + q2 + 1];
        fa[j][0] = fmaxf(fa[j][0] + bc0, 0.f);
        fa[j][1] = fmaxf(fa[j][1] + bc1, 0.f);
        fa[j][2] = fmaxf(fa[j][2] + bc0, 0.f);
        fa[j][3] = fmaxf(fa[j][3] + bc1, 0.f);
    }

    // ---- stage B as MMA: logits = H @ W2, 3-pass fp16 (A from accum regs) ----
    float lg0[4] = {0.f,0.f,0.f,0.f}, lg1[4] = {0.f,0.f,0.f,0.f};
    {
        const int br = tx & 7;
        const int bsel = (tx >> 3) & 1;
        const uint32_t w2th = sb + OFF_W2TH, w2tl = sb + OFF_W2TL;
        #pragma unroll
        for (int ks = 0; ks < 8; ks++) {
            uint32_t ah[4], al[4];
            ah[0] = pack_f16(fa[2*ks][0],   fa[2*ks][1]);
            ah[1] = pack_f16(fa[2*ks][2],   fa[2*ks][3]);
            ah[2] = pack_f16(fa[2*ks+1][0], fa[2*ks+1][1]);
            ah[3] = pack_f16(fa[2*ks+1][2], fa[2*ks+1][3]);
            al[0] = pack_f16_lo(fa[2*ks][0],   fa[2*ks][1]);
            al[1] = pack_f16_lo(fa[2*ks][2],   fa[2*ks][3]);
            al[2] = pack_f16_lo(fa[2*ks+1][0], fa[2*ks+1][1]);
            al[3] = pack_f16_lo(fa[2*ks+1][2], fa[2*ks+1][3]);
            const uint32_t coff = (uint32_t)(ks * 2 + bsel) * 16;
            uint32_t bh[2], bl[2];
            ldmx2(bh, w2th + br * TSTR + coff);
            ldmx2(bl, w2tl + br * TSTR + coff);
            mma_f16(lg0, ah, bh); mma_f16(lg0, al, bh); mma_f16(lg0, ah, bl);
            ldmx2(bh, w2th + (8 + br) * TSTR + coff);
            ldmx2(bl, w2tl + (8 + br) * TSTR + coff);
            mma_f16(lg1, ah, bh); mma_f16(lg1, al, bh); mma_f16(lg1, ah, bl);
        }
    }

    // ---- fused bias+mask+scale+gumbel+softmax in registers (quad shuffle) ----
    {
        const int r0v = wp * 16 + (tx >> 2);
        const int r1v = r0v + 8;
        const float sc = scs[0];
        float v0[4] = {lg0[0], lg0[1], lg1[0], lg1[1]};
        float v1[4] = {lg0[2], lg0[3], lg1[2], lg1[3]};
        const int kidx[4] = {q2, q2 + 1, 8 + q2, 9 + q2};
        #pragma unroll
        for (int j = 0; j < 4; j++) {
            const int k = kidx[j];
            const float bb = b2s[k];
            const float mk = acts[k];
            const float a0 = (mk == 0.f) ? -1e9f : (v0[j] + bb) * sc;
            const float a1 = (mk == 0.f) ? -1e9f : (v1[j] + bb) * sc;
            v0[j] = a0 + gum[r0v * KK + k];
            v1[j] = a1 + gum[r1v * KK + k];
        }
        float m0 = fmaxf(fmaxf(v0[0], v0[1]), fmaxf(v0[2], v0[3]));
        float m1 = fmaxf(fmaxf(v1[0], v1[1]), fmaxf(v1[2], v1[3]));
        m0 = fmaxf(m0, __shfl_xor_sync(0xffffffffu, m0, 1));
        m0 = fmaxf(m0, __shfl_xor_sync(0xffffffffu, m0, 2));
        m1 = fmaxf(m1, __shfl_xor_sync(0xffffffffu, m1, 1));
        m1 = fmaxf(m1, __shfl_xor_sync(0xffffffffu, m1, 2));
        float s0 = 0.f, s1 = 0.f;
        #pragma unroll
        for (int j = 0; j < 4; j++) {
            v0[j] = __expf(v0[j] - m0); s0 += v0[j];
            v1[j] = __expf(v1[j] - m1); s1 += v1[j];
        }
        s0 += __shfl_xor_sync(0xffffffffu, s0, 1);
        s0 += __shfl_xor_sync(0xffffffffu, s0, 2);
        s1 += __shfl_xor_sync(0xffffffffu, s1, 1);
        s1 += __shfl_xor_sync(0xffffffffu, s1, 2);
        const float i0 = 1.f / s0, i1 = 1.f / s1;
        const bool ok0 = r0v < nvalid, ok1 = r1v < nvalid;
        #pragma unroll
        for (int j = 0; j < 4; j++) {
            v0[j] = ok0 ? v0[j] * i0 : 0.f;
            v1[j] = ok1 ? v1[j] * i1 : 0.f;
        }
        if (ok0) {
            *(float2*)(out_s + (size_t)(n0 + r0v) * KK + q2)     = make_float2(v0[0], v0[1]);
            *(float2*)(out_s + (size_t)(n0 + r0v) * KK + 8 + q2) = make_float2(v0[2], v0[3]);
        }
        if (ok1) {
            *(float2*)(out_s + (size_t)(n0 + r1v) * KK + q2)     = make_float2(v1[0], v1[1]);
            *(float2*)(out_s + (size_t)(n0 + r1v) * KK + 8 + q2) = make_float2(v1[2], v1[3]);
        }
        *(float2*)(Ls + r0v * KK + q2)     = make_float2(v0[0], v0[1]);
        *(float2*)(Ls + r0v * KK + 8 + q2) = make_float2(v0[2], v0[3]);
        *(float2*)(Ls + r1v * KK + q2)     = make_float2(v1[0], v1[1]);
        *(float2*)(Ls + r1v * KK + 8 + q2) = make_float2(v1[2], v1[3]);
        #pragma unroll
        for (int j = 0; j < 4; j++) {
            const int k = kidx[j];
            __half h0 = __float2half_rn(v0[j]);
            __half h1 = __float2half_rn(v1[j]);
            *(__half*)(smem + OFF_STH + k * TSTR + r0v * 2) = h0;
            *(__half*)(smem + OFF_STH + k * TSTR + r1v * 2) = h1;
            *(__half*)(smem + OFF_STL + k * TSTR + r0v * 2) =
                __float2half_rn(v0[j] - __half2float(h0));
            *(__half*)(smem + OFF_STL + k * TSTR + r1v * 2) =
                __float2half_rn(v1[j] - __half2float(h1));
        }
    }
    __syncthreads();

    // ---- stage C1: statistics ----
    const bool uniform = (nvalid == MT) && (Bsm[0] == Bsm[MT-1]);
    if (uniform) {
        const int k = tid >> 4;
        const int g = tid & 15;
        float gs = 0.f, ge = 0.f, gax = 0.f, gay = 0.f, gp = 0.f;
        #pragma unroll
        for (int j = 0; j < 8; j++) {
            const int n = g*8 + j;
            const float sv = Ls[n*KK + k];
            const float px = Ps[2*n], py = Ps[2*n+1];
            gs  += sv;
            ge  += sv * __logf(sv + EPSF);
            gax += sv * px;
            gay += sv * py;
            gp  += sv * (px*px + py*py);
        }
        #pragma unroll
        for (int off = 8; off > 0; off >>= 1) {
            gs  += __shfl_down_sync(0xffffffffu, gs,  off, 16);
            ge  += __shfl_down_sync(0xffffffffu, ge,  off, 16);
            gax += __shfl_down_sync(0xffffffffu, gax, off, 16);
            gay += __shfl_down_sync(0xffffffffu, gay, off, 16);
            gp  += __shfl_down_sync(0xffffffffu, gp,  off, 16);
        }
        if (g == 0) {
            const int b = Bsm[0];
            atomicAdd(&g_sum_s[k], gs);
            atomicAdd(&g_ent, ge);
            red_add_v2(&g_A[k][0], gax, gay);
            atomicAdd(&g_P[k], gp);
            atomicAdd(&g_bs[b][k], gs);
            red_add_v2(&g_bsp[b][k][0], gax, gay);
        }
    } else if (tid < KK) {
        const int k = tid;
        float gs = 0.f, ge = 0.f, gax = 0.f, gay = 0.f, gp = 0.f;
        int cur = Bsm[0];
        float bs = 0.f, bx = 0.f, by = 0.f;
        for (int n = 0; n < MT; n++) {
            const int bv = Bsm[n];
            if (bv < 0) break;
            if (bv != cur) {
                atomicAdd(&g_bs[cur][k], bs);
                red_add_v2(&g_bsp[cur][k][0], bx, by);
                bs = bx = by = 0.f; cur = bv;
            }
            const float sv = Ls[n*KK + k];
            const float px = Ps[2*n], py = Ps[2*n+1];
            gs  += sv;
            ge  += sv * __logf(sv + EPSF);
            gax += sv * px;
            gay += sv * py;
            gp  += sv * (px*px + py*py);
            bs  += sv; bx += sv * px; by += sv * py;
        }
        if (cur >= 0) {
            atomicAdd(&g_bs[cur][k], bs);
            red_add_v2(&g_bsp[cur][k][0], bx, by);
        }
        atomicAdd(&g_sum_s[k], gs);
        atomicAdd(&g_ent, ge);
        red_add_v2(&g_A[k][0], gax, gay);
        atomicAdd(&g_P[k], gp);
    }

    // ---- stage C2: pooled features ----
    if (uniform) {
        // out[b] += s^T @ x via MMA, 2-pass fp16: (s_hi + s_lo) * x_h
        float p0[4] = {0.f,0.f,0.f,0.f}, p1[4] = {0.f,0.f,0.f,0.f};
        const uint32_t sth = sb + OFF_STH, stl = sb + OFF_STL;
        const uint32_t xh = sb + OFF_XH;
        const int arow = tx & 15;
        const int asel = tx >> 4;
        #pragma unroll
        for (int ks = 0; ks < 8; ks++) {
            uint32_t sah[4], sal[4];
            const uint32_t aoff = (uint32_t)arow * TSTR + (uint32_t)(ks * 2 + asel) * 16;
            ldmx4(sah, sth + aoff);
            ldmx4(sal, stl + aoff);
            const int brow = ks * 16 + (tx & 15);
            uint32_t bh[2];
            ldmx2t(bh, xh + sw_off(brow, wp * 2));
            mma_f16(p0, sah, bh); mma_f16(p0, sal, bh);
            ldmx2t(bh, xh + sw_off(brow, wp * 2 + 1));
            mma_f16(p1, sah, bh); mma_f16(p1, sal, bh);
        }
        const int b  = Bsm[0];
        const int kr = tx >> 2;
        float* base0 = out_pool + ((size_t)b * KK + kr) * CC + wp * 16;
        float* base1 = out_pool + ((size_t)b * KK + kr + 8) * CC + wp * 16;
        red_add_v2(base0 + q2,     p0[0], p0[1]);
        red_add_v2(base1 + q2,     p0[2], p0[3]);
        red_add_v2(base0 + 8 + q2, p1[0], p1[1]);
        red_add_v2(base1 + 8 + q2, p1[2], p1[3]);
    } else {
        const int k    = tx & 15;
        const int half = tx >> 4;
        const int cb4  = wp * 4 + half * 2;
        const float4* xg4 = (const float4*)(x + (size_t)n0 * CC);
        float4 A0 = make_float4(0.f,0.f,0.f,0.f);
        float4 A1 = make_float4(0.f,0.f,0.f,0.f);
        int cur = Bsm[0];
        for (int n = 0; n < MT; n++) {
            const int bv = Bsm[n];
            if (bv < 0) break;
            if (bv != cur) {
                float* base = out_pool + ((size_t)cur * KK + k) * CC + cb4 * 4;
                red_add_v2(base+0, A0.x, A0.y);
                red_add_v2(base+2, A0.z, A0.w);
                red_add_v2(base+4, A1.x, A1.y);
                red_add_v2(base+6, A1.z, A1.w);
                A0 = make_float4(0.f,0.f,0.f,0.f);
                A1 = make_float4(0.f,0.f,0.f,0.f);
                cur = bv;
            }
            const float sv = Ls[n*KK + k];
            const float4 x0 = xg4[(size_t)n * 32 + cb4];
            const float4 x1 = xg4[(size_t)n * 32 + cb4 + 1];
            A0.x += sv*x0.x; A0.y += sv*x0.y; A0.z += sv*x0.z; A0.w += sv*x0.w;
            A1.x += sv*x1.x; A1.y += sv*x1.y; A1.z += sv*x1.z; A1.w += sv*x1.w;
        }
        if (cur >= 0) {
            float* base = out_pool + ((size_t)cur * KK + k) * CC + cb4 * 4;
            red_add_v2(base+0, A0.x, A0.y);
            red_add_v2(base+2, A0.z, A0.w);
            red_add_v2(base+4, A1.x, A1.y);
            red_add_v2(base+6, A1.z, A1.w);
        }
    }
}

// -------- finalize --------
__global__ void finalize_kernel(const float* __restrict__ active,
                                float* __restrict__ mu_out,
                                float* __restrict__ losses)
{
    __shared__ float mus[BB][KK][2];
    __shared__ float red[256];
    const int tid = threadIdx.x;
    const int b = tid >> 4, k = tid & 15;

    const float denom = g_bs[b][k] + EPSF;
    const float mx = g_bsp[b][k][0] / denom;
    const float my = g_bsp[b][k][1] / denom;
    mus[b][k][0] = mx; mus[b][k][1] = my;
    mu_out[tid * 2]     = mx;
    mu_out[tid * 2 + 1] = my;
    __syncthreads();

    float rep = 0.f;
    #pragma unroll
    for (int j = 0; j < KK; j++) {
        if (j == k) continue;
        float dx = mus[b][k][0] - mus[b][j][0];
        float dy = mus[b][k][1] - mus[b][j][1];
        rep += 1.f / (dx*dx + dy*dy + 1.f);
    }
    red[tid] = rep;
    __syncthreads();
    for (int st = 128; st > 0; st >>= 1) {
        if (tid < st) red[tid] += red[tid + st];
        __syncthreads();
    }

    if (tid == 0) {
        const float sep = red[0] / ((float)(KK * (KK - 1)) + EPSF);
        const float entropy = -g_ent / (float)NN;
        float div = 0.f, prun = 0.f, spat = 0.f, spar = 0.f;
        for (int kk = 0; kk < KK; kk++) {
            const float avg = g_sum_s[kk] / (float)NN;
            div  += avg * __logf(avg + EPSF);
            const float am = active[kk];
            prun += fabsf(avg * (1.f - am));
            spar += am;
            const float S = g_sum_s[kk] + EPSF;
            const float mgx = g_A[kk][0] / S;
            const float mgy = g_A[kk][1] / S;
            spat += g_P[kk] / S - (mgx*mgx + mgy*mgy);
        }
        losses[0] = entropy;
        losses[1] = div;
        losses[2] = spat / (float)KK;
        losses[3] = prun / (float)KK;
        losses[4] = spar / (float)KK;
        losses[5] = sep;
    }
}

extern "C" void kernel_launch(void* const* d_in, const int* in_sizes, int n_in,
                              void* d_out, int out_size) {
    const float* x       = (const float*)d_in[0];
    const float* pos     = (const float*)d_in[1];
    const int*   batch   = (const int*)  d_in[2];
    const float* gumbel  = (const float*)d_in[3];
    const float* W1      = (const float*)d_in[4];
    const float* b1      = (const float*)d_in[5];
    const float* W2      = (const float*)d_in[6];
    const float* b2      = (const float*)d_in[7];
    const float* scaling = (const float*)d_in[8];
    const float* active  = (const float*)d_in[9];

    float* out = (float*)d_out;
    float* out_pool   = out;
    float* out_s      = out + (size_t)BB*KK*CC;
    float* out_mu     = out_s + (size_t)NN*KK;
    float* out_losses = out_mu + (size_t)BB*KK*2;

    cudaFuncSetAttribute(fused_kernel, cudaFuncAttributeMaxDynamicSharedMemorySize,
                         SMEM_TOTAL);

    init_kernel<<<128, 256>>>(out_pool, W1);
    fused_kernel<<<(NN + MT - 1) / MT, NTHREADS, SMEM_TOTAL>>>(
        x, pos, batch, gumbel, b1, W2, b2, scaling, active, out_pool, out_s);
    finalize_kernel<<<1, 256>>>(active, out_mu, out_losses);
}

// round 9
// speedup vs baseline: 3.2902x; 1.1388x over previous
#include <cuda_runtime.h>
#include <cuda_fp16.h>
#include <cstdint>
#include <math.h>

#define NN 100000
#define CC 128
#define KK 16
#define BB 16
#define MT 128          // nodes per block
#define NTHREADS 256
#define EPSF 1e-9f
#define TSTR 272        // padded row stride (bytes) for sT / W2T 16-row tiles

// ---------------- dynamic shared-memory layout (bytes) ----------------
#define OFF_XH    0        // x_hi fp16 [128][128], 16B-chunk XOR swizzle (32768)
#define OFF_W2TH  32768    // W2^T [16][128] fp16 hi, 272B row stride (4352)
#define OFF_STH   37120    // s^T  [16][128] fp16 hi (4352)
#define OFF_STL   41472    // s^T  fp16 lo (4352)
#define OFF_LS    45824    // s fp32 [128][16]           (8192)
#define OFF_GUM   54016    // gumbel fp32 [128][16]      (8192)
#define OFF_PS    62208    // pos [128][2]               (1024)
#define OFF_BSM   63232    // batch [128] int            (512)
#define OFF_B1    63744    // b1 [128]                   (512)
#define OFF_B2    64256    // 64
#define OFF_ACT   64320    // 64
#define OFF_SC    64384    // 16
#define SMEM_TOTAL 64400

// -------- device scratch --------
__device__ float g_sum_s[KK];
__device__ float g_ent;
__device__ float g_A[KK][2];
__device__ float g_P[KK];
__device__ float g_bs[BB][KK];
__device__ float g_bsp[BB][KK][2];
// W1 (fp16) in mma.sync B-fragment order: [ks=8][j=16][lane=32] x uint2(bh0, bh1)
__device__ __align__(16) uint2 g_W1frag[8 * 16 * 32];

// swizzled byte offset inside a 128x128 fp16 tile, row-major 256B rows,
// 16B chunks XORed with (row & 7)
__host__ __device__ __forceinline__ uint32_t sw_off(int row, int chunk) {
    return (uint32_t)(row * 256 + ((chunk ^ (row & 7)) << 4));
}

// ---------------- PTX helpers ----------------
__device__ __forceinline__ uint32_t smem_u32(const void* p) {
    uint32_t a;
    asm("{ .reg .u64 t; cvta.to.shared.u64 t, %1; cvt.u32.u64 %0, t; }" : "=r"(a) : "l"(p));
    return a;
}
__device__ __forceinline__ void ldmx4(uint32_t* r, uint32_t addr) {
    asm volatile("ldmatrix.sync.aligned.m8n8.x4.shared.b16 {%0,%1,%2,%3}, [%4];"
                 : "=r"(r[0]), "=r"(r[1]), "=r"(r[2]), "=r"(r[3]) : "r"(addr));
}
__device__ __forceinline__ void ldmx2(uint32_t* r, uint32_t addr) {
    asm volatile("ldmatrix.sync.aligned.m8n8.x2.shared.b16 {%0,%1}, [%2];"
                 : "=r"(r[0]), "=r"(r[1]) : "r"(addr));
}
__device__ __forceinline__ void ldmx2t(uint32_t* r, uint32_t addr) {
    asm volatile("ldmatrix.sync.aligned.m8n8.x2.trans.shared.b16 {%0,%1}, [%2];"
                 : "=r"(r[0]), "=r"(r[1]) : "r"(addr));
}
__device__ __forceinline__ void mma_f16(float* d, const uint32_t* a, const uint32_t* b) {
    asm volatile("mma.sync.aligned.m16n8k16.row.col.f32.f16.f16.f32 "
                 "{%0,%1,%2,%3}, {%4,%5,%6,%7}, {%8,%9}, {%0,%1,%2,%3};"
                 : "+f"(d[0]), "+f"(d[1]), "+f"(d[2]), "+f"(d[3])
                 : "r"(a[0]), "r"(a[1]), "r"(a[2]), "r"(a[3]), "r"(b[0]), "r"(b[1]));
}
__device__ __forceinline__ void red_add_v2(float* addr, float a, float b) {
    asm volatile("red.global.add.v2.f32 [%0], {%1, %2};"
                 :: "l"(addr), "f"(a), "f"(b) : "memory");
}

__device__ __forceinline__ uint32_t pack_f16(float a, float b) {
    __half ha = __float2half_rn(a), hb = __float2half_rn(b);
    return ((uint32_t)__half_as_ushort(hb) << 16) | __half_as_ushort(ha);
}
__device__ __forceinline__ uint32_t pack_f16_lo(float a, float b) {
    __half ha = __float2half_rn(a), hb = __float2half_rn(b);
    __half la = __float2half_rn(a - __half2float(ha));
    __half lb = __float2half_rn(b - __half2float(hb));
    return ((uint32_t)__half_as_ushort(lb) << 16) | __half_as_ushort(la);
}

// ---------------- init: zero accum + out_pool, build W1 fragment array ----------------
__global__ void init_kernel(float* __restrict__ out_pool, const float* __restrict__ W1) {
    int i = blockIdx.x * blockDim.x + threadIdx.x;
    if (i < BB * KK * CC) out_pool[i] = 0.0f;
    if (i < KK) {
        g_sum_s[i] = 0.f; g_P[i] = 0.f;
        g_A[i][0] = 0.f; g_A[i][1] = 0.f;
    }
    if (i == 0) g_ent = 0.f;
    if (i < BB * KK)     ((float*)g_bs)[i] = 0.f;
    if (i < BB * KK * 2) ((float*)g_bsp)[i] = 0.f;

    if (i < 8 * 16 * 32) {
        const int ks = i >> 9;
        const int j  = (i >> 5) & 15;
        const int t  = i & 31;
        const int n  = j * 8 + (t >> 2);
        const int k0 = ks * 16 + (t & 3) * 2;
        uint2 w;
        w.x = pack_f16(W1[(size_t)(k0 + 0) * CC + n], W1[(size_t)(k0 + 1) * CC + n]);
        w.y = pack_f16(W1[(size_t)(k0 + 8) * CC + n], W1[(size_t)(k0 + 9) * CC + n]);
        g_W1frag[i] = w;
    }
}

// ---------------- fused kernel ----------------
__global__ __launch_bounds__(NTHREADS, 2)
void fused_kernel(const float* __restrict__ x,
                  const float* __restrict__ pos,
                  const int*   __restrict__ batch,
                  const float* __restrict__ gumbel,
                  const float* __restrict__ b1,
                  const float* __restrict__ W2,
                  const float* __restrict__ b2,
                  const float* __restrict__ scaling,
                  const float* __restrict__ active,
                  float* __restrict__ out_pool,
                  float* __restrict__ out_s)
{
    extern __shared__ __align__(16) char smem[];
    const uint32_t sb = smem_u32(smem);
    const int tid = threadIdx.x;
    const int tx  = tid & 31;
    const int wp  = tid >> 5;
    const int n0  = blockIdx.x * MT;
    const int nvalid = min(MT, NN - n0);

    float* Ls  = (float*)(smem + OFF_LS);
    float* gum = (float*)(smem + OFF_GUM);
    float* Ps  = (float*)(smem + OFF_PS);
    int*   Bsm = (int*)(smem + OFF_BSM);
    float* b1s = (float*)(smem + OFF_B1);
    float* b2s = (float*)(smem + OFF_B2);
    float* acts= (float*)(smem + OFF_ACT);
    float* scs = (float*)(smem + OFF_SC);

    // ---- x tile: fp32 -> fp16 (hi only) into swizzled smem ([m][k]) ----
    {
        const float4* xg = (const float4*)(x + (size_t)n0 * CC);
        for (int i = tid; i < MT * CC / 8; i += NTHREADS) {   // 2048 groups of 8 elems
            const int row   = i >> 4;
            const int chunk = i & 15;
            float4 v0, v1;
            if (row < nvalid) {
                v0 = xg[(size_t)row * 32 + chunk * 2];
                v1 = xg[(size_t)row * 32 + chunk * 2 + 1];
            } else {
                v0 = v1 = make_float4(0.f, 0.f, 0.f, 0.f);
            }
            uint4 hi;
            hi.x = pack_f16(v0.x, v0.y); hi.y = pack_f16(v0.z, v0.w);
            hi.z = pack_f16(v1.x, v1.y); hi.w = pack_f16(v1.z, v1.w);
            *(uint4*)(smem + OFF_XH + sw_off(row, chunk)) = hi;
        }
    }

    // ---- gumbel tile -> smem (coalesced) ----
    {
        const float4* gg = (const float4*)(gumbel + (size_t)n0 * KK);
        const int valid4 = nvalid * (KK / 4);
        for (int i = tid; i < MT * KK / 4; i += NTHREADS)
            ((float4*)gum)[i] = (i < valid4) ? gg[i] : make_float4(0.f, 0.f, 0.f, 0.f);
    }

    // ---- W2^T fp16 (hi only) tile [16][128], 272B row stride ----
    for (int i = tid; i < CC * KK; i += NTHREADS) {
        const int c = i >> 4, k = i & 15;
        *(__half*)(smem + OFF_W2TH + k * TSTR + c * 2) = __float2half_rn(W2[i]);
    }

    // ---- small tiles ----
    if (tid < CC) b1s[tid] = b1[tid];
    if (tid < KK) { b2s[tid] = b2[tid]; acts[tid] = active[tid]; }
    if (tid == 0) scs[0] = scaling[0];
    for (int i = tid; i < MT; i += NTHREADS) {
        if (i < nvalid) {
            Ps[2*i]   = pos[(size_t)(n0 + i) * 2];
            Ps[2*i+1] = pos[(size_t)(n0 + i) * 2 + 1];
            Bsm[i]    = batch[n0 + i];
        } else {
            Ps[2*i] = 0.f; Ps[2*i+1] = 0.f; Bsm[i] = -1;
        }
    }
    __syncthreads();

    // ---- stage A: H = x_h @ W1_h, single-pass fp16; W1 frags via LDG ----
    float fa[16][4];
    #pragma unroll
    for (int j = 0; j < 16; j++) { fa[j][0]=0.f; fa[j][1]=0.f; fa[j][2]=0.f; fa[j][3]=0.f; }
    {
        const int ar = wp * 16 + (tx & 7) + (tx & 8);
        const uint32_t sxh = sb + OFF_XH;
        const uint2* wf = g_W1frag + tx;
        #pragma unroll
        for (int ks = 0; ks < 8; ks++) {
            const int ac = ks * 2 + (tx >> 4);
            uint32_t ahi[4];
            ldmx4(ahi, sxh + sw_off(ar, ac));
            #pragma unroll
            for (int j = 0; j < 16; j++) {
                const uint2 w = __ldg(wf + (ks * 16 + j) * 32);
                uint32_t bh[2];
                bh[0] = w.x; bh[1] = w.y;
                mma_f16(fa[j], ahi, bh);
            }
        }
    }

    // ---- relu(H + b1) in registers ----
    const int q2 = (tx & 3) * 2;
    #pragma unroll
    for (int j = 0; j < 16; j++) {
        const float bc0 = b1s[j*8 + q2], bc1 = b1s[j*8 + q2 + 1];
        fa[j][0] = fmaxf(fa[j][0] + bc0, 0.f);
        fa[j][1] = fmaxf(fa[j][1] + bc1, 0.f);
        fa[j][2] = fmaxf(fa[j][2] + bc0, 0.f);
        fa[j][3] = fmaxf(fa[j][3] + bc1, 0.f);
    }

    // ---- stage B as MMA: logits = H @ W2_h, 2-pass fp16 (H hi+lo from regs) ----
    float lg0[4] = {0.f,0.f,0.f,0.f}, lg1[4] = {0.f,0.f,0.f,0.f};
    {
        const int br = tx & 7;
        const int bsel = (tx >> 3) & 1;
        const uint32_t w2th = sb + OFF_W2TH;
        #pragma unroll
        for (int ks = 0; ks < 8; ks++) {
            uint32_t ah[4], al[4];
            ah[0] = pack_f16(fa[2*ks][0],   fa[2*ks][1]);
            ah[1] = pack_f16(fa[2*ks][2],   fa[2*ks][3]);
            ah[2] = pack_f16(fa[2*ks+1][0], fa[2*ks+1][1]);
            ah[3] = pack_f16(fa[2*ks+1][2], fa[2*ks+1][3]);
            al[0] = pack_f16_lo(fa[2*ks][0],   fa[2*ks][1]);
            al[1] = pack_f16_lo(fa[2*ks][2],   fa[2*ks][3]);
            al[2] = pack_f16_lo(fa[2*ks+1][0], fa[2*ks+1][1]);
            al[3] = pack_f16_lo(fa[2*ks+1][2], fa[2*ks+1][3]);
            const uint32_t coff = (uint32_t)(ks * 2 + bsel) * 16;
            uint32_t bh[2];
            ldmx2(bh, w2th + br * TSTR + coff);
            mma_f16(lg0, ah, bh); mma_f16(lg0, al, bh);
            ldmx2(bh, w2th + (8 + br) * TSTR + coff);
            mma_f16(lg1, ah, bh); mma_f16(lg1, al, bh);
        }
    }

    // ---- fused bias+mask+scale+gumbel+softmax in registers (quad shuffle) ----
    {
        const int r0v = wp * 16 + (tx >> 2);
        const int r1v = r0v + 8;
        const float sc = scs[0];
        float v0[4] = {lg0[0], lg0[1], lg1[0], lg1[1]};
        float v1[4] = {lg0[2], lg0[3], lg1[2], lg1[3]};
        const int kidx[4] = {q2, q2 + 1, 8 + q2, 9 + q2};
        #pragma unroll
        for (int j = 0; j < 4; j++) {
            const int k = kidx[j];
            const float bb = b2s[k];
            const float mk = acts[k];
            const float a0 = (mk == 0.f) ? -1e9f : (v0[j] + bb) * sc;
            const float a1 = (mk == 0.f) ? -1e9f : (v1[j] + bb) * sc;
            v0[j] = a0 + gum[r0v * KK + k];
            v1[j] = a1 + gum[r1v * KK + k];
        }
        float m0 = fmaxf(fmaxf(v0[0], v0[1]), fmaxf(v0[2], v0[3]));
        float m1 = fmaxf(fmaxf(v1[0], v1[1]), fmaxf(v1[2], v1[3]));
        m0 = fmaxf(m0, __shfl_xor_sync(0xffffffffu, m0, 1));
        m0 = fmaxf(m0, __shfl_xor_sync(0xffffffffu, m0, 2));
        m1 = fmaxf(m1, __shfl_xor_sync(0xffffffffu, m1, 1));
        m1 = fmaxf(m1, __shfl_xor_sync(0xffffffffu, m1, 2));
        float s0 = 0.f, s1 = 0.f;
        #pragma unroll
        for (int j = 0; j < 4; j++) {
            v0[j] = __expf(v0[j] - m0); s0 += v0[j];
            v1[j] = __expf(v1[j] - m1); s1 += v1[j];
        }
        s0 += __shfl_xor_sync(0xffffffffu, s0, 1);
        s0 += __shfl_xor_sync(0xffffffffu, s0, 2);
        s1 += __shfl_xor_sync(0xffffffffu, s1, 1);
        s1 += __shfl_xor_sync(0xffffffffu, s1, 2);
        const float i0 = 1.f / s0, i1 = 1.f / s1;
        const bool ok0 = r0v < nvalid, ok1 = r1v < nvalid;
        #pragma unroll
        for (int j = 0; j < 4; j++) {
            v0[j] = ok0 ? v0[j] * i0 : 0.f;
            v1[j] = ok1 ? v1[j] * i1 : 0.f;
        }
        if (ok0) {
            *(float2*)(out_s + (size_t)(n0 + r0v) * KK + q2)     = make_float2(v0[0], v0[1]);
            *(float2*)(out_s + (size_t)(n0 + r0v) * KK + 8 + q2) = make_float2(v0[2], v0[3]);
        }
        if (ok1) {
            *(float2*)(out_s + (size_t)(n0 + r1v) * KK + q2)     = make_float2(v1[0], v1[1]);
            *(float2*)(out_s + (size_t)(n0 + r1v) * KK + 8 + q2) = make_float2(v1[2], v1[3]);
        }
        *(float2*)(Ls + r0v * KK + q2)     = make_float2(v0[0], v0[1]);
        *(float2*)(Ls + r0v * KK + 8 + q2) = make_float2(v0[2], v0[3]);
        *(float2*)(Ls + r1v * KK + q2)     = make_float2(v1[0], v1[1]);
        *(float2*)(Ls + r1v * KK + 8 + q2) = make_float2(v1[2], v1[3]);
        #pragma unroll
        for (int j = 0; j < 4; j++) {
            const int k = kidx[j];
            __half h0 = __float2half_rn(v0[j]);
            __half h1 = __float2half_rn(v1[j]);
            *(__half*)(smem + OFF_STH + k * TSTR + r0v * 2) = h0;
            *(__half*)(smem + OFF_STH + k * TSTR + r1v * 2) = h1;
            *(__half*)(smem + OFF_STL + k * TSTR + r0v * 2) =
                __float2half_rn(v0[j] - __half2float(h0));
            *(__half*)(smem + OFF_STL + k * TSTR + r1v * 2) =
                __float2half_rn(v1[j] - __half2float(h1));
        }
    }
    __syncthreads();

    // ---- stage C1: statistics ----
    const bool uniform = (nvalid == MT) && (Bsm[0] == Bsm[MT-1]);
    if (uniform) {
        const int k = tid >> 4;
        const int g = tid & 15;
        float gs = 0.f, ge = 0.f, gax = 0.f, gay = 0.f, gp = 0.f;
        #pragma unroll
        for (int j = 0; j < 8; j++) {
            const int n = g*8 + j;
            const float sv = Ls[n*KK + k];
            const float px = Ps[2*n], py = Ps[2*n+1];
            gs  += sv;
            ge  += sv * __logf(sv + EPSF);
            gax += sv * px;
            gay += sv * py;
            gp  += sv * (px*px + py*py);
        }
        #pragma unroll
        for (int off = 8; off > 0; off >>= 1) {
            gs  += __shfl_down_sync(0xffffffffu, gs,  off, 16);
            ge  += __shfl_down_sync(0xffffffffu, ge,  off, 16);
            gax += __shfl_down_sync(0xffffffffu, gax, off, 16);
            gay += __shfl_down_sync(0xffffffffu, gay, off, 16);
            gp  += __shfl_down_sync(0xffffffffu, gp,  off, 16);
        }
        if (g == 0) {
            const int b = Bsm[0];
            atomicAdd(&g_sum_s[k], gs);
            atomicAdd(&g_ent, ge);
            red_add_v2(&g_A[k][0], gax, gay);
            atomicAdd(&g_P[k], gp);
            atomicAdd(&g_bs[b][k], gs);
            red_add_v2(&g_bsp[b][k][0], gax, gay);
        }
    } else if (tid < KK) {
        const int k = tid;
        float gs = 0.f, ge = 0.f, gax = 0.f, gay = 0.f, gp = 0.f;
        int cur = Bsm[0];
        float bs = 0.f, bx = 0.f, by = 0.f;
        for (int n = 0; n < MT; n++) {
            const int bv = Bsm[n];
            if (bv < 0) break;
            if (bv != cur) {
                atomicAdd(&g_bs[cur][k], bs);
                red_add_v2(&g_bsp[cur][k][0], bx, by);
                bs = bx = by = 0.f; cur = bv;
            }
            const float sv = Ls[n*KK + k];
            const float px = Ps[2*n], py = Ps[2*n+1];
            gs  += sv;
            ge  += sv * __logf(sv + EPSF);
            gax += sv * px;
            gay += sv * py;
            gp  += sv * (px*px + py*py);
            bs  += sv; bx += sv * px; by += sv * py;
        }
        if (cur >= 0) {
            atomicAdd(&g_bs[cur][k], bs);
            red_add_v2(&g_bsp[cur][k][0], bx, by);
        }
        atomicAdd(&g_sum_s[k], gs);
        atomicAdd(&g_ent, ge);
        red_add_v2(&g_A[k][0], gax, gay);
        atomicAdd(&g_P[k], gp);
    }

    // ---- stage C2: pooled features ----
    if (uniform) {
        // out[b] += s^T @ x via MMA, 2-pass fp16: (s_hi + s_lo) * x_h
        float p0[4] = {0.f,0.f,0.f,0.f}, p1[4] = {0.f,0.f,0.f,0.f};
        const uint32_t sth = sb + OFF_STH, stl = sb + OFF_STL;
        const uint32_t xh = sb + OFF_XH;
        const int arow = tx & 15;
        const int asel = tx >> 4;
        #pragma unroll
        for (int ks = 0; ks < 8; ks++) {
            uint32_t sah[4], sal[4];
            const uint32_t aoff = (uint32_t)arow * TSTR + (uint32_t)(ks * 2 + asel) * 16;
            ldmx4(sah, sth + aoff);
            ldmx4(sal, stl + aoff);
            const int brow = ks * 16 + (tx & 15);
            uint32_t bh[2];
            ldmx2t(bh, xh + sw_off(brow, wp * 2));
            mma_f16(p0, sah, bh); mma_f16(p0, sal, bh);
            ldmx2t(bh, xh + sw_off(brow, wp * 2 + 1));
            mma_f16(p1, sah, bh); mma_f16(p1, sal, bh);
        }
        const int b  = Bsm[0];
        const int kr = tx >> 2;
        float* base0 = out_pool + ((size_t)b * KK + kr) * CC + wp * 16;
        float* base1 = out_pool + ((size_t)b * KK + kr + 8) * CC + wp * 16;
        red_add_v2(base0 + q2,     p0[0], p0[1]);
        red_add_v2(base1 + q2,     p0[2], p0[3]);
        red_add_v2(base0 + 8 + q2, p1[0], p1[1]);
        red_add_v2(base1 + 8 + q2, p1[2], p1[3]);
    } else {
        const int k    = tx & 15;
        const int half = tx >> 4;
        const int cb4  = wp * 4 + half * 2;
        const float4* xg4 = (const float4*)(x + (size_t)n0 * CC);
        float4 A0 = make_float4(0.f,0.f,0.f,0.f);
        float4 A1 = make_float4(0.f,0.f,0.f,0.f);
        int cur = Bsm[0];
        for (int n = 0; n < MT; n++) {
            const int bv = Bsm[n];
            if (bv < 0) break;
            if (bv != cur) {
                float* base = out_pool + ((size_t)cur * KK + k) * CC + cb4 * 4;
                red_add_v2(base+0, A0.x, A0.y);
                red_add_v2(base+2, A0.z, A0.w);
                red_add_v2(base+4, A1.x, A1.y);
                red_add_v2(base+6, A1.z, A1.w);
                A0 = make_float4(0.f,0.f,0.f,0.f);
                A1 = make_float4(0.f,0.f,0.f,0.f);
                cur = bv;
            }
            const float sv = Ls[n*KK + k];
            const float4 x0 = xg4[(size_t)n * 32 + cb4];
            const float4 x1 = xg4[(size_t)n * 32 + cb4 + 1];
            A0.x += sv*x0.x; A0.y += sv*x0.y; A0.z += sv*x0.z; A0.w += sv*x0.w;
            A1.x += sv*x1.x; A1.y += sv*x1.y; A1.z += sv*x1.z; A1.w += sv*x1.w;
        }
        if (cur >= 0) {
            float* base = out_pool + ((size_t)cur * KK + k) * CC + cb4 * 4;
            red_add_v2(base+0, A0.x, A0.y);
            red_add_v2(base+2, A0.z, A0.w);
            red_add_v2(base+4, A1.x, A1.y);
            red_add_v2(base+6, A1.z, A1.w);
        }
    }
}

// -------- finalize --------
__global__ void finalize_kernel(const float* __restrict__ active,
                                float* __restrict__ mu_out,
                                float* __restrict__ losses)
{
    __shared__ float mus[BB][KK][2];
    __shared__ float red[256];
    const int tid = threadIdx.x;
    const int b = tid >> 4, k = tid & 15;

    const float denom = g_bs[b][k] + EPSF;
    const float mx = g_bsp[b][k][0] / denom;
    const float my = g_bsp[b][k][1] / denom;
    mus[b][k][0] = mx; mus[b][k][1] = my;
    mu_out[tid * 2]     = mx;
    mu_out[tid * 2 + 1] = my;
    __syncthreads();

    float rep = 0.f;
    #pragma unroll
    for (int j = 0; j < KK; j++) {
        if (j == k) continue;
        float dx = mus[b][k][0] - mus[b][j][0];
        float dy = mus[b][k][1] - mus[b][j][1];
        rep += 1.f / (dx*dx + dy*dy + 1.f);
    }
    red[tid] = rep;
    __syncthreads();
    for (int st = 128; st > 0; st >>= 1) {
        if (tid < st) red[tid] += red[tid + st];
        __syncthreads();
    }

    if (tid == 0) {
        const float sep = red[0] / ((float)(KK * (KK - 1)) + EPSF);
        const float entropy = -g_ent / (float)NN;
        float div = 0.f, prun = 0.f, spat = 0.f, spar = 0.f;
        for (int kk = 0; kk < KK; kk++) {
            const float avg = g_sum_s[kk] / (float)NN;
            div  += avg * __logf(avg + EPSF);
            const float am = active[kk];
            prun += fabsf(avg * (1.f - am));
            spar += am;
            const float S = g_sum_s[kk] + EPSF;
            const float mgx = g_A[kk][0] / S;
            const float mgy = g_A[kk][1] / S;
            spat += g_P[kk] / S - (mgx*mgx + mgy*mgy);
        }
        losses[0] = entropy;
        losses[1] = div;
        losses[2] = spat / (float)KK;
        losses[3] = prun / (float)KK;
        losses[4] = spar / (float)KK;
        losses[5] = sep;
    }
}

extern "C" void kernel_launch(void* const* d_in, const int* in_sizes, int n_in,
                              void* d_out, int out_size) {
    const float* x       = (const float*)d_in[0];
    const float* pos     = (const float*)d_in[1];
    const int*   batch   = (const int*)  d_in[2];
    const float* gumbel  = (const float*)d_in[3];
    const float* W1      = (const float*)d_in[4];
    const float* b1      = (const float*)d_in[5];
    const float* W2      = (const float*)d_in[6];
    const float* b2      = (const float*)d_in[7];
    const float* scaling = (const float*)d_in[8];
    const float* active  = (const float*)d_in[9];

    float* out = (float*)d_out;
    float* out_pool   = out;
    float* out_s      = out + (size_t)BB*KK*CC;
    float* out_mu     = out_s + (size_t)NN*KK;
    float* out_losses = out_mu + (size_t)BB*KK*2;

    cudaFuncSetAttribute(fused_kernel, cudaFuncAttributeMaxDynamicSharedMemorySize,
                         SMEM_TOTAL);

    init_kernel<<<128, 256>>>(out_pool, W1);
    fused_kernel<<<(NN + MT - 1) / MT, NTHREADS, SMEM_TOTAL>>>(
        x, pos, batch, gumbel, b1, W2, b2, scaling, active, out_pool, out_s);
    finalize_kernel<<<1, 256>>>(active, out_mu, out_losses);
}

// round 10
// speedup vs baseline: 3.4201x; 1.0395x over previous
#include <cuda_runtime.h>
#include <cuda_fp16.h>
#include <cstdint>
#include <math.h>

#define NN 100000
#define CC 128
#define KK 16
#define BB 16
#define MT 128          // nodes per block
#define NTHREADS 256
#define EPSF 1e-9f
#define TSTR 272        // padded row stride (bytes) for sT / W2T 16-row tiles

// ---------------- dynamic shared-memory layout (bytes) ----------------
#define OFF_XH    0        // x_hi fp16 [128][128], 16B-chunk XOR swizzle (32768)
#define OFF_W2TH  32768    // W2^T [16][128] fp16, 272B row stride (4352)
#define OFF_STH   37120    // s^T  [16][128] fp16 (4352)
#define OFF_LS    41472    // s fp32 [128][16]           (8192)
#define OFF_GUM   49664    // gumbel fp32 [128][16]      (8192)
#define OFF_PS    57856    // pos [128][2]               (1024)
#define OFF_BSM   58880    // batch [128] int            (512)
#define OFF_B1    59392    // b1 [128]                   (512)
#define OFF_B2    59904    // 64
#define OFF_ACT   59968    // 64
#define OFF_SC    60032    // 16
#define SMEM_TOTAL 60048

// -------- device scratch --------
__device__ float g_sum_s[KK];
__device__ float g_ent;
__device__ float g_A[KK][2];
__device__ float g_P[KK];
__device__ float g_bs[BB][KK];
__device__ float g_bsp[BB][KK][2];
// W1 (fp16) in mma.sync B-fragment order: [ks=8][j=16][lane=32] x uint2(bh0, bh1)
__device__ __align__(16) uint2 g_W1frag[8 * 16 * 32];

// swizzled byte offset inside a 128x128 fp16 tile, row-major 256B rows,
// 16B chunks XORed with (row & 7)
__host__ __device__ __forceinline__ uint32_t sw_off(int row, int chunk) {
    return (uint32_t)(row * 256 + ((chunk ^ (row & 7)) << 4));
}

// ---------------- PTX helpers ----------------
__device__ __forceinline__ uint32_t smem_u32(const void* p) {
    uint32_t a;
    asm("{ .reg .u64 t; cvta.to.shared.u64 t, %1; cvt.u32.u64 %0, t; }" : "=r"(a) : "l"(p));
    return a;
}
__device__ __forceinline__ void ldmx4(uint32_t* r, uint32_t addr) {
    asm volatile("ldmatrix.sync.aligned.m8n8.x4.shared.b16 {%0,%1,%2,%3}, [%4];"
                 : "=r"(r[0]), "=r"(r[1]), "=r"(r[2]), "=r"(r[3]) : "r"(addr));
}
__device__ __forceinline__ void ldmx2(uint32_t* r, uint32_t addr) {
    asm volatile("ldmatrix.sync.aligned.m8n8.x2.shared.b16 {%0,%1}, [%2];"
                 : "=r"(r[0]), "=r"(r[1]) : "r"(addr));
}
__device__ __forceinline__ void ldmx2t(uint32_t* r, uint32_t addr) {
    asm volatile("ldmatrix.sync.aligned.m8n8.x2.trans.shared.b16 {%0,%1}, [%2];"
                 : "=r"(r[0]), "=r"(r[1]) : "r"(addr));
}
__device__ __forceinline__ void mma_f16(float* d, const uint32_t* a, const uint32_t* b) {
    asm volatile("mma.sync.aligned.m16n8k16.row.col.f32.f16.f16.f32 "
                 "{%0,%1,%2,%3}, {%4,%5,%6,%7}, {%8,%9}, {%0,%1,%2,%3};"
                 : "+f"(d[0]), "+f"(d[1]), "+f"(d[2]), "+f"(d[3])
                 : "r"(a[0]), "r"(a[1]), "r"(a[2]), "r"(a[3]), "r"(b[0]), "r"(b[1]));
}
__device__ __forceinline__ void red_add_v2(float* addr, float a, float b) {
    asm volatile("red.global.add.v2.f32 [%0], {%1, %2};"
                 :: "l"(addr), "f"(a), "f"(b) : "memory");
}

// single-instruction pack: result = (f16(b) << 16) | f16(a)
// (cvt.rn.f16x2.f32 packs FIRST source into the UPPER half)
__device__ __forceinline__ uint32_t pack_f16(float a, float b) {
    uint32_t u;
    asm("cvt.rn.f16x2.f32 %0, %1, %2;" : "=r"(u) : "f"(b), "f"(a));
    return u;
}

// ---------------- init: zero accum + out_pool, build W1 fragment array ----------------
__global__ void init_kernel(float* __restrict__ out_pool, const float* __restrict__ W1) {
    int i = blockIdx.x * blockDim.x + threadIdx.x;
    if (i < BB * KK * CC) out_pool[i] = 0.0f;
    if (i < KK) {
        g_sum_s[i] = 0.f; g_P[i] = 0.f;
        g_A[i][0] = 0.f; g_A[i][1] = 0.f;
    }
    if (i == 0) g_ent = 0.f;
    if (i < BB * KK)     ((float*)g_bs)[i] = 0.f;
    if (i < BB * KK * 2) ((float*)g_bsp)[i] = 0.f;

    if (i < 8 * 16 * 32) {
        const int ks = i >> 9;
        const int j  = (i >> 5) & 15;
        const int t  = i & 31;
        const int n  = j * 8 + (t >> 2);
        const int k0 = ks * 16 + (t & 3) * 2;
        uint2 w;
        w.x = pack_f16(W1[(size_t)(k0 + 0) * CC + n], W1[(size_t)(k0 + 1) * CC + n]);
        w.y = pack_f16(W1[(size_t)(k0 + 8) * CC + n], W1[(size_t)(k0 + 9) * CC + n]);
        g_W1frag[i] = w;
    }
}

// ---------------- fused kernel ----------------
__global__ __launch_bounds__(NTHREADS, 2)
void fused_kernel(const float* __restrict__ x,
                  const float* __restrict__ pos,
                  const int*   __restrict__ batch,
                  const float* __restrict__ gumbel,
                  const float* __restrict__ b1,
                  const float* __restrict__ W2,
                  const float* __restrict__ b2,
                  const float* __restrict__ scaling,
                  const float* __restrict__ active,
                  float* __restrict__ out_pool,
                  float* __restrict__ out_s)
{
    extern __shared__ __align__(16) char smem[];
    const uint32_t sb = smem_u32(smem);
    const int tid = threadIdx.x;
    const int tx  = tid & 31;
    const int wp  = tid >> 5;
    const int n0  = blockIdx.x * MT;
    const int nvalid = min(MT, NN - n0);

    float* Ls  = (float*)(smem + OFF_LS);
    float* gum = (float*)(smem + OFF_GUM);
    float* Ps  = (float*)(smem + OFF_PS);
    int*   Bsm = (int*)(smem + OFF_BSM);
    float* b1s = (float*)(smem + OFF_B1);
    float* b2s = (float*)(smem + OFF_B2);
    float* acts= (float*)(smem + OFF_ACT);
    float* scs = (float*)(smem + OFF_SC);

    // ---- x tile: fp32 -> fp16 into swizzled smem ([m][k]) ----
    {
        const float4* xg = (const float4*)(x + (size_t)n0 * CC);
        for (int i = tid; i < MT * CC / 8; i += NTHREADS) {   // 2048 groups of 8 elems
            const int row   = i >> 4;
            const int chunk = i & 15;
            float4 v0, v1;
            if (row < nvalid) {
                v0 = xg[(size_t)row * 32 + chunk * 2];
                v1 = xg[(size_t)row * 32 + chunk * 2 + 1];
            } else {
                v0 = v1 = make_float4(0.f, 0.f, 0.f, 0.f);
            }
            uint4 hi;
            hi.x = pack_f16(v0.x, v0.y); hi.y = pack_f16(v0.z, v0.w);
            hi.z = pack_f16(v1.x, v1.y); hi.w = pack_f16(v1.z, v1.w);
            *(uint4*)(smem + OFF_XH + sw_off(row, chunk)) = hi;
        }
    }

    // ---- gumbel tile -> smem (coalesced) ----
    {
        const float4* gg = (const float4*)(gumbel + (size_t)n0 * KK);
        const int valid4 = nvalid * (KK / 4);
        for (int i = tid; i < MT * KK / 4; i += NTHREADS)
            ((float4*)gum)[i] = (i < valid4) ? gg[i] : make_float4(0.f, 0.f, 0.f, 0.f);
    }

    // ---- W2^T fp16 tile [16][128], 272B row stride ----
    for (int i = tid; i < CC * KK; i += NTHREADS) {
        const int c = i >> 4, k = i & 15;
        *(__half*)(smem + OFF_W2TH + k * TSTR + c * 2) = __float2half_rn(W2[i]);
    }

    // ---- small tiles ----
    if (tid < CC) b1s[tid] = b1[tid];
    if (tid < KK) { b2s[tid] = b2[tid]; acts[tid] = active[tid]; }
    if (tid == 0) scs[0] = scaling[0];
    for (int i = tid; i < MT; i += NTHREADS) {
        if (i < nvalid) {
            Ps[2*i]   = pos[(size_t)(n0 + i) * 2];
            Ps[2*i+1] = pos[(size_t)(n0 + i) * 2 + 1];
            Bsm[i]    = batch[n0 + i];
        } else {
            Ps[2*i] = 0.f; Ps[2*i+1] = 0.f; Bsm[i] = -1;
        }
    }
    __syncthreads();

    // ---- stage A: H = x_h @ W1_h, single-pass fp16; W1 frags via LDG ----
    float fa[16][4];
    #pragma unroll
    for (int j = 0; j < 16; j++) { fa[j][0]=0.f; fa[j][1]=0.f; fa[j][2]=0.f; fa[j][3]=0.f; }
    {
        const int ar = wp * 16 + (tx & 7) + (tx & 8);
        const uint32_t sxh = sb + OFF_XH;
        const uint2* wf = g_W1frag + tx;
        #pragma unroll
        for (int ks = 0; ks < 8; ks++) {
            const int ac = ks * 2 + (tx >> 4);
            uint32_t ahi[4];
            ldmx4(ahi, sxh + sw_off(ar, ac));
            #pragma unroll
            for (int j = 0; j < 16; j++) {
                const uint2 w = __ldg(wf + (ks * 16 + j) * 32);
                uint32_t bh[2];
                bh[0] = w.x; bh[1] = w.y;
                mma_f16(fa[j], ahi, bh);
            }
        }
    }

    // ---- relu(H + b1) in registers ----
    const int q2 = (tx & 3) * 2;
    #pragma unroll
    for (int j = 0; j < 16; j++) {
        const float bc0 = b1s[j*8 + q2], bc1 = b1s[j*8 + q2 + 1];
        fa[j][0] = fmaxf(fa[j][0] + bc0, 0.f);
        fa[j][1] = fmaxf(fa[j][1] + bc1, 0.f);
        fa[j][2] = fmaxf(fa[j][2] + bc0, 0.f);
        fa[j][3] = fmaxf(fa[j][3] + bc1, 0.f);
    }

    // ---- stage B as MMA: logits = H_h @ W2_h, single-pass fp16 ----
    float lg0[4] = {0.f,0.f,0.f,0.f}, lg1[4] = {0.f,0.f,0.f,0.f};
    {
        const int br = tx & 7;
        const int bsel = (tx >> 3) & 1;
        const uint32_t w2th = sb + OFF_W2TH;
        #pragma unroll
        for (int ks = 0; ks < 8; ks++) {
            uint32_t ah[4];
            ah[0] = pack_f16(fa[2*ks][0],   fa[2*ks][1]);
            ah[1] = pack_f16(fa[2*ks][2],   fa[2*ks][3]);
            ah[2] = pack_f16(fa[2*ks+1][0], fa[2*ks+1][1]);
            ah[3] = pack_f16(fa[2*ks+1][2], fa[2*ks+1][3]);
            const uint32_t coff = (uint32_t)(ks * 2 + bsel) * 16;
            uint32_t bh[2];
            ldmx2(bh, w2th + br * TSTR + coff);
            mma_f16(lg0, ah, bh);
            ldmx2(bh, w2th + (8 + br) * TSTR + coff);
            mma_f16(lg1, ah, bh);
        }
    }

    // ---- fused bias+mask+scale+gumbel+softmax in registers (quad shuffle) ----
    {
        const int r0v = wp * 16 + (tx >> 2);
        const int r1v = r0v + 8;
        const float sc = scs[0];
        float v0[4] = {lg0[0], lg0[1], lg1[0], lg1[1]};
        float v1[4] = {lg0[2], lg0[3], lg1[2], lg1[3]};
        const int kidx[4] = {q2, q2 + 1, 8 + q2, 9 + q2};
        #pragma unroll
        for (int j = 0; j < 4; j++) {
            const int k = kidx[j];
            const float bb = b2s[k];
            const float mk = acts[k];
            const float a0 = (mk == 0.f) ? -1e9f : (v0[j] + bb) * sc;
            const float a1 = (mk == 0.f) ? -1e9f : (v1[j] + bb) * sc;
            v0[j] = a0 + gum[r0v * KK + k];
            v1[j] = a1 + gum[r1v * KK + k];
        }
        float m0 = fmaxf(fmaxf(v0[0], v0[1]), fmaxf(v0[2], v0[3]));
        float m1 = fmaxf(fmaxf(v1[0], v1[1]), fmaxf(v1[2], v1[3]));
        m0 = fmaxf(m0, __shfl_xor_sync(0xffffffffu, m0, 1));
        m0 = fmaxf(m0, __shfl_xor_sync(0xffffffffu, m0, 2));
        m1 = fmaxf(m1, __shfl_xor_sync(0xffffffffu, m1, 1));
        m1 = fmaxf(m1, __shfl_xor_sync(0xffffffffu, m1, 2));
        float s0 = 0.f, s1 = 0.f;
        #pragma unroll
        for (int j = 0; j < 4; j++) {
            v0[j] = __expf(v0[j] - m0); s0 += v0[j];
            v1[j] = __expf(v1[j] - m1); s1 += v1[j];
        }
        s0 += __shfl_xor_sync(0xffffffffu, s0, 1);
        s0 += __shfl_xor_sync(0xffffffffu, s0, 2);
        s1 += __shfl_xor_sync(0xffffffffu, s1, 1);
        s1 += __shfl_xor_sync(0xffffffffu, s1, 2);
        const float i0 = 1.f / s0, i1 = 1.f / s1;
        const bool ok0 = r0v < nvalid, ok1 = r1v < nvalid;
        #pragma unroll
        for (int j = 0; j < 4; j++) {
            v0[j] = ok0 ? v0[j] * i0 : 0.f;
            v1[j] = ok1 ? v1[j] * i1 : 0.f;
        }
        if (ok0) {
            *(float2*)(out_s + (size_t)(n0 + r0v) * KK + q2)     = make_float2(v0[0], v0[1]);
            *(float2*)(out_s + (size_t)(n0 + r0v) * KK + 8 + q2) = make_float2(v0[2], v0[3]);
        }
        if (ok1) {
            *(float2*)(out_s + (size_t)(n0 + r1v) * KK + q2)     = make_float2(v1[0], v1[1]);
            *(float2*)(out_s + (size_t)(n0 + r1v) * KK + 8 + q2) = make_float2(v1[2], v1[3]);
        }
        *(float2*)(Ls + r0v * KK + q2)     = make_float2(v0[0], v0[1]);
        *(float2*)(Ls + r0v * KK + 8 + q2) = make_float2(v0[2], v0[3]);
        *(float2*)(Ls + r1v * KK + q2)     = make_float2(v1[0], v1[1]);
        *(float2*)(Ls + r1v * KK + 8 + q2) = make_float2(v1[2], v1[3]);
        #pragma unroll
        for (int j = 0; j < 4; j++) {
            const int k = kidx[j];
            *(__half*)(smem + OFF_STH + k * TSTR + r0v * 2) = __float2half_rn(v0[j]);
            *(__half*)(smem + OFF_STH + k * TSTR + r1v * 2) = __float2half_rn(v1[j]);
        }
    }
    __syncthreads();

    // ---- stage C1: statistics ----
    const bool uniform = (nvalid == MT) && (Bsm[0] == Bsm[MT-1]);
    if (uniform) {
        const int k = tid >> 4;
        const int g = tid & 15;
        float gs = 0.f, ge = 0.f, gax = 0.f, gay = 0.f, gp = 0.f;
        #pragma unroll
        for (int j = 0; j < 8; j++) {
            const int n = g*8 + j;
            const float sv = Ls[n*KK + k];
            const float px = Ps[2*n], py = Ps[2*n+1];
            gs  += sv;
            ge  += sv * __logf(sv + EPSF);
            gax += sv * px;
            gay += sv * py;
            gp  += sv * (px*px + py*py);
        }
        #pragma unroll
        for (int off = 8; off > 0; off >>= 1) {
            gs  += __shfl_down_sync(0xffffffffu, gs,  off, 16);
            ge  += __shfl_down_sync(0xffffffffu, ge,  off, 16);
            gax += __shfl_down_sync(0xffffffffu, gax, off, 16);
            gay += __shfl_down_sync(0xffffffffu, gay, off, 16);
            gp  += __shfl_down_sync(0xffffffffu, gp,  off, 16);
        }
        if (g == 0) {
            const int b = Bsm[0];
            atomicAdd(&g_sum_s[k], gs);
            atomicAdd(&g_ent, ge);
            red_add_v2(&g_A[k][0], gax, gay);
            atomicAdd(&g_P[k], gp);
            atomicAdd(&g_bs[b][k], gs);
            red_add_v2(&g_bsp[b][k][0], gax, gay);
        }
    } else if (tid < KK) {
        const int k = tid;
        float gs = 0.f, ge = 0.f, gax = 0.f, gay = 0.f, gp = 0.f;
        int cur = Bsm[0];
        float bs = 0.f, bx = 0.f, by = 0.f;
        for (int n = 0; n < MT; n++) {
            const int bv = Bsm[n];
            if (bv < 0) break;
            if (bv != cur) {
                atomicAdd(&g_bs[cur][k], bs);
                red_add_v2(&g_bsp[cur][k][0], bx, by);
                bs = bx = by = 0.f; cur = bv;
            }
            const float sv = Ls[n*KK + k];
            const float px = Ps[2*n], py = Ps[2*n+1];
            gs  += sv;
            ge  += sv * __logf(sv + EPSF);
            gax += sv * px;
            gay += sv * py;
            gp  += sv * (px*px + py*py);
            bs  += sv; bx += sv * px; by += sv * py;
        }
        if (cur >= 0) {
            atomicAdd(&g_bs[cur][k], bs);
            red_add_v2(&g_bsp[cur][k][0], bx, by);
        }
        atomicAdd(&g_sum_s[k], gs);
        atomicAdd(&g_ent, ge);
        red_add_v2(&g_A[k][0], gax, gay);
        atomicAdd(&g_P[k], gp);
    }

    // ---- stage C2: pooled features ----
    if (uniform) {
        // out[b] += s^T @ x via MMA, single-pass fp16: s_h * x_h
        float p0[4] = {0.f,0.f,0.f,0.f}, p1[4] = {0.f,0.f,0.f,0.f};
        const uint32_t sth = sb + OFF_STH;
        const uint32_t xh = sb + OFF_XH;
        const int arow = tx & 15;
        const int asel = tx >> 4;
        #pragma unroll
        for (int ks = 0; ks < 8; ks++) {
            uint32_t sah[4];
            ldmx4(sah, sth + (uint32_t)arow * TSTR + (uint32_t)(ks * 2 + asel) * 16);
            const int brow = ks * 16 + (tx & 15);
            uint32_t bh[2];
            ldmx2t(bh, xh + sw_off(brow, wp * 2));
            mma_f16(p0, sah, bh);
            ldmx2t(bh, xh + sw_off(brow, wp * 2 + 1));
            mma_f16(p1, sah, bh);
        }
        const int b  = Bsm[0];
        const int kr = tx >> 2;
        float* base0 = out_pool + ((size_t)b * KK + kr) * CC + wp * 16;
        float* base1 = out_pool + ((size_t)b * KK + kr + 8) * CC + wp * 16;
        red_add_v2(base0 + q2,     p0[0], p0[1]);
        red_add_v2(base1 + q2,     p0[2], p0[3]);
        red_add_v2(base0 + 8 + q2, p1[0], p1[1]);
        red_add_v2(base1 + 8 + q2, p1[2], p1[3]);
    } else {
        const int k    = tx & 15;
        const int half = tx >> 4;
        const int cb4  = wp * 4 + half * 2;
        const float4* xg4 = (const float4*)(x + (size_t)n0 * CC);
        float4 A0 = make_float4(0.f,0.f,0.f,0.f);
        float4 A1 = make_float4(0.f,0.f,0.f,0.f);
        int cur = Bsm[0];
        for (int n = 0; n < MT; n++) {
            const int bv = Bsm[n];
            if (bv < 0) break;
            if (bv != cur) {
                float* base = out_pool + ((size_t)cur * KK + k) * CC + cb4 * 4;
                red_add_v2(base+0, A0.x, A0.y);
                red_add_v2(base+2, A0.z, A0.w);
                red_add_v2(base+4, A1.x, A1.y);
                red_add_v2(base+6, A1.z, A1.w);
                A0 = make_float4(0.f,0.f,0.f,0.f);
                A1 = make_float4(0.f,0.f,0.f,0.f);
                cur = bv;
            }
            const float sv = Ls[n*KK + k];
            const float4 x0 = xg4[(size_t)n * 32 + cb4];
            const float4 x1 = xg4[(size_t)n * 32 + cb4 + 1];
            A0.x += sv*x0.x; A0.y += sv*x0.y; A0.z += sv*x0.z; A0.w += sv*x0.w;
            A1.x += sv*x1.x; A1.y += sv*x1.y; A1.z += sv*x1.z; A1.w += sv*x1.w;
        }
        if (cur >= 0) {
            float* base = out_pool + ((size_t)cur * KK + k) * CC + cb4 * 4;
            red_add_v2(base+0, A0.x, A0.y);
            red_add_v2(base+2, A0.z, A0.w);
            red_add_v2(base+4, A1.x, A1.y);
            red_add_v2(base+6, A1.z, A1.w);
        }
    }
}

// -------- finalize --------
__global__ void finalize_kernel(const float* __restrict__ active,
                                float* __restrict__ mu_out,
                                float* __restrict__ losses)
{
    __shared__ float mus[BB][KK][2];
    __shared__ float red[256];
    const int tid = threadIdx.x;
    const int b = tid >> 4, k = tid & 15;

    const float denom = g_bs[b][k] + EPSF;
    const float mx = g_bsp[b][k][0] / denom;
    const float my = g_bsp[b][k][1] / denom;
    mus[b][k][0] = mx; mus[b][k][1] = my;
    mu_out[tid * 2]     = mx;
    mu_out[tid * 2 + 1] = my;
    __syncthreads();

    float rep = 0.f;
    #pragma unroll
    for (int j = 0; j < KK; j++) {
        if (j == k) continue;
        float dx = mus[b][k][0] - mus[b][j][0];
        float dy = mus[b][k][1] - mus[b][j][1];
        rep += 1.f / (dx*dx + dy*dy + 1.f);
    }
    red[tid] = rep;
    __syncthreads();
    for (int st = 128; st > 0; st >>= 1) {
        if (tid < st) red[tid] += red[tid + st];
        __syncthreads();
    }

    if (tid == 0) {
        const float sep = red[0] / ((float)(KK * (KK - 1)) + EPSF);
        const float entropy = -g_ent / (float)NN;
        float div = 0.f, prun = 0.f, spat = 0.f, spar = 0.f;
        for (int kk = 0; kk < KK; kk++) {
            const float avg = g_sum_s[kk] / (float)NN;
            div  += avg * __logf(avg + EPSF);
            const float am = active[kk];
            prun += fabsf(avg * (1.f - am));
            spar += am;
            const float S = g_sum_s[kk] + EPSF;
            const float mgx = g_A[kk][0] / S;
            const float mgy = g_A[kk][1] / S;
            spat += g_P[kk] / S - (mgx*mgx + mgy*mgy);
        }
        losses[0] = entropy;
        losses[1] = div;
        losses[2] = spat / (float)KK;
        losses[3] = prun / (float)KK;
        losses[4] = spar / (float)KK;
        losses[5] = sep;
    }
}

extern "C" void kernel_launch(void* const* d_in, const int* in_sizes, int n_in,
                              void* d_out, int out_size) {
    const float* x       = (const float*)d_in[0];
    const float* pos     = (const float*)d_in[1];
    const int*   batch   = (const int*)  d_in[2];
    const float* gumbel  = (const float*)d_in[3];
    const float* W1      = (const float*)d_in[4];
    const float* b1      = (const float*)d_in[5];
    const float* W2      = (const float*)d_in[6];
    const float* b2      = (const float*)d_in[7];
    const float* scaling = (const float*)d_in[8];
    const float* active  = (const float*)d_in[9];

    float* out = (float*)d_out;
    float* out_pool   = out;
    float* out_s      = out + (size_t)BB*KK*CC;
    float* out_mu     = out_s + (size_t)NN*KK;
    float* out_losses = out_mu + (size_t)BB*KK*2;

    cudaFuncSetAttribute(fused_kernel, cudaFuncAttributeMaxDynamicSharedMemorySize,
                         SMEM_TOTAL);

    init_kernel<<<128, 256>>>(out_pool, W1);
    fused_kernel<<<(NN + MT - 1) / MT, NTHREADS, SMEM_TOTAL>>>(
        x, pos, batch, gumbel, b1, W2, b2, scaling, active, out_pool, out_s);
    finalize_kernel<<<1, 256>>>(active, out_mu, out_losses);
}